// round 1
// baseline (speedup 1.0000x reference)
#include <cuda_runtime.h>
#include <math.h>

// Problem constants
#define Bz 2
#define Tt 2048
#define Dd 1024
#define Hh 16
#define dh 64
#define INNER 1024
#define Mrows 4096   // B*T

// ---------------- scratch (no allocations allowed; use __device__ globals) ----
__device__ float g_Xq[Mrows * INNER];
__device__ float g_Xk[Mrows * INNER];
__device__ float g_Xv[Mrows * INNER];
__device__ float g_Xg[Mrows * INNER];   // silu'd in place -> gate
__device__ float g_Qn[Mrows * INNER];
__device__ float g_Kn[Mrows * INNER];
__device__ float g_Vv[Mrows * INNER];
__device__ float g_AB[Mrows * 32];      // [m][0..15]=alpha(h), [m][16..31]=beta(h)
__device__ float g_O [Mrows * INNER];   // scan output
__device__ float g_Y [Mrows * INNER];   // rms*gamma*gate result (GEMM input)

// ---------------- 128x128x8 fp32 SGEMM tile (8x8 per thread, 256 threads) ----
__device__ __forceinline__ void sgemm128(const float* __restrict__ A,
                                         const float* __restrict__ Bm,
                                         float* __restrict__ C,
                                         int Kdim, int N, int bm, int bn)
{
    __shared__ float As[8][128];
    __shared__ float Bs[8][128];
    const int tid  = threadIdx.x;
    const int arow = tid >> 1;           // 0..127
    const int acol = (tid & 1) << 2;     // 0 or 4
    const int brow = tid >> 5;           // 0..7
    const int bcol = (tid & 31) << 2;    // 0..124
    const int tx   = (tid & 15) << 3;    // col base 0..120
    const int ty   = (tid >> 4) << 3;    // row base 0..120

    float acc[8][8];
#pragma unroll
    for (int i = 0; i < 8; i++)
#pragma unroll
        for (int j = 0; j < 8; j++) acc[i][j] = 0.f;

    const float* Aptr = A + (long)(bm + arow) * Kdim + acol;
    const float* Bptr = Bm + (long)brow * N + bn + bcol;

    for (int k0 = 0; k0 < Kdim; k0 += 8) {
        float4 av = *(const float4*)(Aptr + k0);
        float4 bv = *(const float4*)(Bptr + (long)k0 * N);
        __syncthreads();
        As[acol + 0][arow] = av.x;
        As[acol + 1][arow] = av.y;
        As[acol + 2][arow] = av.z;
        As[acol + 3][arow] = av.w;
        *(float4*)&Bs[brow][bcol] = bv;
        __syncthreads();
#pragma unroll
        for (int kk = 0; kk < 8; kk++) {
            float ar[8], br[8];
#pragma unroll
            for (int i = 0; i < 8; i++) ar[i] = As[kk][ty + i];
#pragma unroll
            for (int j = 0; j < 8; j++) br[j] = Bs[kk][tx + j];
#pragma unroll
            for (int i = 0; i < 8; i++)
#pragma unroll
                for (int j = 0; j < 8; j++)
                    acc[i][j] = fmaf(ar[i], br[j], acc[i][j]);
        }
    }
#pragma unroll
    for (int i = 0; i < 8; i++) {
        float* crow = C + (long)(bm + ty + i) * N + bn + tx;
#pragma unroll
        for (int j = 0; j < 8; j += 4) {
            float4 v = make_float4(acc[i][j], acc[i][j + 1], acc[i][j + 2], acc[i][j + 3]);
            *(float4*)(crow + j) = v;
        }
    }
}

// ---------------- projections: x @ {Wq,Wk,Wv,Wg} via blockIdx.z ---------------
__global__ __launch_bounds__(256, 2) void proj_gemm_kernel(
    const float* __restrict__ x,
    const float* __restrict__ Wq, const float* __restrict__ Wk,
    const float* __restrict__ Wv, const float* __restrict__ Wg)
{
    const float* W;
    float* O;
    switch (blockIdx.z) {
        case 0:  W = Wq; O = g_Xq; break;
        case 1:  W = Wk; O = g_Xk; break;
        case 2:  W = Wv; O = g_Xv; break;
        default: W = Wg; O = g_Xg; break;
    }
    sgemm128(x, W, O, Dd, INNER, blockIdx.y * 128, blockIdx.x * 128);
}

// ---------------- alpha/beta: sigmoid(x@Wa+ba), sigmoid(x@Wb+bb) --------------
__global__ __launch_bounds__(256) void ab_kernel(
    const float* __restrict__ x,
    const float* __restrict__ Wa, const float* __restrict__ ba,
    const float* __restrict__ Wb, const float* __restrict__ bb)
{
    __shared__ float xs[Dd];
    const int m = blockIdx.x;
    const int tid = threadIdx.x;
    for (int i = tid; i < Dd; i += 256) xs[i] = x[(long)m * Dd + i];
    __syncthreads();
    const int out = tid >> 3;    // 0..31
    const int l8  = tid & 7;
    const float* W = (out < 16) ? Wa : Wb;
    const int h = out & 15;
    float s = 0.f;
    for (int kx = l8; kx < Dd; kx += 8) s = fmaf(xs[kx], W[kx * Hh + h], s);
    s += __shfl_xor_sync(0xffffffffu, s, 1);
    s += __shfl_xor_sync(0xffffffffu, s, 2);
    s += __shfl_xor_sync(0xffffffffu, s, 4);
    if (l8 == 0) {
        float bias = (out < 16) ? ba[h] : bb[h];
        g_AB[(long)m * 32 + out] = 1.f / (1.f + expf(-(s + bias)));
    }
}

// ---------------- gate silu (in place) ---------------------------------------
__global__ void silu_kernel()
{
    long i = (long)blockIdx.x * blockDim.x + threadIdx.x;
    float v = g_Xg[i];
    g_Xg[i] = v / (1.f + expf(-v));
}

// ---------------- depthwise causal conv + silu (+ per-head l2norm for q,k) ---
__global__ __launch_bounds__(64) void conv_kernel(
    const float* __restrict__ cq_w, const float* __restrict__ cq_b,
    const float* __restrict__ ck_w, const float* __restrict__ ck_b,
    const float* __restrict__ cv_w, const float* __restrict__ cv_b)
{
    const float* Xin; float* Out; const float* cw; const float* cb; bool donorm;
    switch (blockIdx.y) {
        case 0:  Xin = g_Xq; Out = g_Qn; cw = cq_w; cb = cq_b; donorm = true;  break;
        case 1:  Xin = g_Xk; Out = g_Kn; cw = ck_w; cb = ck_b; donorm = true;  break;
        default: Xin = g_Xv; Out = g_Vv; cw = cv_w; cb = cv_b; donorm = false; break;
    }
    const int bth = blockIdx.x;          // (b*T + t)*H + h
    const int h   = bth % Hh;
    const int bt  = bth / Hh;            // b*T + t
    const int t   = bt % Tt;
    const int c   = h * dh + threadIdx.x;
    const long base = (long)bt * INNER + c;

    float acc = cb[c];
#pragma unroll
    for (int kk = 0; kk < 4; kk++) {
        int tt = t - 3 + kk;
        if (tt >= 0) acc = fmaf(Xin[base + (long)(kk - 3) * INNER], cw[c * 4 + kk], acc);
    }
    float s = acc / (1.f + expf(-acc));  // silu

    float ss = s * s;
    ss += __shfl_xor_sync(0xffffffffu, ss, 16);
    ss += __shfl_xor_sync(0xffffffffu, ss, 8);
    ss += __shfl_xor_sync(0xffffffffu, ss, 4);
    ss += __shfl_xor_sync(0xffffffffu, ss, 2);
    ss += __shfl_xor_sync(0xffffffffu, ss, 1);
    __shared__ float red[2];
    if ((threadIdx.x & 31) == 0) red[threadIdx.x >> 5] = ss;
    __syncthreads();
    float tot = red[0] + red[1];
    if (donorm) s = s / fmaxf(sqrtf(tot), 1e-12f);
    Out[base] = s;
}

// ---------------- sequential gated delta scan --------------------------------
// One CTA per (b,h). 256 threads; thread owns S[r][cq..cq+15] in registers.
// S_new[i][j] = a*S[i][j] + k[j]*(b*v[i] - a*b*(S k)[i]);  o = S_new @ q
__global__ __launch_bounds__(256) void scan_kernel()
{
    const int bh = blockIdx.x;
    const int b = bh / Hh, h = bh % Hh;
    const int tid = threadIdx.x;
    const int r  = tid >> 2;             // row 0..63
    const int cq = (tid & 3) << 4;       // col base 0/16/32/48

    float S[16];
#pragma unroll
    for (int j = 0; j < 16; j++) S[j] = 0.f;

    __shared__ float sk[2][64], sv[2][64], sq[2][64], sab[2][2];
    const int role = tid >> 6;           // 0:k 1:v 2:q 3:ab
    const int li   = tid & 63;
    const long hoff = (long)h * dh;

    { // preload t=0 into buffer 0
        long base = (long)(b * Tt) * INNER + hoff + li;
        if (role == 0)      sk[0][li] = g_Kn[base];
        else if (role == 1) sv[0][li] = g_Vv[base];
        else if (role == 2) sq[0][li] = g_Qn[base];
        else if (li < 2)    sab[0][li] = g_AB[(long)(b * Tt) * 32 + li * 16 + h];
    }
    __syncthreads();

    for (int t = 0; t < Tt; t++) {
        const int cur = t & 1;
        if (t + 1 < Tt) {                // prefetch next step into other buffer
            const int nb = cur ^ 1;
            long base = (long)(b * Tt + t + 1) * INNER + hoff + li;
            if (role == 0)      sk[nb][li] = g_Kn[base];
            else if (role == 1) sv[nb][li] = g_Vv[base];
            else if (role == 2) sq[nb][li] = g_Qn[base];
            else if (li < 2)    sab[nb][li] = g_AB[(long)(b * Tt + t + 1) * 32 + li * 16 + h];
        }

        const float a  = sab[cur][0];
        const float be = sab[cur][1];

        float kreg[16];
#pragma unroll
        for (int j = 0; j < 16; j++) kreg[j] = sk[cur][cq + j];

        float part = 0.f;                // (S k)[r] partial over 16 cols
#pragma unroll
        for (int j = 0; j < 16; j++) part = fmaf(S[j], kreg[j], part);
        part += __shfl_xor_sync(0xffffffffu, part, 1);
        part += __shfl_xor_sync(0xffffffffu, part, 2);

        const float vr   = sv[cur][r];
        const float coef = be * vr - a * be * part;

        float op = 0.f;
#pragma unroll
        for (int j = 0; j < 16; j++) {
            S[j] = fmaf(a, S[j], coef * kreg[j]);
            op   = fmaf(S[j], sq[cur][cq + j], op);
        }
        op += __shfl_xor_sync(0xffffffffu, op, 1);
        op += __shfl_xor_sync(0xffffffffu, op, 2);
        if ((tid & 3) == 0)
            g_O[(long)(b * Tt + t) * INNER + hoff + r] = op;
        __syncthreads();
    }
}

// ---------------- RMS norm + (1+gamma) + gate --------------------------------
__global__ __launch_bounds__(256) void rmsgate_kernel(const float* __restrict__ gamma)
{
    const int m = blockIdx.x;
    const int tid = threadIdx.x;
    const long base = (long)m * INNER;
    float xv[4];
    float ss = 0.f;
#pragma unroll
    for (int i = 0; i < 4; i++) {
        xv[i] = g_O[base + tid + i * 256];
        ss += xv[i] * xv[i];
    }
    for (int off = 16; off; off >>= 1) ss += __shfl_xor_sync(0xffffffffu, ss, off);
    __shared__ float red[8];
    if ((tid & 31) == 0) red[tid >> 5] = ss;
    __syncthreads();
    float tot = 0.f;
#pragma unroll
    for (int w = 0; w < 8; w++) tot += red[w];
    const float inv = 1.f / sqrtf(tot * (1.f / (float)INNER) + 1e-6f);
#pragma unroll
    for (int i = 0; i < 4; i++) {
        int c = tid + i * 256;
        g_Y[base + c] = xv[i] * inv * (1.f + gamma[c]) * g_Xg[base + c];
    }
}

// ---------------- output GEMM: y @ Wo -> d_out -------------------------------
__global__ __launch_bounds__(256, 2) void out_gemm_kernel(const float* __restrict__ Wo,
                                                          float* __restrict__ out)
{
    sgemm128(g_Y, Wo, out, INNER, Dd, blockIdx.y * 128, blockIdx.x * 128);
}

// ---------------- launch -----------------------------------------------------
extern "C" void kernel_launch(void* const* d_in, const int* in_sizes, int n_in,
                              void* d_out, int out_size)
{
    const float* x    = (const float*)d_in[0];
    const float* Wq   = (const float*)d_in[1];
    const float* Wk   = (const float*)d_in[2];
    const float* Wv   = (const float*)d_in[3];
    const float* Wa   = (const float*)d_in[4];
    const float* ba   = (const float*)d_in[5];
    const float* Wb   = (const float*)d_in[6];
    const float* bb   = (const float*)d_in[7];
    const float* Wg   = (const float*)d_in[8];
    const float* Wo   = (const float*)d_in[9];
    const float* cq_w = (const float*)d_in[10];
    const float* cq_b = (const float*)d_in[11];
    const float* ck_w = (const float*)d_in[12];
    const float* ck_b = (const float*)d_in[13];
    const float* cv_w = (const float*)d_in[14];
    const float* cv_b = (const float*)d_in[15];
    const float* gamma= (const float*)d_in[16];
    float* out = (float*)d_out;

    proj_gemm_kernel<<<dim3(INNER / 128, Mrows / 128, 4), 256>>>(x, Wq, Wk, Wv, Wg);
    ab_kernel<<<Mrows, 256>>>(x, Wa, ba, Wb, bb);
    silu_kernel<<<(Mrows * INNER) / 256, 256>>>();
    conv_kernel<<<dim3(Mrows * Hh, 3), 64>>>(cq_w, cq_b, ck_w, ck_b, cv_w, cv_b);
    scan_kernel<<<Bz * Hh, 256>>>();
    rmsgate_kernel<<<Mrows, 256>>>(gamma);
    out_gemm_kernel<<<dim3(Dd / 128, Mrows / 128), 256>>>(Wo, out);
}

// round 2
// speedup vs baseline: 1.2988x; 1.2988x over previous
#include <cuda_runtime.h>
#include <math.h>

// Problem constants
#define Bz 2
#define Tt 2048
#define Dd 1024
#define Hh 16
#define dh 64
#define INNER 1024
#define Mrows 4096   // B*T

// ---------------- scratch ----------------------------------------------------
__device__ float g_Xq[Mrows * INNER];
__device__ float g_Xk[Mrows * INNER];
__device__ float g_Xv[Mrows * INNER];
__device__ float g_Xg[Mrows * INNER];   // gate (silu applied in GEMM epilogue)
__device__ float g_Qn[Mrows * INNER];
__device__ float g_Kn[Mrows * INNER];
__device__ float g_Vv[Mrows * INNER];
__device__ float g_AB[Mrows * 32];      // [m][0..15]=alpha(h), [m][16..31]=beta(h)
__device__ float g_O [Mrows * INNER];   // scan output
__device__ float g_Y [Mrows * INNER];   // rms*gamma*gate result (GEMM input)

// ---------------- tf32 helpers -----------------------------------------------
__device__ __forceinline__ unsigned cvt_tf32(float f) {
    unsigned u;
    asm("cvt.rna.tf32.f32 %0, %1;" : "=r"(u) : "f"(f));
    return u;
}

__device__ __forceinline__ void mma_tf32(float* d, unsigned a0, unsigned a1,
                                         unsigned a2, unsigned a3,
                                         unsigned b0, unsigned b1) {
    asm("mma.sync.aligned.m16n8k8.row.col.f32.tf32.tf32.f32 "
        "{%0,%1,%2,%3}, {%4,%5,%6,%7}, {%8,%9}, {%0,%1,%2,%3};\n"
        : "+f"(d[0]), "+f"(d[1]), "+f"(d[2]), "+f"(d[3])
        : "r"(a0), "r"(a1), "r"(a2), "r"(a3), "r"(b0), "r"(b1));
}

// ---------------- tf32 tensor-core GEMM, 128x128 tile, BK=16 -----------------
// A (M,Kd) row-major, B (Kd,N) row-major. C = A@B. Optional silu epilogue.
#define ASTR 136
__device__ __forceinline__ void tgemm128(const float* __restrict__ A,
                                         const float* __restrict__ Bm,
                                         float* __restrict__ C,
                                         int Kd, int N, int bm, int bn,
                                         bool do_silu)
{
    __shared__ unsigned As[16 * ASTR];
    __shared__ unsigned Bs[16 * ASTR];

    const int tid  = threadIdx.x;
    const int lane = tid & 31;
    const int wid  = tid >> 5;
    const int warpM = (wid & 3) * 32;   // 4 warps in M
    const int warpN = (wid >> 2) * 64;  // 2 warps in N

    float acc[2][8][4];
#pragma unroll
    for (int mt = 0; mt < 2; mt++)
#pragma unroll
        for (int nt = 0; nt < 8; nt++)
#pragma unroll
            for (int i = 0; i < 4; i++) acc[mt][nt][i] = 0.f;

    // A loader: e = tid + i*256; m = e/4, kq = (e%4)*4
    const int am0 = tid >> 2;
    const int akq = (tid & 3) << 2;
    // B loader: e = tid + i*256; k = e/32, nq = (e%32)*4
    const int bk0 = tid >> 5;
    const int bnq = (tid & 31) << 2;

    float4 aval[2], bval[2];
    // prefetch tile 0
#pragma unroll
    for (int i = 0; i < 2; i++) {
        aval[i] = *(const float4*)(A + (long)(bm + am0 + i * 64) * Kd + akq);
        bval[i] = *(const float4*)(Bm + (long)(bk0 + i * 8) * N + bn + bnq);
    }

    const int nKT = Kd >> 4;
    for (int kt = 0; kt < nKT; kt++) {
        __syncthreads();
        // store A with XOR swizzle: idx = k*ASTR + (m ^ ((k>>2)<<3))
#pragma unroll
        for (int i = 0; i < 2; i++) {
            const int m = am0 + i * 64;
            const float* v = (const float*)&aval[i];
#pragma unroll
            for (int j = 0; j < 4; j++) {
                const int k = akq + j;
                As[k * ASTR + (m ^ ((k >> 2) << 3))] = cvt_tf32(v[j]);
            }
            const int kb = bk0 + i * 8;
            const float* w = (const float*)&bval[i];
            uint4 bu;
            bu.x = cvt_tf32(w[0]); bu.y = cvt_tf32(w[1]);
            bu.z = cvt_tf32(w[2]); bu.w = cvt_tf32(w[3]);
            *(uint4*)&Bs[kb * ASTR + bnq] = bu;
        }
        __syncthreads();

        if (kt + 1 < nKT) {
            const int koff = (kt + 1) << 4;
#pragma unroll
            for (int i = 0; i < 2; i++) {
                aval[i] = *(const float4*)(A + (long)(bm + am0 + i * 64) * Kd + koff + akq);
                bval[i] = *(const float4*)(Bm + (long)(koff + bk0 + i * 8) * N + bn + bnq);
            }
        }

#pragma unroll
        for (int k8 = 0; k8 < 16; k8 += 8) {
            unsigned af[2][4], bf[8][2];
            const int kk0 = k8 + (lane & 3);
            const int kk1 = kk0 + 4;
            const int msk0 = (kk0 >> 2) << 3;
            const int msk1 = (kk1 >> 2) << 3;
#pragma unroll
            for (int mt = 0; mt < 2; mt++) {
                const int r0 = warpM + mt * 16 + (lane >> 2);
                af[mt][0] = As[kk0 * ASTR + (r0 ^ msk0)];
                af[mt][1] = As[kk0 * ASTR + ((r0 + 8) ^ msk0)];
                af[mt][2] = As[kk1 * ASTR + (r0 ^ msk1)];
                af[mt][3] = As[kk1 * ASTR + ((r0 + 8) ^ msk1)];
            }
#pragma unroll
            for (int nt = 0; nt < 8; nt++) {
                const int n = warpN + nt * 8 + (lane >> 2);
                bf[nt][0] = Bs[kk0 * ASTR + n];
                bf[nt][1] = Bs[kk1 * ASTR + n];
            }
#pragma unroll
            for (int mt = 0; mt < 2; mt++)
#pragma unroll
                for (int nt = 0; nt < 8; nt++)
                    mma_tf32(acc[mt][nt], af[mt][0], af[mt][1], af[mt][2], af[mt][3],
                             bf[nt][0], bf[nt][1]);
        }
    }

    // epilogue
#pragma unroll
    for (int mt = 0; mt < 2; mt++) {
        const int r0 = bm + warpM + mt * 16 + (lane >> 2);
#pragma unroll
        for (int nt = 0; nt < 8; nt++) {
            const int c = bn + warpN + nt * 8 + ((lane & 3) << 1);
            float v0 = acc[mt][nt][0], v1 = acc[mt][nt][1];
            float v2 = acc[mt][nt][2], v3 = acc[mt][nt][3];
            if (do_silu) {
                v0 = v0 / (1.f + expf(-v0));
                v1 = v1 / (1.f + expf(-v1));
                v2 = v2 / (1.f + expf(-v2));
                v3 = v3 / (1.f + expf(-v3));
            }
            *(float2*)(C + (long)r0 * N + c)       = make_float2(v0, v1);
            *(float2*)(C + (long)(r0 + 8) * N + c) = make_float2(v2, v3);
        }
    }
}

// ---------------- projections: x @ {Wq,Wk,Wv,Wg} -----------------------------
__global__ __launch_bounds__(256) void proj_gemm_kernel(
    const float* __restrict__ x,
    const float* __restrict__ Wq, const float* __restrict__ Wk,
    const float* __restrict__ Wv, const float* __restrict__ Wg)
{
    const float* W;
    float* O;
    bool silu = false;
    switch (blockIdx.z) {
        case 0:  W = Wq; O = g_Xq; break;
        case 1:  W = Wk; O = g_Xk; break;
        case 2:  W = Wv; O = g_Xv; break;
        default: W = Wg; O = g_Xg; silu = true; break;
    }
    tgemm128(x, W, O, Dd, INNER, blockIdx.y * 128, blockIdx.x * 128, silu);
}

// ---------------- alpha/beta: sigmoid(x@Wa+ba), sigmoid(x@Wb+bb) --------------
__global__ __launch_bounds__(256) void ab_kernel(
    const float* __restrict__ x,
    const float* __restrict__ Wa, const float* __restrict__ ba,
    const float* __restrict__ Wb, const float* __restrict__ bb)
{
    __shared__ float xs[Dd];
    const int m = blockIdx.x;
    const int tid = threadIdx.x;
    for (int i = tid; i < Dd; i += 256) xs[i] = x[(long)m * Dd + i];
    __syncthreads();
    const int out = tid >> 3;    // 0..31
    const int l8  = tid & 7;
    const float* W = (out < 16) ? Wa : Wb;
    const int h = out & 15;
    float s = 0.f;
    for (int kx = l8; kx < Dd; kx += 8) s = fmaf(xs[kx], W[kx * Hh + h], s);
    s += __shfl_xor_sync(0xffffffffu, s, 1);
    s += __shfl_xor_sync(0xffffffffu, s, 2);
    s += __shfl_xor_sync(0xffffffffu, s, 4);
    if (l8 == 0) {
        float bias = (out < 16) ? ba[h] : bb[h];
        g_AB[(long)m * 32 + out] = 1.f / (1.f + expf(-(s + bias)));
    }
}

// ---------------- depthwise causal conv + silu (+ l2norm for q,k) ------------
// block: 256 threads, one bt row; thread handles 4 channels (float4).
__global__ __launch_bounds__(256) void conv_kernel(
    const float* __restrict__ cq_w, const float* __restrict__ cq_b,
    const float* __restrict__ ck_w, const float* __restrict__ ck_b,
    const float* __restrict__ cv_w, const float* __restrict__ cv_b)
{
    const float* Xin; float* Out; const float* cw; const float* cb; bool donorm;
    switch (blockIdx.y) {
        case 0:  Xin = g_Xq; Out = g_Qn; cw = cq_w; cb = cq_b; donorm = true;  break;
        case 1:  Xin = g_Xk; Out = g_Kn; cw = ck_w; cb = ck_b; donorm = true;  break;
        default: Xin = g_Xv; Out = g_Vv; cw = cv_w; cb = cv_b; donorm = false; break;
    }
    const int bt = blockIdx.x;           // b*T + t
    const int t  = bt % Tt;
    const int c0 = threadIdx.x << 2;     // channel base
    const long base = (long)bt * INNER + c0;

    float acc[4];
#pragma unroll
    for (int j = 0; j < 4; j++) acc[j] = cb[c0 + j];
#pragma unroll
    for (int kk = 0; kk < 4; kk++) {
        const int dt = kk - 3;
        if (t + dt >= 0) {
            float4 xv = *(const float4*)(Xin + base + (long)dt * INNER);
            acc[0] = fmaf(xv.x, cw[(c0 + 0) * 4 + kk], acc[0]);
            acc[1] = fmaf(xv.y, cw[(c0 + 1) * 4 + kk], acc[1]);
            acc[2] = fmaf(xv.z, cw[(c0 + 2) * 4 + kk], acc[2]);
            acc[3] = fmaf(xv.w, cw[(c0 + 3) * 4 + kk], acc[3]);
        }
    }
    float s[4], ss = 0.f;
#pragma unroll
    for (int j = 0; j < 4; j++) {
        s[j] = acc[j] / (1.f + expf(-acc[j]));
        ss += s[j] * s[j];
    }
    // reduce over 16-thread group (one head = 64 channels)
    ss += __shfl_xor_sync(0xffffffffu, ss, 1);
    ss += __shfl_xor_sync(0xffffffffu, ss, 2);
    ss += __shfl_xor_sync(0xffffffffu, ss, 4);
    ss += __shfl_xor_sync(0xffffffffu, ss, 8);
    if (donorm) {
        const float inv = 1.f / fmaxf(sqrtf(ss), 1e-12f);
#pragma unroll
        for (int j = 0; j < 4; j++) s[j] *= inv;
    }
    *(float4*)(Out + base) = make_float4(s[0], s[1], s[2], s[3]);
}

// ---------------- sequential gated delta scan --------------------------------
__global__ __launch_bounds__(256) void scan_kernel()
{
    const int bh = blockIdx.x;
    const int b = bh / Hh, h = bh % Hh;
    const int tid = threadIdx.x;
    const int r  = tid >> 2;             // row 0..63
    const int cq = (tid & 3) << 4;       // col base 0/16/32/48

    float S[16];
#pragma unroll
    for (int j = 0; j < 16; j++) S[j] = 0.f;

    __shared__ float sk[2][64], sv[2][64], sq[2][64], sab[2][2];
    const int role = tid >> 6;           // 0:k 1:v 2:q 3:ab
    const int li   = tid & 63;
    const long hoff = (long)h * dh;

    {
        long base = (long)(b * Tt) * INNER + hoff + li;
        if (role == 0)      sk[0][li] = g_Kn[base];
        else if (role == 1) sv[0][li] = g_Vv[base];
        else if (role == 2) sq[0][li] = g_Qn[base];
        else if (li < 2)    sab[0][li] = g_AB[(long)(b * Tt) * 32 + li * 16 + h];
    }
    __syncthreads();

    for (int t = 0; t < Tt; t++) {
        const int cur = t & 1;
        if (t + 1 < Tt) {
            const int nb = cur ^ 1;
            long base = (long)(b * Tt + t + 1) * INNER + hoff + li;
            if (role == 0)      sk[nb][li] = g_Kn[base];
            else if (role == 1) sv[nb][li] = g_Vv[base];
            else if (role == 2) sq[nb][li] = g_Qn[base];
            else if (li < 2)    sab[nb][li] = g_AB[(long)(b * Tt + t + 1) * 32 + li * 16 + h];
        }

        const float a  = sab[cur][0];
        const float be = sab[cur][1];

        float kreg[16];
#pragma unroll
        for (int j = 0; j < 16; j++) kreg[j] = sk[cur][cq + j];

        float part = 0.f;
#pragma unroll
        for (int j = 0; j < 16; j++) part = fmaf(S[j], kreg[j], part);
        part += __shfl_xor_sync(0xffffffffu, part, 1);
        part += __shfl_xor_sync(0xffffffffu, part, 2);

        const float vr   = sv[cur][r];
        const float coef = be * vr - a * be * part;

        float op = 0.f;
#pragma unroll
        for (int j = 0; j < 16; j++) {
            S[j] = fmaf(a, S[j], coef * kreg[j]);
            op   = fmaf(S[j], sq[cur][cq + j], op);
        }
        op += __shfl_xor_sync(0xffffffffu, op, 1);
        op += __shfl_xor_sync(0xffffffffu, op, 2);
        if ((tid & 3) == 0)
            g_O[(long)(b * Tt + t) * INNER + hoff + r] = op;
        __syncthreads();
    }
}

// ---------------- RMS norm + (1+gamma) + gate --------------------------------
__global__ __launch_bounds__(256) void rmsgate_kernel(const float* __restrict__ gamma)
{
    const int m = blockIdx.x;
    const int tid = threadIdx.x;
    const long base = (long)m * INNER;
    float xv[4];
    float ss = 0.f;
#pragma unroll
    for (int i = 0; i < 4; i++) {
        xv[i] = g_O[base + tid + i * 256];
        ss += xv[i] * xv[i];
    }
    for (int off = 16; off; off >>= 1) ss += __shfl_xor_sync(0xffffffffu, ss, off);
    __shared__ float red[8];
    if ((tid & 31) == 0) red[tid >> 5] = ss;
    __syncthreads();
    float tot = 0.f;
#pragma unroll
    for (int w = 0; w < 8; w++) tot += red[w];
    const float inv = 1.f / sqrtf(tot * (1.f / (float)INNER) + 1e-6f);
#pragma unroll
    for (int i = 0; i < 4; i++) {
        int c = tid + i * 256;
        g_Y[base + c] = xv[i] * inv * (1.f + gamma[c]) * g_Xg[base + c];
    }
}

// ---------------- output GEMM: y @ Wo -> d_out -------------------------------
__global__ __launch_bounds__(256) void out_gemm_kernel(const float* __restrict__ Wo,
                                                       float* __restrict__ out)
{
    tgemm128(g_Y, Wo, out, INNER, Dd, blockIdx.y * 128, blockIdx.x * 128, false);
}

// ---------------- launch -----------------------------------------------------
extern "C" void kernel_launch(void* const* d_in, const int* in_sizes, int n_in,
                              void* d_out, int out_size)
{
    const float* x    = (const float*)d_in[0];
    const float* Wq   = (const float*)d_in[1];
    const float* Wk   = (const float*)d_in[2];
    const float* Wv   = (const float*)d_in[3];
    const float* Wa   = (const float*)d_in[4];
    const float* ba   = (const float*)d_in[5];
    const float* Wb   = (const float*)d_in[6];
    const float* bb   = (const float*)d_in[7];
    const float* Wg   = (const float*)d_in[8];
    const float* Wo   = (const float*)d_in[9];
    const float* cq_w = (const float*)d_in[10];
    const float* cq_b = (const float*)d_in[11];
    const float* ck_w = (const float*)d_in[12];
    const float* ck_b = (const float*)d_in[13];
    const float* cv_w = (const float*)d_in[14];
    const float* cv_b = (const float*)d_in[15];
    const float* gamma= (const float*)d_in[16];
    float* out = (float*)d_out;

    proj_gemm_kernel<<<dim3(INNER / 128, Mrows / 128, 4), 256>>>(x, Wq, Wk, Wv, Wg);
    ab_kernel<<<Mrows, 256>>>(x, Wa, ba, Wb, bb);
    conv_kernel<<<dim3(Mrows, 3), 256>>>(cq_w, cq_b, ck_w, ck_b, cv_w, cv_b);
    scan_kernel<<<Bz * Hh, 256>>>();
    rmsgate_kernel<<<Mrows, 256>>>(gamma);
    out_gemm_kernel<<<dim3(Dd / 128, Mrows / 128), 256>>>(Wo, out);
}

// round 4
// speedup vs baseline: 1.3307x; 1.0246x over previous
#include <cuda_runtime.h>
#include <math.h>
#include <stdint.h>

// Problem constants
#define Bz 2
#define Tt 2048
#define Dd 1024
#define Hh 16
#define dh 64
#define INNER 1024
#define Mrows 4096   // B*T

// ---------------- scratch ----------------------------------------------------
__device__ float g_Xq[Mrows * INNER];
__device__ float g_Xk[Mrows * INNER];
__device__ float g_Xv[Mrows * INNER];
__device__ float g_Xg[Mrows * INNER];   // gate (silu applied in GEMM epilogue)
__device__ float g_Qn[Mrows * INNER];
__device__ float g_Kn[Mrows * INNER];
__device__ float g_Vv[Mrows * INNER];
__device__ float g_AB[Mrows * 32];      // [m][0..15]=alpha(h), [m][16..31]=beta(h)
__device__ float g_O [Mrows * INNER];
__device__ float g_Y [Mrows * INNER];   // rms*gamma*gate (tf32-rounded)
__device__ float g_xa[Mrows * Dd];      // tf32-rounded x
__device__ float g_Wr[5 * Dd * INNER];  // tf32-rounded weights (row-major)

// ---------------- tf32 helpers -----------------------------------------------
__device__ __forceinline__ unsigned cvt_tf32(float f) {
    unsigned u;
    asm("cvt.rna.tf32.f32 %0, %1;" : "=r"(u) : "f"(f));
    return u;
}
__device__ __forceinline__ float rna_tf32(float f) {
    return __uint_as_float(cvt_tf32(f));
}

__device__ __forceinline__ void mma_tf32(float* d, unsigned a0, unsigned a1,
                                         unsigned a2, unsigned a3,
                                         unsigned b0, unsigned b1) {
    asm("mma.sync.aligned.m16n8k8.row.col.f32.tf32.tf32.f32 "
        "{%0,%1,%2,%3}, {%4,%5,%6,%7}, {%8,%9}, {%0,%1,%2,%3};\n"
        : "+f"(d[0]), "+f"(d[1]), "+f"(d[2]), "+f"(d[3])
        : "r"(a0), "r"(a1), "r"(a2), "r"(a3), "r"(b0), "r"(b1));
}

// ---------------- tf32 tensor-core GEMM, 128x128 tile, 4 warps (64x64 each) --
// A (M,Kd) row-major (pre-rounded), B (Kd,N) row-major (pre-rounded). C = A@B.
#define ASTR 136
__device__ __forceinline__ void tgemm128(const float* __restrict__ A,
                                         const float* __restrict__ Bm,
                                         float* __restrict__ C,
                                         int Kd, int N, int bm, int bn,
                                         bool do_silu)
{
    __shared__ unsigned As[16 * ASTR];
    __shared__ unsigned Bs[16 * ASTR];

    const int tid  = threadIdx.x;       // 0..127
    const int lane = tid & 31;
    const int wid  = tid >> 5;          // 0..3
    const int warpM = (wid & 1) * 64;   // 2 warps in M
    const int warpN = (wid >> 1) * 64;  // 2 warps in N

    float acc[4][8][4];
#pragma unroll
    for (int mt = 0; mt < 4; mt++)
#pragma unroll
        for (int nt = 0; nt < 8; nt++)
#pragma unroll
            for (int i = 0; i < 4; i++) acc[mt][nt][i] = 0.f;

    // A loader: f = tid + i*128 -> row = f>>2 (0..127), kq = (f&3)*4
    const int arow = tid >> 2;          // + i*32
    const int akq  = (tid & 3) << 2;
    // B loader: f = tid + i*128 -> k = f>>5 (0..15), nq = (f&31)*4
    const int bk0  = tid >> 5;          // + i*4
    const int bnq  = (tid & 31) << 2;

    float4 aval[4], bval[4];
#pragma unroll
    for (int i = 0; i < 4; i++) {
        aval[i] = *(const float4*)(A + (long)(bm + arow + i * 32) * Kd + akq);
        bval[i] = *(const float4*)(Bm + (long)(bk0 + i * 4) * N + bn + bnq);
    }

    const int nKT = Kd >> 4;
    for (int kt = 0; kt < nKT; kt++) {
        __syncthreads();
#pragma unroll
        for (int i = 0; i < 4; i++) {
            const int m = arow + i * 32;
            const float* v = (const float*)&aval[i];
#pragma unroll
            for (int j = 0; j < 4; j++) {
                const int k = akq + j;
                As[k * ASTR + (m ^ ((k >> 2) << 3))] = __float_as_uint(v[j]);
            }
            *(uint4*)&Bs[(bk0 + i * 4) * ASTR + bnq] = *(const uint4*)&bval[i];
        }
        __syncthreads();

        if (kt + 1 < nKT) {
            const int koff = (kt + 1) << 4;
#pragma unroll
            for (int i = 0; i < 4; i++) {
                aval[i] = *(const float4*)(A + (long)(bm + arow + i * 32) * Kd + koff + akq);
                bval[i] = *(const float4*)(Bm + (long)(koff + bk0 + i * 4) * N + bn + bnq);
            }
        }

#pragma unroll
        for (int k8 = 0; k8 < 16; k8 += 8) {
            unsigned af[4][4], bf[8][2];
            const int kk0 = k8 + (lane & 3);
            const int kk1 = kk0 + 4;
            const int msk0 = (kk0 >> 2) << 3;
            const int msk1 = (kk1 >> 2) << 3;
#pragma unroll
            for (int mt = 0; mt < 4; mt++) {
                const int r0 = warpM + mt * 16 + (lane >> 2);
                af[mt][0] = As[kk0 * ASTR + (r0 ^ msk0)];
                af[mt][1] = As[kk0 * ASTR + ((r0 + 8) ^ msk0)];
                af[mt][2] = As[kk1 * ASTR + (r0 ^ msk1)];
                af[mt][3] = As[kk1 * ASTR + ((r0 + 8) ^ msk1)];
            }
#pragma unroll
            for (int nt = 0; nt < 8; nt++) {
                const int n = warpN + nt * 8 + (lane >> 2);
                bf[nt][0] = Bs[kk0 * ASTR + n];
                bf[nt][1] = Bs[kk1 * ASTR + n];
            }
#pragma unroll
            for (int mt = 0; mt < 4; mt++)
#pragma unroll
                for (int nt = 0; nt < 8; nt++)
                    mma_tf32(acc[mt][nt], af[mt][0], af[mt][1], af[mt][2], af[mt][3],
                             bf[nt][0], bf[nt][1]);
        }
    }

    // epilogue
#pragma unroll
    for (int mt = 0; mt < 4; mt++) {
        const int r0 = bm + warpM + mt * 16 + (lane >> 2);
#pragma unroll
        for (int nt = 0; nt < 8; nt++) {
            const int c = bn + warpN + nt * 8 + ((lane & 3) << 1);
            float v0 = acc[mt][nt][0], v1 = acc[mt][nt][1];
            float v2 = acc[mt][nt][2], v3 = acc[mt][nt][3];
            if (do_silu) {
                v0 = v0 / (1.f + expf(-v0));
                v1 = v1 / (1.f + expf(-v1));
                v2 = v2 / (1.f + expf(-v2));
                v3 = v3 / (1.f + expf(-v3));
            }
            *(float2*)(C + (long)r0 * N + c)       = make_float2(v0, v1);
            *(float2*)(C + (long)(r0 + 8) * N + c) = make_float2(v2, v3);
        }
    }
}

// ---------------- projections: xa @ {Wq,Wk,Wv,Wg} ----------------------------
__global__ __launch_bounds__(128) void proj_gemm_kernel()
{
    const int z = blockIdx.z;
    const float* W = g_Wr + (long)z * (Dd * INNER);
    float* O;
    bool silu = false;
    switch (z) {
        case 0:  O = g_Xq; break;
        case 1:  O = g_Xk; break;
        case 2:  O = g_Xv; break;
        default: O = g_Xg; silu = true; break;
    }
    tgemm128(g_xa, W, O, Dd, INNER, blockIdx.y * 128, blockIdx.x * 128, silu);
}

// ---------------- output GEMM: g_Y @ Wo -> d_out -----------------------------
__global__ __launch_bounds__(128) void out_gemm_kernel(float* __restrict__ out)
{
    tgemm128(g_Y, g_Wr + 4L * Dd * INNER, out, INNER, Dd,
             blockIdx.y * 128, blockIdx.x * 128, false);
}

// ---------------- pre-pass: rna(x) -> g_xa -----------------------------------
__global__ __launch_bounds__(256) void cvtx_kernel(const float* __restrict__ x)
{
    const long i = ((long)blockIdx.x * 256 + threadIdx.x) * 4;
    float4 v = *(const float4*)(x + i);
    v.x = rna_tf32(v.x); v.y = rna_tf32(v.y);
    v.z = rna_tf32(v.z); v.w = rna_tf32(v.w);
    *(float4*)(g_xa + i) = v;
}

// ---------------- pre-pass: rna(W) -> g_Wr (row-major) -----------------------
__global__ __launch_bounds__(256) void wround_kernel(
    const float* __restrict__ Wq, const float* __restrict__ Wk,
    const float* __restrict__ Wv, const float* __restrict__ Wg,
    const float* __restrict__ Wo)
{
    const float* W;
    switch (blockIdx.y) {
        case 0: W = Wq; break;
        case 1: W = Wk; break;
        case 2: W = Wv; break;
        case 3: W = Wg; break;
        default: W = Wo; break;
    }
    const long i = ((long)blockIdx.x * 256 + threadIdx.x) * 4;
    float4 v = *(const float4*)(W + i);
    v.x = rna_tf32(v.x); v.y = rna_tf32(v.y);
    v.z = rna_tf32(v.z); v.w = rna_tf32(v.w);
    *(float4*)(g_Wr + (long)blockIdx.y * (Dd * INNER) + i) = v;
}

// ---------------- alpha/beta -------------------------------------------------
__global__ __launch_bounds__(256) void ab_kernel(
    const float* __restrict__ x,
    const float* __restrict__ Wa, const float* __restrict__ ba,
    const float* __restrict__ Wb, const float* __restrict__ bb)
{
    __shared__ float xs[Dd];
    const int m = blockIdx.x;
    const int tid = threadIdx.x;
    for (int i = tid; i < Dd; i += 256) xs[i] = x[(long)m * Dd + i];
    __syncthreads();
    const int out = tid >> 3;
    const int l8  = tid & 7;
    const float* W = (out < 16) ? Wa : Wb;
    const int h = out & 15;
    float s = 0.f;
    for (int kx = l8; kx < Dd; kx += 8) s = fmaf(xs[kx], W[kx * Hh + h], s);
    s += __shfl_xor_sync(0xffffffffu, s, 1);
    s += __shfl_xor_sync(0xffffffffu, s, 2);
    s += __shfl_xor_sync(0xffffffffu, s, 4);
    if (l8 == 0) {
        float bias = (out < 16) ? ba[h] : bb[h];
        g_AB[(long)m * 32 + out] = 1.f / (1.f + expf(-(s + bias)));
    }
}

// ---------------- depthwise causal conv + silu (+ l2norm for q,k) ------------
__global__ __launch_bounds__(256) void conv_kernel(
    const float* __restrict__ cq_w, const float* __restrict__ cq_b,
    const float* __restrict__ ck_w, const float* __restrict__ ck_b,
    const float* __restrict__ cv_w, const float* __restrict__ cv_b)
{
    const float* Xin; float* Out; const float* cw; const float* cb; bool donorm;
    switch (blockIdx.y) {
        case 0:  Xin = g_Xq; Out = g_Qn; cw = cq_w; cb = cq_b; donorm = true;  break;
        case 1:  Xin = g_Xk; Out = g_Kn; cw = ck_w; cb = ck_b; donorm = true;  break;
        default: Xin = g_Xv; Out = g_Vv; cw = cv_w; cb = cv_b; donorm = false; break;
    }
    const int bt = blockIdx.x;
    const int t  = bt % Tt;
    const int c0 = threadIdx.x << 2;
    const long base = (long)bt * INNER + c0;

    float acc[4];
#pragma unroll
    for (int j = 0; j < 4; j++) acc[j] = cb[c0 + j];
#pragma unroll
    for (int kk = 0; kk < 4; kk++) {
        const int dt = kk - 3;
        if (t + dt >= 0) {
            float4 xv = *(const float4*)(Xin + base + (long)dt * INNER);
            acc[0] = fmaf(xv.x, cw[(c0 + 0) * 4 + kk], acc[0]);
            acc[1] = fmaf(xv.y, cw[(c0 + 1) * 4 + kk], acc[1]);
            acc[2] = fmaf(xv.z, cw[(c0 + 2) * 4 + kk], acc[2]);
            acc[3] = fmaf(xv.w, cw[(c0 + 3) * 4 + kk], acc[3]);
        }
    }
    float s[4], ss = 0.f;
#pragma unroll
    for (int j = 0; j < 4; j++) {
        s[j] = acc[j] / (1.f + expf(-acc[j]));
        ss += s[j] * s[j];
    }
    ss += __shfl_xor_sync(0xffffffffu, ss, 1);
    ss += __shfl_xor_sync(0xffffffffu, ss, 2);
    ss += __shfl_xor_sync(0xffffffffu, ss, 4);
    ss += __shfl_xor_sync(0xffffffffu, ss, 8);
    if (donorm) {
        const float inv = 1.f / fmaxf(sqrtf(ss), 1e-12f);
#pragma unroll
        for (int j = 0; j < 4; j++) s[j] *= inv;
    }
    *(float4*)(Out + base) = make_float4(s[0], s[1], s[2], s[3]);
}

// ---------------- sequential gated delta scan --------------------------------
__global__ __launch_bounds__(256) void scan_kernel()
{
    const int bh = blockIdx.x;
    const int b = bh / Hh, h = bh % Hh;
    const int tid = threadIdx.x;
    const int r  = tid >> 2;
    const int cq = (tid & 3) << 4;

    float S[16];
#pragma unroll
    for (int j = 0; j < 16; j++) S[j] = 0.f;

    __shared__ float sk[2][64], sv[2][64], sq[2][64], sab[2][2];
    const int role = tid >> 6;
    const int li   = tid & 63;
    const long hoff = (long)h * dh;

    {
        long base = (long)(b * Tt) * INNER + hoff + li;
        if (role == 0)      sk[0][li] = g_Kn[base];
        else if (role == 1) sv[0][li] = g_Vv[base];
        else if (role == 2) sq[0][li] = g_Qn[base];
        else if (li < 2)    sab[0][li] = g_AB[(long)(b * Tt) * 32 + li * 16 + h];
    }
    __syncthreads();

    for (int t = 0; t < Tt; t++) {
        const int cur = t & 1;
        if (t + 1 < Tt) {
            const int nb = cur ^ 1;
            long base = (long)(b * Tt + t + 1) * INNER + hoff + li;
            if (role == 0)      sk[nb][li] = g_Kn[base];
            else if (role == 1) sv[nb][li] = g_Vv[base];
            else if (role == 2) sq[nb][li] = g_Qn[base];
            else if (li < 2)    sab[nb][li] = g_AB[(long)(b * Tt + t + 1) * 32 + li * 16 + h];
        }

        const float a  = sab[cur][0];
        const float be = sab[cur][1];

        float kreg[16];
#pragma unroll
        for (int j = 0; j < 16; j++) kreg[j] = sk[cur][cq + j];

        float part = 0.f;
#pragma unroll
        for (int j = 0; j < 16; j++) part = fmaf(S[j], kreg[j], part);
        part += __shfl_xor_sync(0xffffffffu, part, 1);
        part += __shfl_xor_sync(0xffffffffu, part, 2);

        const float vr   = sv[cur][r];
        const float coef = be * vr - a * be * part;

        float op = 0.f;
#pragma unroll
        for (int j = 0; j < 16; j++) {
            S[j] = fmaf(a, S[j], coef * kreg[j]);
            op   = fmaf(S[j], sq[cur][cq + j], op);
        }
        op += __shfl_xor_sync(0xffffffffu, op, 1);
        op += __shfl_xor_sync(0xffffffffu, op, 2);
        if ((tid & 3) == 0)
            g_O[(long)(b * Tt + t) * INNER + hoff + r] = op;
        __syncthreads();
    }
}

// ---------------- RMS norm + (1+gamma) + gate (tf32-rounded output) ----------
__global__ __launch_bounds__(256) void rmsgate_kernel(const float* __restrict__ gamma)
{
    const int m = blockIdx.x;
    const int tid = threadIdx.x;
    const long base = (long)m * INNER;
    float xv[4];
    float ss = 0.f;
#pragma unroll
    for (int i = 0; i < 4; i++) {
        xv[i] = g_O[base + tid + i * 256];
        ss += xv[i] * xv[i];
    }
    for (int off = 16; off; off >>= 1) ss += __shfl_xor_sync(0xffffffffu, ss, off);
    __shared__ float red[8];
    if ((tid & 31) == 0) red[tid >> 5] = ss;
    __syncthreads();
    float tot = 0.f;
#pragma unroll
    for (int w = 0; w < 8; w++) tot += red[w];
    const float inv = 1.f / sqrtf(tot * (1.f / (float)INNER) + 1e-6f);
#pragma unroll
    for (int i = 0; i < 4; i++) {
        int c = tid + i * 256;
        g_Y[base + c] = rna_tf32(xv[i] * inv * (1.f + gamma[c]) * g_Xg[base + c]);
    }
}

// ---------------- launch -----------------------------------------------------
extern "C" void kernel_launch(void* const* d_in, const int* in_sizes, int n_in,
                              void* d_out, int out_size)
{
    const float* x    = (const float*)d_in[0];
    const float* Wq   = (const float*)d_in[1];
    const float* Wk   = (const float*)d_in[2];
    const float* Wv   = (const float*)d_in[3];
    const float* Wa   = (const float*)d_in[4];
    const float* ba   = (const float*)d_in[5];
    const float* Wb   = (const float*)d_in[6];
    const float* bb   = (const float*)d_in[7];
    const float* Wg   = (const float*)d_in[8];
    const float* Wo   = (const float*)d_in[9];
    const float* cq_w = (const float*)d_in[10];
    const float* cq_b = (const float*)d_in[11];
    const float* ck_w = (const float*)d_in[12];
    const float* ck_b = (const float*)d_in[13];
    const float* cv_w = (const float*)d_in[14];
    const float* cv_b = (const float*)d_in[15];
    const float* gamma= (const float*)d_in[16];
    float* out = (float*)d_out;

    // launch order chosen so proj_gemm_kernel is the 4th launch (ncu target)
    cvtx_kernel<<<Mrows * Dd / 1024, 256>>>(x);
    wround_kernel<<<dim3(Dd * INNER / 1024, 5), 256>>>(Wq, Wk, Wv, Wg, Wo);
    ab_kernel<<<Mrows, 256>>>(x, Wa, ba, Wb, bb);
    proj_gemm_kernel<<<dim3(INNER / 128, Mrows / 128, 4), 128>>>();
    conv_kernel<<<dim3(Mrows, 3), 256>>>(cq_w, cq_b, ck_w, ck_b, cv_w, cv_b);
    scan_kernel<<<Bz * Hh, 256>>>();
    rmsgate_kernel<<<Mrows, 256>>>(gamma);
    out_gemm_kernel<<<dim3(Dd / 128, Mrows / 128), 128>>>(out);
}

// round 5
// speedup vs baseline: 2.0075x; 1.5085x over previous
#include <cuda_runtime.h>
#include <math.h>
#include <stdint.h>

// Problem constants
#define Bz 2
#define Tt 2048
#define Dd 1024
#define Hh 16
#define dh 64
#define INNER 1024
#define Mrows 4096   // B*T
#define NCHUNK 32    // chunks per sequence (T/64)
#define CPAD 65

// ---------------- scratch ----------------------------------------------------
__device__ float g_Xq[Mrows * INNER];
__device__ float g_Xk[Mrows * INNER];
__device__ float g_Xv[Mrows * INNER];
__device__ float g_Xg[Mrows * INNER];
__device__ float g_Qn[Mrows * INNER];
__device__ float g_Kn[Mrows * INNER];
__device__ float g_Vv[Mrows * INNER];
__device__ float g_AB[Mrows * 32];
__device__ float g_O [Mrows * INNER];
__device__ float g_Y [Mrows * INNER];
__device__ float g_xa[Mrows * Dd];
__device__ float g_Wr[5 * Dd * INNER];
// chunked-scan scratch: 1024 chunks x 64x64
__device__ float g_T [1024 * 4096];
__device__ float g_W [1024 * 4096];
__device__ float g_M [1024 * 4096];
__device__ float g_N [1024 * 4096];
__device__ float g_S0[1024 * 4096];
__device__ float g_gam[1024 * 64];
__device__ float g_r  [1024 * 64];

// ---------------- tf32 helpers -----------------------------------------------
__device__ __forceinline__ unsigned cvt_tf32(float f) {
    unsigned u;
    asm("cvt.rna.tf32.f32 %0, %1;" : "=r"(u) : "f"(f));
    return u;
}
__device__ __forceinline__ float rna_tf32(float f) {
    return __uint_as_float(cvt_tf32(f));
}

__device__ __forceinline__ void mma_tf32(float* d, unsigned a0, unsigned a1,
                                         unsigned a2, unsigned a3,
                                         unsigned b0, unsigned b1) {
    asm("mma.sync.aligned.m16n8k8.row.col.f32.tf32.tf32.f32 "
        "{%0,%1,%2,%3}, {%4,%5,%6,%7}, {%8,%9}, {%0,%1,%2,%3};\n"
        : "+f"(d[0]), "+f"(d[1]), "+f"(d[2]), "+f"(d[3])
        : "r"(a0), "r"(a1), "r"(a2), "r"(a3), "r"(b0), "r"(b1));
}

// ---------------- tf32 tensor-core GEMM (as round 4) -------------------------
#define ASTR 136
__device__ __forceinline__ void tgemm128(const float* __restrict__ A,
                                         const float* __restrict__ Bm,
                                         float* __restrict__ C,
                                         int Kd, int N, int bm, int bn,
                                         bool do_silu)
{
    __shared__ unsigned As[16 * ASTR];
    __shared__ unsigned Bs[16 * ASTR];

    const int tid  = threadIdx.x;
    const int lane = tid & 31;
    const int wid  = tid >> 5;
    const int warpM = (wid & 1) * 64;
    const int warpN = (wid >> 1) * 64;

    float acc[4][8][4];
#pragma unroll
    for (int mt = 0; mt < 4; mt++)
#pragma unroll
        for (int nt = 0; nt < 8; nt++)
#pragma unroll
            for (int i = 0; i < 4; i++) acc[mt][nt][i] = 0.f;

    const int arow = tid >> 2;
    const int akq  = (tid & 3) << 2;
    const int bk0  = tid >> 5;
    const int bnq  = (tid & 31) << 2;

    float4 aval[4], bval[4];
#pragma unroll
    for (int i = 0; i < 4; i++) {
        aval[i] = *(const float4*)(A + (long)(bm + arow + i * 32) * Kd + akq);
        bval[i] = *(const float4*)(Bm + (long)(bk0 + i * 4) * N + bn + bnq);
    }

    const int nKT = Kd >> 4;
    for (int kt = 0; kt < nKT; kt++) {
        __syncthreads();
#pragma unroll
        for (int i = 0; i < 4; i++) {
            const int m = arow + i * 32;
            const float* v = (const float*)&aval[i];
#pragma unroll
            for (int j = 0; j < 4; j++) {
                const int k = akq + j;
                As[k * ASTR + (m ^ ((k >> 2) << 3))] = __float_as_uint(v[j]);
            }
            *(uint4*)&Bs[(bk0 + i * 4) * ASTR + bnq] = *(const uint4*)&bval[i];
        }
        __syncthreads();

        if (kt + 1 < nKT) {
            const int koff = (kt + 1) << 4;
#pragma unroll
            for (int i = 0; i < 4; i++) {
                aval[i] = *(const float4*)(A + (long)(bm + arow + i * 32) * Kd + koff + akq);
                bval[i] = *(const float4*)(Bm + (long)(koff + bk0 + i * 4) * N + bn + bnq);
            }
        }

#pragma unroll
        for (int k8 = 0; k8 < 16; k8 += 8) {
            unsigned af[4][4], bf[8][2];
            const int kk0 = k8 + (lane & 3);
            const int kk1 = kk0 + 4;
            const int msk0 = (kk0 >> 2) << 3;
            const int msk1 = (kk1 >> 2) << 3;
#pragma unroll
            for (int mt = 0; mt < 4; mt++) {
                const int r0 = warpM + mt * 16 + (lane >> 2);
                af[mt][0] = As[kk0 * ASTR + (r0 ^ msk0)];
                af[mt][1] = As[kk0 * ASTR + ((r0 + 8) ^ msk0)];
                af[mt][2] = As[kk1 * ASTR + (r0 ^ msk1)];
                af[mt][3] = As[kk1 * ASTR + ((r0 + 8) ^ msk1)];
            }
#pragma unroll
            for (int nt = 0; nt < 8; nt++) {
                const int n = warpN + nt * 8 + (lane >> 2);
                bf[nt][0] = Bs[kk0 * ASTR + n];
                bf[nt][1] = Bs[kk1 * ASTR + n];
            }
#pragma unroll
            for (int mt = 0; mt < 4; mt++)
#pragma unroll
                for (int nt = 0; nt < 8; nt++)
                    mma_tf32(acc[mt][nt], af[mt][0], af[mt][1], af[mt][2], af[mt][3],
                             bf[nt][0], bf[nt][1]);
        }
    }

#pragma unroll
    for (int mt = 0; mt < 4; mt++) {
        const int r0 = bm + warpM + mt * 16 + (lane >> 2);
#pragma unroll
        for (int nt = 0; nt < 8; nt++) {
            const int c = bn + warpN + nt * 8 + ((lane & 3) << 1);
            float v0 = acc[mt][nt][0], v1 = acc[mt][nt][1];
            float v2 = acc[mt][nt][2], v3 = acc[mt][nt][3];
            if (do_silu) {
                v0 = v0 / (1.f + expf(-v0));
                v1 = v1 / (1.f + expf(-v1));
                v2 = v2 / (1.f + expf(-v2));
                v3 = v3 / (1.f + expf(-v3));
            }
            *(float2*)(C + (long)r0 * N + c)       = make_float2(v0, v1);
            *(float2*)(C + (long)(r0 + 8) * N + c) = make_float2(v2, v3);
        }
    }
}

__global__ __launch_bounds__(128) void proj_gemm_kernel()
{
    const int z = blockIdx.z;
    const float* W = g_Wr + (long)z * (Dd * INNER);
    float* O;
    bool silu = false;
    switch (z) {
        case 0:  O = g_Xq; break;
        case 1:  O = g_Xk; break;
        case 2:  O = g_Xv; break;
        default: O = g_Xg; silu = true; break;
    }
    tgemm128(g_xa, W, O, Dd, INNER, blockIdx.y * 128, blockIdx.x * 128, silu);
}

__global__ __launch_bounds__(128) void out_gemm_kernel(float* __restrict__ out)
{
    tgemm128(g_Y, g_Wr + 4L * Dd * INNER, out, INNER, Dd,
             blockIdx.y * 128, blockIdx.x * 128, false);
}

// ---------------- pre-passes -------------------------------------------------
__global__ __launch_bounds__(256) void cvtx_kernel(const float* __restrict__ x)
{
    const long i = ((long)blockIdx.x * 256 + threadIdx.x) * 4;
    float4 v = *(const float4*)(x + i);
    v.x = rna_tf32(v.x); v.y = rna_tf32(v.y);
    v.z = rna_tf32(v.z); v.w = rna_tf32(v.w);
    *(float4*)(g_xa + i) = v;
}

__global__ __launch_bounds__(256) void wround_kernel(
    const float* __restrict__ Wq, const float* __restrict__ Wk,
    const float* __restrict__ Wv, const float* __restrict__ Wg,
    const float* __restrict__ Wo)
{
    const float* W;
    switch (blockIdx.y) {
        case 0: W = Wq; break;
        case 1: W = Wk; break;
        case 2: W = Wv; break;
        case 3: W = Wg; break;
        default: W = Wo; break;
    }
    const long i = ((long)blockIdx.x * 256 + threadIdx.x) * 4;
    float4 v = *(const float4*)(W + i);
    v.x = rna_tf32(v.x); v.y = rna_tf32(v.y);
    v.z = rna_tf32(v.z); v.w = rna_tf32(v.w);
    *(float4*)(g_Wr + (long)blockIdx.y * (Dd * INNER) + i) = v;
}

// ---------------- alpha/beta -------------------------------------------------
__global__ __launch_bounds__(256) void ab_kernel(
    const float* __restrict__ x,
    const float* __restrict__ Wa, const float* __restrict__ ba,
    const float* __restrict__ Wb, const float* __restrict__ bb)
{
    __shared__ float xs[Dd];
    const int m = blockIdx.x;
    const int tid = threadIdx.x;
    for (int i = tid; i < Dd; i += 256) xs[i] = x[(long)m * Dd + i];
    __syncthreads();
    const int out = tid >> 3;
    const int l8  = tid & 7;
    const float* W = (out < 16) ? Wa : Wb;
    const int h = out & 15;
    float s = 0.f;
    for (int kx = l8; kx < Dd; kx += 8) s = fmaf(xs[kx], W[kx * Hh + h], s);
    s += __shfl_xor_sync(0xffffffffu, s, 1);
    s += __shfl_xor_sync(0xffffffffu, s, 2);
    s += __shfl_xor_sync(0xffffffffu, s, 4);
    if (l8 == 0) {
        float bias = (out < 16) ? ba[h] : bb[h];
        g_AB[(long)m * 32 + out] = 1.f / (1.f + expf(-(s + bias)));
    }
}

// ---------------- depthwise causal conv + silu (+ l2norm for q,k) ------------
__global__ __launch_bounds__(256) void conv_kernel(
    const float* __restrict__ cq_w, const float* __restrict__ cq_b,
    const float* __restrict__ ck_w, const float* __restrict__ ck_b,
    const float* __restrict__ cv_w, const float* __restrict__ cv_b)
{
    const float* Xin; float* Out; const float* cw; const float* cb; bool donorm;
    switch (blockIdx.y) {
        case 0:  Xin = g_Xq; Out = g_Qn; cw = cq_w; cb = cq_b; donorm = true;  break;
        case 1:  Xin = g_Xk; Out = g_Kn; cw = ck_w; cb = ck_b; donorm = true;  break;
        default: Xin = g_Xv; Out = g_Vv; cw = cv_w; cb = cv_b; donorm = false; break;
    }
    const int bt = blockIdx.x;
    const int t  = bt % Tt;
    const int c0 = threadIdx.x << 2;
    const long base = (long)bt * INNER + c0;

    float acc[4];
#pragma unroll
    for (int j = 0; j < 4; j++) acc[j] = cb[c0 + j];
#pragma unroll
    for (int kk = 0; kk < 4; kk++) {
        const int dt = kk - 3;
        if (t + dt >= 0) {
            float4 xv = *(const float4*)(Xin + base + (long)dt * INNER);
            acc[0] = fmaf(xv.x, cw[(c0 + 0) * 4 + kk], acc[0]);
            acc[1] = fmaf(xv.y, cw[(c0 + 1) * 4 + kk], acc[1]);
            acc[2] = fmaf(xv.z, cw[(c0 + 2) * 4 + kk], acc[2]);
            acc[3] = fmaf(xv.w, cw[(c0 + 3) * 4 + kk], acc[3]);
        }
    }
    float s[4], ss = 0.f;
#pragma unroll
    for (int j = 0; j < 4; j++) {
        s[j] = acc[j] / (1.f + expf(-acc[j]));
        ss += s[j] * s[j];
    }
    ss += __shfl_xor_sync(0xffffffffu, ss, 1);
    ss += __shfl_xor_sync(0xffffffffu, ss, 2);
    ss += __shfl_xor_sync(0xffffffffu, ss, 4);
    ss += __shfl_xor_sync(0xffffffffu, ss, 8);
    if (donorm) {
        const float inv = 1.f / fmaxf(sqrtf(ss), 1e-12f);
#pragma unroll
        for (int j = 0; j < 4; j++) s[j] *= inv;
    }
    *(float4*)(Out + base) = make_float4(s[0], s[1], s[2], s[3]);
}

// ============== chunked delta-rule scan ======================================
// chunk id = ((b*H + h)*NCHUNK + c); rows t = b*T + c*64 + i; cols h*64 + j.
//  prep:  L[j][i] = gam[j]*r[i]*<k_i,k_j> (i<j);  (I+L)T = V; (I+L)W = diag(gam)K
//         M = gam63*I - W^T diag(gam63*r) K;  N = T^T diag(gam63*r) K
//  scan:  S0[c] = S;  S = S*M + N    (serial over c, parallel over b,h)
//  out:   U = T - W*S0^T;  A[t][j] = gam[t]*r[j]*<k_j,q_t> (j<=t)
//         O = diag(gam) Q S0^T + A*U

__global__ __launch_bounds__(256) void chunk_prep_kernel()
{
    extern __shared__ float sm[];
    float* sK = sm;                 // [64][CPAD]
    float* sV = sm + 64 * CPAD;     // V -> T
    float* sW = sm + 2 * 64 * CPAD; // -> W
    float* sL = sm + 3 * 64 * CPAD;
    float* sGam = sm + 4 * 64 * CPAD;
    float* sR   = sGam + 64;

    const int chunk = blockIdx.x;
    const int c  = chunk & (NCHUNK - 1);
    const int bh = chunk >> 5;
    const int b = bh >> 4, h = bh & 15;
    const int tid = threadIdx.x;
    const long rowbase = (long)b * Tt + c * 64;
    const int colbase = h * dh;

    for (int idx = tid; idx < 1024; idx += 256) {
        const int row = idx >> 4;
        const int c4  = (idx & 15) << 2;
        const long g = (rowbase + row) * INNER + colbase + c4;
        float4 kv = *(const float4*)(g_Kn + g);
        float4 vv = *(const float4*)(g_Vv + g);
        sK[row * CPAD + c4 + 0] = kv.x; sK[row * CPAD + c4 + 1] = kv.y;
        sK[row * CPAD + c4 + 2] = kv.z; sK[row * CPAD + c4 + 3] = kv.w;
        sV[row * CPAD + c4 + 0] = vv.x; sV[row * CPAD + c4 + 1] = vv.y;
        sV[row * CPAD + c4 + 2] = vv.z; sV[row * CPAD + c4 + 3] = vv.w;
    }
    if (tid < 64) {
        sGam[tid] = g_AB[(rowbase + tid) * 32 + h];        // a
        sR[tid]   = g_AB[(rowbase + tid) * 32 + 16 + h];   // b
    }
    __syncthreads();
    if (tid == 0) {
        float p = 1.f;
        for (int i = 0; i < 64; i++) { p *= sGam[i]; sGam[i] = p; }
    }
    __syncthreads();
    if (tid < 64) sR[tid] = sR[tid] / sGam[tid];
    __syncthreads();

    // L (strict lower)
#pragma unroll
    for (int e = 0; e < 16; e++) {
        const int idx = e * 256 + tid;
        const int j = idx >> 6, i = idx & 63;
        float dt = 0.f;
        if (i < j) {
#pragma unroll 8
            for (int k = 0; k < 64; k++)
                dt = fmaf(sK[i * CPAD + k], sK[j * CPAD + k], dt);
            dt *= sGam[j] * sR[i];
        }
        sL[j * CPAD + i] = dt;
    }
    __syncthreads();

    // forward substitution: cols 0..63 -> T (in sV), cols 64..127 -> W (in sW)
    {
        const int col = tid;
        const int cc = col & 63;
        float* dst = (col < 64) ? sV : sW;
        for (int j = 0; j < 64; j++) {
            float val = 0.f;
            if (col < 128) {
                float s = 0.f;
                for (int i = 0; i < j; i++)
                    s = fmaf(sL[j * CPAD + i], dst[i * CPAD + cc], s);
                const float rhs = (col < 64) ? sV[j * CPAD + cc]
                                             : sGam[j] * sK[j * CPAD + cc];
                val = rhs - s;
                dst[j * CPAD + cc] = val;
            }
            __syncthreads();
        }
    }

    // write T, W
    for (int idx = tid; idx < 4096; idx += 256) {
        g_T[(long)chunk * 4096 + idx] = sV[(idx >> 6) * CPAD + (idx & 63)];
        g_W[(long)chunk * 4096 + idx] = sW[(idx >> 6) * CPAD + (idx & 63)];
    }
    if (tid < 64) {
        g_gam[chunk * 64 + tid] = sGam[tid];
        g_r  [chunk * 64 + tid] = sR[tid];
    }

    // scale K rows by gam63*r[j]
    const float gC = sGam[63];
    __syncthreads();
    for (int idx = tid; idx < 4096; idx += 256) {
        const int j = idx >> 6;
        sK[j * CPAD + (idx & 63)] *= gC * sR[j];
    }
    __syncthreads();

    // M, N
    const int p  = tid >> 2;
    const int q0 = tid & 3;
#pragma unroll
    for (int e = 0; e < 16; e++) {
        const int q = q0 + 4 * e;
        float mm = 0.f, nn = 0.f;
#pragma unroll 8
        for (int j = 0; j < 64; j++) {
            const float kq = sK[j * CPAD + q];
            mm = fmaf(sW[j * CPAD + p], kq, mm);
            nn = fmaf(sV[j * CPAD + p], kq, nn);
        }
        g_M[(long)chunk * 4096 + p * 64 + q] = (p == q ? gC : 0.f) - mm;
        g_N[(long)chunk * 4096 + p * 64 + q] = nn;
    }
}

__global__ __launch_bounds__(256) void chunk_scan_kernel()
{
    __shared__ float sS[64 * CPAD];
    __shared__ float sM[64 * CPAD];
    const int bh = blockIdx.x;
    const int tid = threadIdx.x;
    const int i  = tid >> 2;
    const int q0 = tid & 3;

    for (int idx = tid; idx < 4096; idx += 256)
        sS[(idx >> 6) * CPAD + (idx & 63)] = 0.f;
    __syncthreads();

    for (int c = 0; c < NCHUNK; c++) {
        const long cb = (long)(bh * NCHUNK + c) * 4096;
        for (int idx = tid; idx < 4096; idx += 256) {
            g_S0[cb + idx] = sS[(idx >> 6) * CPAD + (idx & 63)];
            sM[(idx >> 6) * CPAD + (idx & 63)] = g_M[cb + idx];
        }
        __syncthreads();
        float acc[16];
#pragma unroll
        for (int e = 0; e < 16; e++)
            acc[e] = g_N[cb + i * 64 + q0 + 4 * e];
#pragma unroll 8
        for (int k = 0; k < 64; k++) {
            const float sik = sS[i * CPAD + k];
#pragma unroll
            for (int e = 0; e < 16; e++)
                acc[e] = fmaf(sik, sM[k * CPAD + q0 + 4 * e], acc[e]);
        }
        __syncthreads();
#pragma unroll
        for (int e = 0; e < 16; e++)
            sS[i * CPAD + q0 + 4 * e] = acc[e];
        __syncthreads();
    }
}

__global__ __launch_bounds__(256) void chunk_out_kernel()
{
    extern __shared__ float sm[];
    float* sQ  = sm;
    float* sK2 = sm + 64 * CPAD;
    float* sS0 = sm + 2 * 64 * CPAD;
    float* sTU = sm + 3 * 64 * CPAD;   // T -> U
    float* sWA = sm + 4 * 64 * CPAD;   // W -> A
    float* sGam = sm + 5 * 64 * CPAD;
    float* sR   = sGam + 64;

    const int chunk = blockIdx.x;
    const int c  = chunk & (NCHUNK - 1);
    const int bh = chunk >> 5;
    const int b = bh >> 4, h = bh & 15;
    const int tid = threadIdx.x;
    const long rowbase = (long)b * Tt + c * 64;
    const int colbase = h * dh;
    const long cb = (long)chunk * 4096;

    for (int idx = tid; idx < 1024; idx += 256) {
        const int row = idx >> 4;
        const int c4  = (idx & 15) << 2;
        float4 qv = *(const float4*)(g_Qn + (rowbase + row) * INNER + colbase + c4);
        sQ[row * CPAD + c4 + 0] = qv.x; sQ[row * CPAD + c4 + 1] = qv.y;
        sQ[row * CPAD + c4 + 2] = qv.z; sQ[row * CPAD + c4 + 3] = qv.w;
        float4 kv = *(const float4*)(g_Kn + (rowbase + row) * INNER + colbase + c4);
        sK2[row * CPAD + c4 + 0] = kv.x; sK2[row * CPAD + c4 + 1] = kv.y;
        sK2[row * CPAD + c4 + 2] = kv.z; sK2[row * CPAD + c4 + 3] = kv.w;
    }
    for (int idx = tid; idx < 4096; idx += 256) {
        const int r = idx >> 6, cc = idx & 63;
        sS0[r * CPAD + cc] = g_S0[cb + idx];
        sTU[r * CPAD + cc] = g_T[cb + idx];
        sWA[r * CPAD + cc] = g_W[cb + idx];
    }
    if (tid < 64) {
        sGam[tid] = g_gam[chunk * 64 + tid];
        sR[tid]   = g_r[chunk * 64 + tid];
    }
    __syncthreads();

    const int t  = tid >> 2;     // also j-row / p
    const int q0 = tid & 3;

    // Phase 1: U = T - W * S0^T   (U[j][a], a = v-dim)
    float u[16];
#pragma unroll
    for (int e = 0; e < 16; e++) {
        const int a = q0 + 4 * e;
        float s = sTU[t * CPAD + a];
#pragma unroll 8
        for (int k = 0; k < 64; k++)
            s = fmaf(-sWA[t * CPAD + k], sS0[a * CPAD + k], s);
        u[e] = s;
    }
    __syncthreads();
#pragma unroll
    for (int e = 0; e < 16; e++) sTU[t * CPAD + q0 + 4 * e] = u[e];
    __syncthreads();

    // Phase 2: A[t][j] = (j<=t) ? gam[t]*r[j]*<q_t,k_j> : 0  -> sWA
    float av[16];
#pragma unroll
    for (int e = 0; e < 16; e++) {
        const int j = q0 + 4 * e;
        float s = 0.f;
        if (j <= t) {
#pragma unroll 8
            for (int k = 0; k < 64; k++)
                s = fmaf(sQ[t * CPAD + k], sK2[j * CPAD + k], s);
            s *= sGam[t] * sR[j];
        }
        av[e] = s;
    }
    __syncthreads();
#pragma unroll
    for (int e = 0; e < 16; e++) sWA[t * CPAD + q0 + 4 * e] = av[e];
    __syncthreads();

    // Phase 3: O[t][a] = gam[t]*(Q S0^T)[t][a] + (A U)[t][a]
#pragma unroll
    for (int e = 0; e < 16; e++) {
        const int a = q0 + 4 * e;
        float s1 = 0.f;
#pragma unroll 8
        for (int k = 0; k < 64; k++)
            s1 = fmaf(sQ[t * CPAD + k], sS0[a * CPAD + k], s1);
        float s2 = 0.f;
#pragma unroll 8
        for (int j = 0; j < 64; j++)
            s2 = fmaf(sWA[t * CPAD + j], sTU[j * CPAD + a], s2);
        g_O[(rowbase + t) * INNER + colbase + a] = sGam[t] * s1 + s2;
    }
}

// ---------------- RMS norm + (1+gamma) + gate --------------------------------
__global__ __launch_bounds__(256) void rmsgate_kernel(const float* __restrict__ gamma)
{
    const int m = blockIdx.x;
    const int tid = threadIdx.x;
    const long base = (long)m * INNER;
    float xv[4];
    float ss = 0.f;
#pragma unroll
    for (int i = 0; i < 4; i++) {
        xv[i] = g_O[base + tid + i * 256];
        ss += xv[i] * xv[i];
    }
    for (int off = 16; off; off >>= 1) ss += __shfl_xor_sync(0xffffffffu, ss, off);
    __shared__ float red[8];
    if ((tid & 31) == 0) red[tid >> 5] = ss;
    __syncthreads();
    float tot = 0.f;
#pragma unroll
    for (int w = 0; w < 8; w++) tot += red[w];
    const float inv = 1.f / sqrtf(tot * (1.f / (float)INNER) + 1e-6f);
#pragma unroll
    for (int i = 0; i < 4; i++) {
        int c = tid + i * 256;
        g_Y[base + c] = rna_tf32(xv[i] * inv * (1.f + gamma[c]) * g_Xg[base + c]);
    }
}

// ---------------- launch -----------------------------------------------------
extern "C" void kernel_launch(void* const* d_in, const int* in_sizes, int n_in,
                              void* d_out, int out_size)
{
    const float* x    = (const float*)d_in[0];
    const float* Wq   = (const float*)d_in[1];
    const float* Wk   = (const float*)d_in[2];
    const float* Wv   = (const float*)d_in[3];
    const float* Wa   = (const float*)d_in[4];
    const float* ba   = (const float*)d_in[5];
    const float* Wb   = (const float*)d_in[6];
    const float* bb   = (const float*)d_in[7];
    const float* Wg   = (const float*)d_in[8];
    const float* Wo   = (const float*)d_in[9];
    const float* cq_w = (const float*)d_in[10];
    const float* cq_b = (const float*)d_in[11];
    const float* ck_w = (const float*)d_in[12];
    const float* ck_b = (const float*)d_in[13];
    const float* cv_w = (const float*)d_in[14];
    const float* cv_b = (const float*)d_in[15];
    const float* gamma= (const float*)d_in[16];
    float* out = (float*)d_out;

    const int prep_smem = (4 * 64 * CPAD + 128) * sizeof(float);   // ~67 KB
    const int out_smem  = (5 * 64 * CPAD + 128) * sizeof(float);   // ~84 KB
    cudaFuncSetAttribute(chunk_prep_kernel,
                         cudaFuncAttributeMaxDynamicSharedMemorySize, prep_smem);
    cudaFuncSetAttribute(chunk_out_kernel,
                         cudaFuncAttributeMaxDynamicSharedMemorySize, out_smem);

    cvtx_kernel<<<Mrows * Dd / 1024, 256>>>(x);
    wround_kernel<<<dim3(Dd * INNER / 1024, 5), 256>>>(Wq, Wk, Wv, Wg, Wo);
    ab_kernel<<<Mrows, 256>>>(x, Wa, ba, Wb, bb);
    proj_gemm_kernel<<<dim3(INNER / 128, Mrows / 128, 4), 128>>>();
    conv_kernel<<<dim3(Mrows, 3), 256>>>(cq_w, cq_b, ck_w, ck_b, cv_w, cv_b);
    chunk_prep_kernel<<<1024, 256, prep_smem>>>();
    chunk_scan_kernel<<<Bz * Hh, 256>>>();
    chunk_out_kernel<<<1024, 256, out_smem>>>();
    rmsgate_kernel<<<Mrows, 256>>>(gamma);
    out_gemm_kernel<<<dim3(Dd / 128, Mrows / 128), 128>>>(out);
}

// round 6
// speedup vs baseline: 3.6773x; 1.8318x over previous
#include <cuda_runtime.h>
#include <math.h>
#include <stdint.h>

// Problem constants
#define Bz 2
#define Tt 2048
#define Dd 1024
#define Hh 16
#define dh 64
#define INNER 1024
#define Mrows 4096   // B*T
#define NCHUNK 32
#define CP 65        // padded stride for 64x64 smem tiles

// ---------------- scratch ----------------------------------------------------
__device__ float g_Xq[Mrows * INNER];
__device__ float g_Xk[Mrows * INNER];
__device__ float g_Xv[Mrows * INNER];
__device__ float g_Xg[Mrows * INNER];
__device__ float g_Qn[Mrows * INNER];
__device__ float g_Kn[Mrows * INNER];
__device__ float g_Vv[Mrows * INNER];
__device__ float g_AB[Mrows * 32];
__device__ float g_O [Mrows * INNER];
__device__ float g_Y [Mrows * INNER];
__device__ float g_xa[Mrows * Dd];
__device__ float g_Wr[5 * Dd * INNER];
__device__ float g_T [1024 * 4096];
__device__ float g_W [1024 * 4096];
__device__ float g_M [1024 * 4096];
__device__ float g_N [1024 * 4096];
__device__ float g_S0[1024 * 4096];
__device__ float g_gam[1024 * 64];
__device__ float g_r  [1024 * 64];

// ---------------- tf32 helpers -----------------------------------------------
__device__ __forceinline__ unsigned cvt_tf32(float f) {
    unsigned u;
    asm("cvt.rna.tf32.f32 %0, %1;" : "=r"(u) : "f"(f));
    return u;
}
__device__ __forceinline__ float rna_tf32(float f) {
    return __uint_as_float(cvt_tf32(f));
}

__device__ __forceinline__ void mma_tf32(float* d, unsigned a0, unsigned a1,
                                         unsigned a2, unsigned a3,
                                         unsigned b0, unsigned b1) {
    asm("mma.sync.aligned.m16n8k8.row.col.f32.tf32.tf32.f32 "
        "{%0,%1,%2,%3}, {%4,%5,%6,%7}, {%8,%9}, {%0,%1,%2,%3};\n"
        : "+f"(d[0]), "+f"(d[1]), "+f"(d[2]), "+f"(d[3])
        : "r"(a0), "r"(a1), "r"(a2), "r"(a3), "r"(b0), "r"(b1));
}

// ---------------- tf32 tensor-core GEMM (unchanged, proven) ------------------
#define ASTR 136
__device__ __forceinline__ void tgemm128(const float* __restrict__ A,
                                         const float* __restrict__ Bm,
                                         float* __restrict__ C,
                                         int Kd, int N, int bm, int bn,
                                         bool do_silu)
{
    __shared__ unsigned As[16 * ASTR];
    __shared__ unsigned Bs[16 * ASTR];

    const int tid  = threadIdx.x;
    const int lane = tid & 31;
    const int wid  = tid >> 5;
    const int warpM = (wid & 1) * 64;
    const int warpN = (wid >> 1) * 64;

    float acc[4][8][4];
#pragma unroll
    for (int mt = 0; mt < 4; mt++)
#pragma unroll
        for (int nt = 0; nt < 8; nt++)
#pragma unroll
            for (int i = 0; i < 4; i++) acc[mt][nt][i] = 0.f;

    const int arow = tid >> 2;
    const int akq  = (tid & 3) << 2;
    const int bk0  = tid >> 5;
    const int bnq  = (tid & 31) << 2;

    float4 aval[4], bval[4];
#pragma unroll
    for (int i = 0; i < 4; i++) {
        aval[i] = *(const float4*)(A + (long)(bm + arow + i * 32) * Kd + akq);
        bval[i] = *(const float4*)(Bm + (long)(bk0 + i * 4) * N + bn + bnq);
    }

    const int nKT = Kd >> 4;
    for (int kt = 0; kt < nKT; kt++) {
        __syncthreads();
#pragma unroll
        for (int i = 0; i < 4; i++) {
            const int m = arow + i * 32;
            const float* v = (const float*)&aval[i];
#pragma unroll
            for (int j = 0; j < 4; j++) {
                const int k = akq + j;
                As[k * ASTR + (m ^ ((k >> 2) << 3))] = __float_as_uint(v[j]);
            }
            *(uint4*)&Bs[(bk0 + i * 4) * ASTR + bnq] = *(const uint4*)&bval[i];
        }
        __syncthreads();

        if (kt + 1 < nKT) {
            const int koff = (kt + 1) << 4;
#pragma unroll
            for (int i = 0; i < 4; i++) {
                aval[i] = *(const float4*)(A + (long)(bm + arow + i * 32) * Kd + koff + akq);
                bval[i] = *(const float4*)(Bm + (long)(koff + bk0 + i * 4) * N + bn + bnq);
            }
        }

#pragma unroll
        for (int k8 = 0; k8 < 16; k8 += 8) {
            unsigned af[4][4], bf[8][2];
            const int kk0 = k8 + (lane & 3);
            const int kk1 = kk0 + 4;
            const int msk0 = (kk0 >> 2) << 3;
            const int msk1 = (kk1 >> 2) << 3;
#pragma unroll
            for (int mt = 0; mt < 4; mt++) {
                const int r0 = warpM + mt * 16 + (lane >> 2);
                af[mt][0] = As[kk0 * ASTR + (r0 ^ msk0)];
                af[mt][1] = As[kk0 * ASTR + ((r0 + 8) ^ msk0)];
                af[mt][2] = As[kk1 * ASTR + (r0 ^ msk1)];
                af[mt][3] = As[kk1 * ASTR + ((r0 + 8) ^ msk1)];
            }
#pragma unroll
            for (int nt = 0; nt < 8; nt++) {
                const int n = warpN + nt * 8 + (lane >> 2);
                bf[nt][0] = Bs[kk0 * ASTR + n];
                bf[nt][1] = Bs[kk1 * ASTR + n];
            }
#pragma unroll
            for (int mt = 0; mt < 4; mt++)
#pragma unroll
                for (int nt = 0; nt < 8; nt++)
                    mma_tf32(acc[mt][nt], af[mt][0], af[mt][1], af[mt][2], af[mt][3],
                             bf[nt][0], bf[nt][1]);
        }
    }

#pragma unroll
    for (int mt = 0; mt < 4; mt++) {
        const int r0 = bm + warpM + mt * 16 + (lane >> 2);
#pragma unroll
        for (int nt = 0; nt < 8; nt++) {
            const int c = bn + warpN + nt * 8 + ((lane & 3) << 1);
            float v0 = acc[mt][nt][0], v1 = acc[mt][nt][1];
            float v2 = acc[mt][nt][2], v3 = acc[mt][nt][3];
            if (do_silu) {
                v0 = v0 / (1.f + expf(-v0));
                v1 = v1 / (1.f + expf(-v1));
                v2 = v2 / (1.f + expf(-v2));
                v3 = v3 / (1.f + expf(-v3));
            }
            *(float2*)(C + (long)r0 * N + c)       = make_float2(v0, v1);
            *(float2*)(C + (long)(r0 + 8) * N + c) = make_float2(v2, v3);
        }
    }
}

__global__ __launch_bounds__(128) void proj_gemm_kernel()
{
    const int z = blockIdx.z;
    const float* W = g_Wr + (long)z * (Dd * INNER);
    float* O;
    bool silu = false;
    switch (z) {
        case 0:  O = g_Xq; break;
        case 1:  O = g_Xk; break;
        case 2:  O = g_Xv; break;
        default: O = g_Xg; silu = true; break;
    }
    tgemm128(g_xa, W, O, Dd, INNER, blockIdx.y * 128, blockIdx.x * 128, silu);
}

__global__ __launch_bounds__(128) void out_gemm_kernel(float* __restrict__ out)
{
    tgemm128(g_Y, g_Wr + 4L * Dd * INNER, out, INNER, Dd,
             blockIdx.y * 128, blockIdx.x * 128, false);
}

// ---------------- pre-passes -------------------------------------------------
__global__ __launch_bounds__(256) void cvtx_kernel(const float* __restrict__ x)
{
    const long i = ((long)blockIdx.x * 256 + threadIdx.x) * 4;
    float4 v = *(const float4*)(x + i);
    v.x = rna_tf32(v.x); v.y = rna_tf32(v.y);
    v.z = rna_tf32(v.z); v.w = rna_tf32(v.w);
    *(float4*)(g_xa + i) = v;
}

__global__ __launch_bounds__(256) void wround_kernel(
    const float* __restrict__ Wq, const float* __restrict__ Wk,
    const float* __restrict__ Wv, const float* __restrict__ Wg,
    const float* __restrict__ Wo)
{
    const float* W;
    switch (blockIdx.y) {
        case 0: W = Wq; break;
        case 1: W = Wk; break;
        case 2: W = Wv; break;
        case 3: W = Wg; break;
        default: W = Wo; break;
    }
    const long i = ((long)blockIdx.x * 256 + threadIdx.x) * 4;
    float4 v = *(const float4*)(W + i);
    v.x = rna_tf32(v.x); v.y = rna_tf32(v.y);
    v.z = rna_tf32(v.z); v.w = rna_tf32(v.w);
    *(float4*)(g_Wr + (long)blockIdx.y * (Dd * INNER) + i) = v;
}

// ---------------- alpha/beta -------------------------------------------------
__global__ __launch_bounds__(256) void ab_kernel(
    const float* __restrict__ x,
    const float* __restrict__ Wa, const float* __restrict__ ba,
    const float* __restrict__ Wb, const float* __restrict__ bb)
{
    __shared__ float xs[Dd];
    const int m = blockIdx.x;
    const int tid = threadIdx.x;
    for (int i = tid; i < Dd; i += 256) xs[i] = x[(long)m * Dd + i];
    __syncthreads();
    const int out = tid >> 3;
    const int l8  = tid & 7;
    const float* W = (out < 16) ? Wa : Wb;
    const int h = out & 15;
    float s = 0.f;
    for (int kx = l8; kx < Dd; kx += 8) s = fmaf(xs[kx], W[kx * Hh + h], s);
    s += __shfl_xor_sync(0xffffffffu, s, 1);
    s += __shfl_xor_sync(0xffffffffu, s, 2);
    s += __shfl_xor_sync(0xffffffffu, s, 4);
    if (l8 == 0) {
        float bias = (out < 16) ? ba[h] : bb[h];
        g_AB[(long)m * 32 + out] = 1.f / (1.f + expf(-(s + bias)));
    }
}

// ---------------- conv: 16 timesteps per thread, warp-per-head ---------------
__global__ __launch_bounds__(128) void conv_kernel(
    const float* __restrict__ cq_w, const float* __restrict__ cq_b,
    const float* __restrict__ ck_w, const float* __restrict__ ck_b,
    const float* __restrict__ cv_w, const float* __restrict__ cv_b)
{
    const float* Xin; float* Out; const float* cw; const float* cb; bool donorm;
    switch (blockIdx.z) {
        case 0:  Xin = g_Xq; Out = g_Qn; cw = cq_w; cb = cq_b; donorm = true;  break;
        case 1:  Xin = g_Xk; Out = g_Kn; cw = ck_w; cb = ck_b; donorm = true;  break;
        default: Xin = g_Xv; Out = g_Vv; cw = cv_w; cb = cv_b; donorm = false; break;
    }
    const int bt0 = blockIdx.x * 16;
    const int t0  = bt0 & (Tt - 1);
    const int lane = threadIdx.x & 31;
    const int wid  = threadIdx.x >> 5;
    const int h = blockIdx.y * 4 + wid;
    const int c0 = h * 64 + lane;        // and c0 + 32

    float x0[19], x1[19];
#pragma unroll
    for (int i = 0; i < 19; i++) {
        const int t = t0 - 3 + i;
        if (t < 0) { x0[i] = 0.f; x1[i] = 0.f; }
        else {
            const long g = (long)(bt0 - t0 + t) * INNER + c0;
            x0[i] = Xin[g];
            x1[i] = Xin[g + 32];
        }
    }
    float w0[4], w1[4];
#pragma unroll
    for (int k = 0; k < 4; k++) {
        w0[k] = cw[c0 * 4 + k];
        w1[k] = cw[(c0 + 32) * 4 + k];
    }
    const float b0 = cb[c0], b1 = cb[c0 + 32];

#pragma unroll
    for (int tt = 0; tt < 16; tt++) {
        float a0 = b0, a1 = b1;
#pragma unroll
        for (int k = 0; k < 4; k++) {
            a0 = fmaf(x0[tt + k], w0[k], a0);
            a1 = fmaf(x1[tt + k], w1[k], a1);
        }
        float s0 = a0 / (1.f + expf(-a0));
        float s1 = a1 / (1.f + expf(-a1));
        float ss = s0 * s0 + s1 * s1;
        ss += __shfl_xor_sync(0xffffffffu, ss, 16);
        ss += __shfl_xor_sync(0xffffffffu, ss, 8);
        ss += __shfl_xor_sync(0xffffffffu, ss, 4);
        ss += __shfl_xor_sync(0xffffffffu, ss, 2);
        ss += __shfl_xor_sync(0xffffffffu, ss, 1);
        if (donorm) {
            const float inv = 1.f / fmaxf(sqrtf(ss), 1e-12f);
            s0 *= inv; s1 *= inv;
        }
        const long g = (long)(bt0 + tt) * INNER + c0;
        Out[g] = s0;
        Out[g + 32] = s1;
    }
}

// ============== chunked delta-rule scan ======================================

__global__ __launch_bounds__(256, 2) void chunk_prep_kernel()
{
    extern __shared__ float sm[];
    float* sK = sm;                     // [64][CP]
    float* sV = sm + 64 * CP;           // V -> T
    float* sL = sm + 2 * 64 * CP;       // L -> W
    float* sGam = sm + 3 * 64 * CP;
    float* sR   = sGam + 64;

    const int chunk = blockIdx.x;
    const int c  = chunk & (NCHUNK - 1);
    const int bh = chunk >> 5;
    const int b = bh >> 4, h = bh & 15;
    const int tid = threadIdx.x;
    const long rowbase = (long)b * Tt + c * 64;
    const int colbase = h * dh;
    const long cb = (long)chunk * 4096;

    for (int idx = tid; idx < 1024; idx += 256) {
        const int row = idx >> 4;
        const int c4  = (idx & 15) << 2;
        const long g = (rowbase + row) * INNER + colbase + c4;
        float4 kv = *(const float4*)(g_Kn + g);
        float4 vv = *(const float4*)(g_Vv + g);
        sK[row * CP + c4 + 0] = kv.x; sK[row * CP + c4 + 1] = kv.y;
        sK[row * CP + c4 + 2] = kv.z; sK[row * CP + c4 + 3] = kv.w;
        sV[row * CP + c4 + 0] = vv.x; sV[row * CP + c4 + 1] = vv.y;
        sV[row * CP + c4 + 2] = vv.z; sV[row * CP + c4 + 3] = vv.w;
    }
    if (tid < 64) {
        sGam[tid] = g_AB[(rowbase + tid) * 32 + h];
        sR[tid]   = g_AB[(rowbase + tid) * 32 + 16 + h];
    }
    __syncthreads();
    if (tid == 0) {
        float p = 1.f;
        for (int i = 0; i < 64; i++) { p *= sGam[i]; sGam[i] = p; }
    }
    __syncthreads();
    if (tid < 64) sR[tid] = sR[tid] / sGam[tid];
    __syncthreads();

    const int ty = tid >> 4, tx = tid & 15;

    // L[j][i] = (i<j) ? gam[j]*r[i]*<k_i,k_j> : 0   (4x4 strided tiles)
    {
        float acc[4][4];
#pragma unroll
        for (int v = 0; v < 4; v++)
#pragma unroll
            for (int u = 0; u < 4; u++) acc[v][u] = 0.f;
        for (int k = 0; k < 64; k++) {
            float a[4], bb[4];
#pragma unroll
            for (int v = 0; v < 4; v++) a[v]  = sK[(ty + 16 * v) * CP + k];
#pragma unroll
            for (int u = 0; u < 4; u++) bb[u] = sK[(tx + 16 * u) * CP + k];
#pragma unroll
            for (int v = 0; v < 4; v++)
#pragma unroll
                for (int u = 0; u < 4; u++)
                    acc[v][u] = fmaf(a[v], bb[u], acc[v][u]);
        }
#pragma unroll
        for (int v = 0; v < 4; v++)
#pragma unroll
            for (int u = 0; u < 4; u++) {
                const int j = ty + 16 * v, i = tx + 16 * u;
                sL[j * CP + i] = (i < j) ? acc[v][u] * sGam[j] * sR[i] : 0.f;
            }
        __syncthreads();
    }

    // register-resident forward substitution (no barriers inside)
    float rr_[64];
    const int col = tid & 63;
    const int isW = (tid >> 6) & 1;
    if (tid < 128) {
#pragma unroll
        for (int j = 0; j < 64; j++)
            rr_[j] = isW ? sGam[j] * sK[j * CP + col] : sV[j * CP + col];
#pragma unroll
        for (int j = 0; j < 64; j++) {
            const float xj = rr_[j];
#pragma unroll
            for (int i = j + 1; i < 64; i++)
                rr_[i] -= sL[i * CP + j] * xj;
        }
    }
    __syncthreads();

    const float gC = sGam[63];
    if (tid < 128) {
        float* dst  = isW ? sL : sV;           // W -> sL, T -> sV
        float* gdst = isW ? g_W : g_T;
#pragma unroll
        for (int j = 0; j < 64; j++) {
            dst[j * CP + col] = rr_[j];
            gdst[cb + j * 64 + col] = rr_[j];
        }
    } else {
        const int t2 = tid - 128;
        for (int idx = t2; idx < 4096; idx += 128) {
            const int j = idx >> 6;
            sK[j * CP + (idx & 63)] *= gC * sR[j];
        }
    }
    if (tid < 64) {
        g_gam[chunk * 64 + tid] = sGam[tid];
        g_r  [chunk * 64 + tid] = sR[tid];
    }
    __syncthreads();

    // M[p][q] = gC*I[pq] - sum_j W[j][p]*Ks[j][q];  N[p][q] = sum_j T[j][p]*Ks[j][q]
    {
        float am[4][4], an[4][4];
#pragma unroll
        for (int v = 0; v < 4; v++)
#pragma unroll
            for (int u = 0; u < 4; u++) {
                am[v][u] = ((ty == tx) && (v == u)) ? gC : 0.f;
                an[v][u] = 0.f;
            }
        for (int j = 0; j < 64; j++) {
            float wv[4], tv[4], kb[4];
#pragma unroll
            for (int v = 0; v < 4; v++) {
                wv[v] = sL[j * CP + ty + 16 * v];
                tv[v] = sV[j * CP + ty + 16 * v];
            }
#pragma unroll
            for (int u = 0; u < 4; u++) kb[u] = sK[j * CP + tx + 16 * u];
#pragma unroll
            for (int v = 0; v < 4; v++)
#pragma unroll
                for (int u = 0; u < 4; u++) {
                    am[v][u] = fmaf(-wv[v], kb[u], am[v][u]);
                    an[v][u] = fmaf( tv[v], kb[u], an[v][u]);
                }
        }
#pragma unroll
        for (int v = 0; v < 4; v++)
#pragma unroll
            for (int u = 0; u < 4; u++) {
                const int p = ty + 16 * v, q = tx + 16 * u;
                g_M[cb + p * 64 + q] = am[v][u];
                g_N[cb + p * 64 + q] = an[v][u];
            }
    }
}

// grid (32 bh, 4 strips): rows R0..R0+15 of S evolve independently
__global__ __launch_bounds__(256) void chunk_scan_kernel()
{
    __shared__ float sS[16 * 64];
    __shared__ float sM[64 * 64];
    const int bh = blockIdx.x;
    const int R0 = blockIdx.y * 16;
    const int tid = threadIdx.x;
    const int row = tid >> 4;
    const int tx  = tid & 15;

    for (int idx = tid; idx < 1024; idx += 256) sS[idx] = 0.f;
    __syncthreads();

    for (int c = 0; c < NCHUNK; c++) {
        const long cb = (long)(bh * NCHUNK + c) * 4096;
        for (int idx = tid; idx < 1024; idx += 256)
            g_S0[cb + (long)(R0 + (idx >> 6)) * 64 + (idx & 63)] = sS[idx];
        for (int idx = tid; idx < 4096; idx += 256)
            sM[idx] = g_M[cb + idx];
        __syncthreads();

        float acc[4];
#pragma unroll
        for (int u = 0; u < 4; u++)
            acc[u] = g_N[cb + (long)(R0 + row) * 64 + tx + 16 * u];
        for (int k = 0; k < 64; k++) {
            const float s = sS[row * 64 + k];
#pragma unroll
            for (int u = 0; u < 4; u++)
                acc[u] = fmaf(s, sM[k * 64 + tx + 16 * u], acc[u]);
        }
        __syncthreads();
#pragma unroll
        for (int u = 0; u < 4; u++) sS[row * 64 + tx + 16 * u] = acc[u];
        __syncthreads();
    }
}

__global__ __launch_bounds__(256, 2) void chunk_out_kernel()
{
    extern __shared__ float sm[];
    float* sQ   = sm;
    float* sKW  = sm + 64 * CP;        // K, then W
    float* sS0T = sm + 2 * 64 * CP;    // S0 transposed: [k][a]
    float* sTU  = sm + 3 * 64 * CP;    // T -> U
    float* sA   = sm + 4 * 64 * CP;
    float* sGam = sm + 5 * 64 * CP;
    float* sR   = sGam + 64;

    const int chunk = blockIdx.x;
    const int c  = chunk & (NCHUNK - 1);
    const int bh = chunk >> 5;
    const int b = bh >> 4, h = bh & 15;
    const int tid = threadIdx.x;
    const long rowbase = (long)b * Tt + c * 64;
    const int colbase = h * dh;
    const long cb = (long)chunk * 4096;

    for (int idx = tid; idx < 1024; idx += 256) {
        const int row = idx >> 4;
        const int c4  = (idx & 15) << 2;
        const long g = (rowbase + row) * INNER + colbase + c4;
        float4 qv = *(const float4*)(g_Qn + g);
        float4 kv = *(const float4*)(g_Kn + g);
        sQ [row * CP + c4 + 0] = qv.x; sQ [row * CP + c4 + 1] = qv.y;
        sQ [row * CP + c4 + 2] = qv.z; sQ [row * CP + c4 + 3] = qv.w;
        sKW[row * CP + c4 + 0] = kv.x; sKW[row * CP + c4 + 1] = kv.y;
        sKW[row * CP + c4 + 2] = kv.z; sKW[row * CP + c4 + 3] = kv.w;
    }
    for (int idx = tid; idx < 4096; idx += 256) {
        sS0T[(idx & 63) * CP + (idx >> 6)] = g_S0[cb + idx];   // [k][a] = S0[a][k]
        sTU [(idx >> 6) * CP + (idx & 63)] = g_T[cb + idx];
    }
    if (tid < 64) {
        sGam[tid] = g_gam[chunk * 64 + tid];
        sR[tid]   = g_r[chunk * 64 + tid];
    }
    __syncthreads();

    const int ty = tid >> 4, tx = tid & 15;

    // Phase A: A[t][j] = (j<=t) ? gam[t]*r[j]*<q_t,k_j> : 0
    {
        float acc[4][4];
#pragma unroll
        for (int v = 0; v < 4; v++)
#pragma unroll
            for (int u = 0; u < 4; u++) acc[v][u] = 0.f;
        for (int k = 0; k < 64; k++) {
            float qa[4], kb[4];
#pragma unroll
            for (int v = 0; v < 4; v++) qa[v] = sQ [(ty + 16 * v) * CP + k];
#pragma unroll
            for (int u = 0; u < 4; u++) kb[u] = sKW[(tx + 16 * u) * CP + k];
#pragma unroll
            for (int v = 0; v < 4; v++)
#pragma unroll
                for (int u = 0; u < 4; u++)
                    acc[v][u] = fmaf(qa[v], kb[u], acc[v][u]);
        }
#pragma unroll
        for (int v = 0; v < 4; v++)
#pragma unroll
            for (int u = 0; u < 4; u++) {
                const int t = ty + 16 * v, j = tx + 16 * u;
                sA[t * CP + j] = (j <= t) ? acc[v][u] * sGam[t] * sR[j] : 0.f;
            }
    }
    __syncthreads();

    // load W over K
    for (int idx = tid; idx < 4096; idx += 256)
        sKW[(idx >> 6) * CP + (idx & 63)] = g_W[cb + idx];
    __syncthreads();

    // Phase U: U[j][a] = T[j][a] - sum_k W[j][k]*S0T[k][a]   (in place in sTU)
    {
        float au[4][4];
#pragma unroll
        for (int v = 0; v < 4; v++)
#pragma unroll
            for (int u = 0; u < 4; u++)
                au[v][u] = sTU[(ty + 16 * v) * CP + tx + 16 * u];
        for (int k = 0; k < 64; k++) {
            float wv[4], sb[4];
#pragma unroll
            for (int v = 0; v < 4; v++) wv[v] = sKW[(ty + 16 * v) * CP + k];
#pragma unroll
            for (int u = 0; u < 4; u++) sb[u] = sS0T[k * CP + tx + 16 * u];
#pragma unroll
            for (int v = 0; v < 4; v++)
#pragma unroll
                for (int u = 0; u < 4; u++)
                    au[v][u] = fmaf(-wv[v], sb[u], au[v][u]);
        }
        __syncthreads();
#pragma unroll
        for (int v = 0; v < 4; v++)
#pragma unroll
            for (int u = 0; u < 4; u++)
                sTU[(ty + 16 * v) * CP + tx + 16 * u] = au[v][u];
    }
    __syncthreads();

    // Phase O: O[t][a] = gam[t]*sum_k Q[t][k]*S0T[k][a] + sum_j A[t][j]*U[j][a]
    {
        float o1[4][4], o2[4][4];
#pragma unroll
        for (int v = 0; v < 4; v++)
#pragma unroll
            for (int u = 0; u < 4; u++) { o1[v][u] = 0.f; o2[v][u] = 0.f; }
        for (int k = 0; k < 64; k++) {
            float qa[4], sb[4], aa[4], ub[4];
#pragma unroll
            for (int v = 0; v < 4; v++) {
                qa[v] = sQ[(ty + 16 * v) * CP + k];
                aa[v] = sA[(ty + 16 * v) * CP + k];
            }
#pragma unroll
            for (int u = 0; u < 4; u++) {
                sb[u] = sS0T[k * CP + tx + 16 * u];
                ub[u] = sTU [k * CP + tx + 16 * u];
            }
#pragma unroll
            for (int v = 0; v < 4; v++)
#pragma unroll
                for (int u = 0; u < 4; u++) {
                    o1[v][u] = fmaf(qa[v], sb[u], o1[v][u]);
                    o2[v][u] = fmaf(aa[v], ub[u], o2[v][u]);
                }
        }
#pragma unroll
        for (int v = 0; v < 4; v++)
#pragma unroll
            for (int u = 0; u < 4; u++) {
                const int t = ty + 16 * v, a = tx + 16 * u;
                g_O[(rowbase + t) * INNER + colbase + a] =
                    sGam[t] * o1[v][u] + o2[v][u];
            }
    }
}

// ---------------- RMS norm + (1+gamma) + gate --------------------------------
__global__ __launch_bounds__(256) void rmsgate_kernel(const float* __restrict__ gamma)
{
    const int m = blockIdx.x;
    const int tid = threadIdx.x;
    const long base = (long)m * INNER;
    float xv[4];
    float ss = 0.f;
#pragma unroll
    for (int i = 0; i < 4; i++) {
        xv[i] = g_O[base + tid + i * 256];
        ss += xv[i] * xv[i];
    }
    for (int off = 16; off; off >>= 1) ss += __shfl_xor_sync(0xffffffffu, ss, off);
    __shared__ float red[8];
    if ((tid & 31) == 0) red[tid >> 5] = ss;
    __syncthreads();
    float tot = 0.f;
#pragma unroll
    for (int w = 0; w < 8; w++) tot += red[w];
    const float inv = 1.f / sqrtf(tot * (1.f / (float)INNER) + 1e-6f);
#pragma unroll
    for (int i = 0; i < 4; i++) {
        int c = tid + i * 256;
        g_Y[base + c] = rna_tf32(xv[i] * inv * (1.f + gamma[c]) * g_Xg[base + c]);
    }
}

// ---------------- launch -----------------------------------------------------
extern "C" void kernel_launch(void* const* d_in, const int* in_sizes, int n_in,
                              void* d_out, int out_size)
{
    const float* x    = (const float*)d_in[0];
    const float* Wq   = (const float*)d_in[1];
    const float* Wk   = (const float*)d_in[2];
    const float* Wv   = (const float*)d_in[3];
    const float* Wa   = (const float*)d_in[4];
    const float* ba   = (const float*)d_in[5];
    const float* Wb   = (const float*)d_in[6];
    const float* bb   = (const float*)d_in[7];
    const float* Wg   = (const float*)d_in[8];
    const float* Wo   = (const float*)d_in[9];
    const float* cq_w = (const float*)d_in[10];
    const float* cq_b = (const float*)d_in[11];
    const float* ck_w = (const float*)d_in[12];
    const float* ck_b = (const float*)d_in[13];
    const float* cv_w = (const float*)d_in[14];
    const float* cv_b = (const float*)d_in[15];
    const float* gamma= (const float*)d_in[16];
    float* out = (float*)d_out;

    const int prep_smem = (3 * 64 * CP + 128) * sizeof(float);   // ~50.4 KB
    const int out_smem  = (5 * 64 * CP + 128) * sizeof(float);   // ~83.7 KB
    cudaFuncSetAttribute(chunk_prep_kernel,
                         cudaFuncAttributeMaxDynamicSharedMemorySize, prep_smem);
    cudaFuncSetAttribute(chunk_out_kernel,
                         cudaFuncAttributeMaxDynamicSharedMemorySize, out_smem);

    cvtx_kernel<<<Mrows * Dd / 1024, 256>>>(x);
    wround_kernel<<<dim3(Dd * INNER / 1024, 5), 256>>>(Wq, Wk, Wv, Wg, Wo);
    proj_gemm_kernel<<<dim3(INNER / 128, Mrows / 128, 4), 128>>>();
    conv_kernel<<<dim3(Mrows / 16, 4, 3), 128>>>(cq_w, cq_b, ck_w, ck_b,
                                                 cv_w, cv_b);
    ab_kernel<<<Mrows, 256>>>(x, Wa, ba, Wb, bb);
    chunk_prep_kernel<<<1024, 256, prep_smem>>>();
    chunk_scan_kernel<<<dim3(Bz * Hh, 4), 256>>>();
    chunk_out_kernel<<<1024, 256, out_smem>>>();
    rmsgate_kernel<<<Mrows, 256>>>(gamma);
    out_gemm_kernel<<<dim3(Dd / 128, Mrows / 128), 128>>>(out);
}

// round 7
// speedup vs baseline: 3.7168x; 1.0107x over previous
#include <cuda_runtime.h>
#include <math.h>
#include <stdint.h>

// Problem constants
#define Bz 2
#define Tt 2048
#define Dd 1024
#define Hh 16
#define dh 64
#define INNER 1024
#define Mrows 4096   // B*T
#define NCHUNK 32
#define CP 65        // padded stride for 64x64 smem tiles

// ---------------- scratch ----------------------------------------------------
__device__ float g_Xq[Mrows * INNER];
__device__ float g_Xk[Mrows * INNER];
__device__ float g_Xv[Mrows * INNER];
__device__ float g_Xg[Mrows * INNER];
__device__ float g_Qn[Mrows * INNER];
__device__ float g_Kn[Mrows * INNER];
__device__ float g_Vv[Mrows * INNER];
__device__ float g_AB[Mrows * 32];
__device__ float g_O [Mrows * INNER];
__device__ float g_Y [Mrows * INNER];
__device__ float g_xa[Mrows * Dd];
__device__ float g_Wr[5 * Dd * INNER];
__device__ float g_T [1024 * 4096];
__device__ float g_W [1024 * 4096];
__device__ float g_M [1024 * 4096];
__device__ float g_N [1024 * 4096];
__device__ float g_S0[1024 * 4096];
__device__ float g_gam[1024 * 64];
__device__ float g_r  [1024 * 64];

// ---------------- helpers ----------------------------------------------------
__device__ __forceinline__ unsigned cvt_tf32(float f) {
    unsigned u;
    asm("cvt.rna.tf32.f32 %0, %1;" : "=r"(u) : "f"(f));
    return u;
}
__device__ __forceinline__ float rna_tf32(float f) {
    return __uint_as_float(cvt_tf32(f));
}
__device__ __forceinline__ uint32_t smem_u32(const void* p) {
    uint32_t a;
    asm("{ .reg .u64 t; cvta.to.shared.u64 t, %1; cvt.u32.u64 %0, t; }"
        : "=r"(a) : "l"(p));
    return a;
}
__device__ __forceinline__ void cp16(uint32_t saddr, const void* gptr) {
    asm volatile("cp.async.cg.shared.global [%0], [%1], 16;" :: "r"(saddr), "l"(gptr));
}
#define CP_COMMIT() asm volatile("cp.async.commit_group;" ::: "memory")

__device__ __forceinline__ void mma_tf32(float* d, unsigned a0, unsigned a1,
                                         unsigned a2, unsigned a3,
                                         unsigned b0, unsigned b1) {
    asm("mma.sync.aligned.m16n8k8.row.col.f32.tf32.tf32.f32 "
        "{%0,%1,%2,%3}, {%4,%5,%6,%7}, {%8,%9}, {%0,%1,%2,%3};\n"
        : "+f"(d[0]), "+f"(d[1]), "+f"(d[2]), "+f"(d[3])
        : "r"(a0), "r"(a1), "r"(a2), "r"(a3), "r"(b0), "r"(b1));
}

// ---------------- tf32 GEMM, 128x128 tile, cp.async 3-stage pipeline ---------
// A (M,1024) row-major pre-rounded, B (1024,N) row-major pre-rounded.
#define APAD 20
#define BPAD 136
#define AST  (128 * APAD)          // floats per A stage (2560)
#define BST  (16 * BPAD)           // floats per B stage (2176)
#define GSMEM ((3 * (AST + BST)) * 4)   // 56832 bytes

__device__ __forceinline__ void tgemm128(const float* __restrict__ A,
                                         const float* __restrict__ Bm,
                                         float* __restrict__ C,
                                         int N, int bm, int bn,
                                         bool do_silu)
{
    extern __shared__ float smp[];
    float* As = smp;                 // [3][AST]
    float* Bs = smp + 3 * AST;       // [3][BST]

    const int tid  = threadIdx.x;
    const int lane = tid & 31;
    const int wid  = tid >> 5;
    const int warpM = (wid & 1) * 64;
    const int warpN = (wid >> 1) * 64;

    float acc[4][8][4];
#pragma unroll
    for (int mt = 0; mt < 4; mt++)
#pragma unroll
        for (int nt = 0; nt < 8; nt++)
#pragma unroll
            for (int i = 0; i < 4; i++) acc[mt][nt][i] = 0.f;

    const uint32_t asu = smem_u32(As);
    const uint32_t bsu = smem_u32(Bs);

    auto load_stage = [&](int kt, int st) {
        const int k0 = kt << 4;
        const uint32_t sa = asu + st * (AST * 4);
        const uint32_t sb = bsu + st * (BST * 4);
#pragma unroll
        for (int i = 0; i < 4; i++) {
            const int idx = tid + i * 128;
            const int row = idx >> 2, kq = (idx & 3) << 2;
            cp16(sa + (row * APAD + kq) * 4,
                 A + (long)(bm + row) * 1024 + k0 + kq);
            const int kk = idx >> 5, nq = (idx & 31) << 2;
            cp16(sb + (kk * BPAD + nq) * 4,
                 Bm + (long)(k0 + kk) * N + bn + nq);
        }
        CP_COMMIT();
    };

    load_stage(0, 0);
    load_stage(1, 1);
    load_stage(2, 2);

    for (int kt = 0; kt < 64; kt++) {
        const int st = kt - (kt / 3) * 3;    // kt % 3
        if (kt <= 61)      asm volatile("cp.async.wait_group 2;" ::: "memory");
        else if (kt == 62) asm volatile("cp.async.wait_group 1;" ::: "memory");
        else               asm volatile("cp.async.wait_group 0;" ::: "memory");
        __syncthreads();

        const float* as = As + st * AST;
        const float* bs = Bs + st * BST;
#pragma unroll
        for (int k8 = 0; k8 < 16; k8 += 8) {
            const int kk0 = k8 + (lane & 3);
            const int kk1 = kk0 + 4;
            unsigned af[4][4], bf[8][2];
#pragma unroll
            for (int mt = 0; mt < 4; mt++) {
                const int r0 = warpM + mt * 16 + (lane >> 2);
                af[mt][0] = __float_as_uint(as[r0 * APAD + kk0]);
                af[mt][1] = __float_as_uint(as[(r0 + 8) * APAD + kk0]);
                af[mt][2] = __float_as_uint(as[r0 * APAD + kk1]);
                af[mt][3] = __float_as_uint(as[(r0 + 8) * APAD + kk1]);
            }
#pragma unroll
            for (int nt = 0; nt < 8; nt++) {
                const int n = warpN + nt * 8 + (lane >> 2);
                bf[nt][0] = __float_as_uint(bs[kk0 * BPAD + n]);
                bf[nt][1] = __float_as_uint(bs[kk1 * BPAD + n]);
            }
#pragma unroll
            for (int mt = 0; mt < 4; mt++)
#pragma unroll
                for (int nt = 0; nt < 8; nt++)
                    mma_tf32(acc[mt][nt], af[mt][0], af[mt][1], af[mt][2], af[mt][3],
                             bf[nt][0], bf[nt][1]);
        }
        __syncthreads();
        if (kt + 3 < 64) load_stage(kt + 3, st);
    }

#pragma unroll
    for (int mt = 0; mt < 4; mt++) {
        const int r0 = bm + warpM + mt * 16 + (lane >> 2);
#pragma unroll
        for (int nt = 0; nt < 8; nt++) {
            const int c = bn + warpN + nt * 8 + ((lane & 3) << 1);
            float v0 = acc[mt][nt][0], v1 = acc[mt][nt][1];
            float v2 = acc[mt][nt][2], v3 = acc[mt][nt][3];
            if (do_silu) {
                v0 = v0 / (1.f + expf(-v0));
                v1 = v1 / (1.f + expf(-v1));
                v2 = v2 / (1.f + expf(-v2));
                v3 = v3 / (1.f + expf(-v3));
            }
            *(float2*)(C + (long)r0 * N + c)       = make_float2(v0, v1);
            *(float2*)(C + (long)(r0 + 8) * N + c) = make_float2(v2, v3);
        }
    }
}

__global__ __launch_bounds__(128) void proj_gemm_kernel()
{
    const int z = blockIdx.z;
    const float* W = g_Wr + (long)z * (Dd * INNER);
    float* O;
    bool silu = false;
    switch (z) {
        case 0:  O = g_Xq; break;
        case 1:  O = g_Xk; break;
        case 2:  O = g_Xv; break;
        default: O = g_Xg; silu = true; break;
    }
    tgemm128(g_xa, W, O, INNER, blockIdx.y * 128, blockIdx.x * 128, silu);
}

__global__ __launch_bounds__(128) void out_gemm_kernel(float* __restrict__ out)
{
    tgemm128(g_Y, g_Wr + 4L * Dd * INNER, out, Dd,
             blockIdx.y * 128, blockIdx.x * 128, false);
}

// ---------------- merged tf32-rounding pre-pass ------------------------------
// flat: [0, 4M) = x -> g_xa; [4M, 9M) = Wq..Wo -> g_Wr
__global__ __launch_bounds__(256) void cvt_kernel(
    const float* __restrict__ x,
    const float* __restrict__ Wq, const float* __restrict__ Wk,
    const float* __restrict__ Wv, const float* __restrict__ Wg,
    const float* __restrict__ Wo)
{
    const long i = ((long)blockIdx.x * 256 + threadIdx.x) * 4;
    const float* src;
    float* dst;
    if (i < (long)Mrows * Dd) {
        src = x + i;
        dst = g_xa + i;
    } else {
        const long j = i - (long)Mrows * Dd;
        const int w = (int)(j >> 20);
        const float* Ws[5] = {Wq, Wk, Wv, Wg, Wo};
        src = Ws[w] + (j & 1048575);
        dst = g_Wr + j;
    }
    float4 v = *(const float4*)src;
    v.x = rna_tf32(v.x); v.y = rna_tf32(v.y);
    v.z = rna_tf32(v.z); v.w = rna_tf32(v.w);
    *(float4*)dst = v;
}

// ---------------- alpha/beta -------------------------------------------------
__global__ __launch_bounds__(256) void ab_kernel(
    const float* __restrict__ x,
    const float* __restrict__ Wa, const float* __restrict__ ba,
    const float* __restrict__ Wb, const float* __restrict__ bb)
{
    __shared__ float xs[Dd];
    const int m = blockIdx.x;
    const int tid = threadIdx.x;
    for (int i = tid; i < Dd; i += 256) xs[i] = x[(long)m * Dd + i];
    __syncthreads();
    const int out = tid >> 3;
    const int l8  = tid & 7;
    const float* W = (out < 16) ? Wa : Wb;
    const int h = out & 15;
    float s = 0.f;
    for (int kx = l8; kx < Dd; kx += 8) s = fmaf(xs[kx], W[kx * Hh + h], s);
    s += __shfl_xor_sync(0xffffffffu, s, 1);
    s += __shfl_xor_sync(0xffffffffu, s, 2);
    s += __shfl_xor_sync(0xffffffffu, s, 4);
    if (l8 == 0) {
        float bias = (out < 16) ? ba[h] : bb[h];
        g_AB[(long)m * 32 + out] = 1.f / (1.f + expf(-(s + bias)));
    }
}

// ---------------- conv: 16 timesteps per thread, warp-per-head ---------------
__global__ __launch_bounds__(128) void conv_kernel(
    const float* __restrict__ cq_w, const float* __restrict__ cq_b,
    const float* __restrict__ ck_w, const float* __restrict__ ck_b,
    const float* __restrict__ cv_w, const float* __restrict__ cv_b)
{
    const float* Xin; float* Out; const float* cw; const float* cb; bool donorm;
    switch (blockIdx.z) {
        case 0:  Xin = g_Xq; Out = g_Qn; cw = cq_w; cb = cq_b; donorm = true;  break;
        case 1:  Xin = g_Xk; Out = g_Kn; cw = ck_w; cb = ck_b; donorm = true;  break;
        default: Xin = g_Xv; Out = g_Vv; cw = cv_w; cb = cv_b; donorm = false; break;
    }
    const int bt0 = blockIdx.x * 16;
    const int t0  = bt0 & (Tt - 1);
    const int lane = threadIdx.x & 31;
    const int wid  = threadIdx.x >> 5;
    const int h = blockIdx.y * 4 + wid;
    const int c0 = h * 64 + lane;

    float x0[19], x1[19];
#pragma unroll
    for (int i = 0; i < 19; i++) {
        const int t = t0 - 3 + i;
        if (t < 0) { x0[i] = 0.f; x1[i] = 0.f; }
        else {
            const long g = (long)(bt0 - t0 + t) * INNER + c0;
            x0[i] = Xin[g];
            x1[i] = Xin[g + 32];
        }
    }
    float w0[4], w1[4];
#pragma unroll
    for (int k = 0; k < 4; k++) {
        w0[k] = cw[c0 * 4 + k];
        w1[k] = cw[(c0 + 32) * 4 + k];
    }
    const float b0 = cb[c0], b1 = cb[c0 + 32];

#pragma unroll
    for (int tt = 0; tt < 16; tt++) {
        float a0 = b0, a1 = b1;
#pragma unroll
        for (int k = 0; k < 4; k++) {
            a0 = fmaf(x0[tt + k], w0[k], a0);
            a1 = fmaf(x1[tt + k], w1[k], a1);
        }
        float s0 = a0 / (1.f + expf(-a0));
        float s1 = a1 / (1.f + expf(-a1));
        float ss = s0 * s0 + s1 * s1;
        ss += __shfl_xor_sync(0xffffffffu, ss, 16);
        ss += __shfl_xor_sync(0xffffffffu, ss, 8);
        ss += __shfl_xor_sync(0xffffffffu, ss, 4);
        ss += __shfl_xor_sync(0xffffffffu, ss, 2);
        ss += __shfl_xor_sync(0xffffffffu, ss, 1);
        if (donorm) {
            const float inv = 1.f / fmaxf(sqrtf(ss), 1e-12f);
            s0 *= inv; s1 *= inv;
        }
        const long g = (long)(bt0 + tt) * INNER + c0;
        Out[g] = s0;
        Out[g + 32] = s1;
    }
}

// ============== chunked delta-rule scan ======================================

__global__ __launch_bounds__(256, 2) void chunk_prep_kernel()
{
    extern __shared__ float sm[];
    float* sK = sm;
    float* sV = sm + 64 * CP;
    float* sL = sm + 2 * 64 * CP;
    float* sGam = sm + 3 * 64 * CP;
    float* sR   = sGam + 64;

    const int chunk = blockIdx.x;
    const int c  = chunk & (NCHUNK - 1);
    const int bh = chunk >> 5;
    const int b = bh >> 4, h = bh & 15;
    const int tid = threadIdx.x;
    const long rowbase = (long)b * Tt + c * 64;
    const int colbase = h * dh;
    const long cb = (long)chunk * 4096;

    for (int idx = tid; idx < 1024; idx += 256) {
        const int row = idx >> 4;
        const int c4  = (idx & 15) << 2;
        const long g = (rowbase + row) * INNER + colbase + c4;
        float4 kv = *(const float4*)(g_Kn + g);
        float4 vv = *(const float4*)(g_Vv + g);
        sK[row * CP + c4 + 0] = kv.x; sK[row * CP + c4 + 1] = kv.y;
        sK[row * CP + c4 + 2] = kv.z; sK[row * CP + c4 + 3] = kv.w;
        sV[row * CP + c4 + 0] = vv.x; sV[row * CP + c4 + 1] = vv.y;
        sV[row * CP + c4 + 2] = vv.z; sV[row * CP + c4 + 3] = vv.w;
    }
    if (tid < 64) {
        sGam[tid] = g_AB[(rowbase + tid) * 32 + h];
        sR[tid]   = g_AB[(rowbase + tid) * 32 + 16 + h];
    }
    __syncthreads();
    if (tid == 0) {
        float p = 1.f;
        for (int i = 0; i < 64; i++) { p *= sGam[i]; sGam[i] = p; }
    }
    __syncthreads();
    if (tid < 64) sR[tid] = sR[tid] / sGam[tid];
    __syncthreads();

    const int ty = tid >> 4, tx = tid & 15;

    {
        float acc[4][4];
#pragma unroll
        for (int v = 0; v < 4; v++)
#pragma unroll
            for (int u = 0; u < 4; u++) acc[v][u] = 0.f;
        for (int k = 0; k < 64; k++) {
            float a[4], bb[4];
#pragma unroll
            for (int v = 0; v < 4; v++) a[v]  = sK[(ty + 16 * v) * CP + k];
#pragma unroll
            for (int u = 0; u < 4; u++) bb[u] = sK[(tx + 16 * u) * CP + k];
#pragma unroll
            for (int v = 0; v < 4; v++)
#pragma unroll
                for (int u = 0; u < 4; u++)
                    acc[v][u] = fmaf(a[v], bb[u], acc[v][u]);
        }
#pragma unroll
        for (int v = 0; v < 4; v++)
#pragma unroll
            for (int u = 0; u < 4; u++) {
                const int j = ty + 16 * v, i = tx + 16 * u;
                sL[j * CP + i] = (i < j) ? acc[v][u] * sGam[j] * sR[i] : 0.f;
            }
        __syncthreads();
    }

    float rr_[64];
    const int col = tid & 63;
    const int isW = (tid >> 6) & 1;
    if (tid < 128) {
#pragma unroll
        for (int j = 0; j < 64; j++)
            rr_[j] = isW ? sGam[j] * sK[j * CP + col] : sV[j * CP + col];
#pragma unroll
        for (int j = 0; j < 64; j++) {
            const float xj = rr_[j];
#pragma unroll
            for (int i = j + 1; i < 64; i++)
                rr_[i] -= sL[i * CP + j] * xj;
        }
    }
    __syncthreads();

    const float gC = sGam[63];
    if (tid < 128) {
        float* dst  = isW ? sL : sV;
        float* gdst = isW ? g_W : g_T;
#pragma unroll
        for (int j = 0; j < 64; j++) {
            dst[j * CP + col] = rr_[j];
            gdst[cb + j * 64 + col] = rr_[j];
        }
    } else {
        const int t2 = tid - 128;
        for (int idx = t2; idx < 4096; idx += 128) {
            const int j = idx >> 6;
            sK[j * CP + (idx & 63)] *= gC * sR[j];
        }
    }
    if (tid < 64) {
        g_gam[chunk * 64 + tid] = sGam[tid];
        g_r  [chunk * 64 + tid] = sR[tid];
    }
    __syncthreads();

    {
        float am[4][4], an[4][4];
#pragma unroll
        for (int v = 0; v < 4; v++)
#pragma unroll
            for (int u = 0; u < 4; u++) {
                am[v][u] = ((ty == tx) && (v == u)) ? gC : 0.f;
                an[v][u] = 0.f;
            }
        for (int j = 0; j < 64; j++) {
            float wv[4], tv[4], kb[4];
#pragma unroll
            for (int v = 0; v < 4; v++) {
                wv[v] = sL[j * CP + ty + 16 * v];
                tv[v] = sV[j * CP + ty + 16 * v];
            }
#pragma unroll
            for (int u = 0; u < 4; u++) kb[u] = sK[j * CP + tx + 16 * u];
#pragma unroll
            for (int v = 0; v < 4; v++)
#pragma unroll
                for (int u = 0; u < 4; u++) {
                    am[v][u] = fmaf(-wv[v], kb[u], am[v][u]);
                    an[v][u] = fmaf( tv[v], kb[u], an[v][u]);
                }
        }
#pragma unroll
        for (int v = 0; v < 4; v++)
#pragma unroll
            for (int u = 0; u < 4; u++) {
                const int p = ty + 16 * v, q = tx + 16 * u;
                g_M[cb + p * 64 + q] = am[v][u];
                g_N[cb + p * 64 + q] = an[v][u];
            }
    }
}

__global__ __launch_bounds__(256) void chunk_scan_kernel()
{
    __shared__ float sS[16 * 64];
    __shared__ float sM[64 * 64];
    const int bh = blockIdx.x;
    const int R0 = blockIdx.y * 16;
    const int tid = threadIdx.x;
    const int row = tid >> 4;
    const int tx  = tid & 15;

    for (int idx = tid; idx < 1024; idx += 256) sS[idx] = 0.f;
    __syncthreads();

    for (int c = 0; c < NCHUNK; c++) {
        const long cb = (long)(bh * NCHUNK + c) * 4096;
        for (int idx = tid; idx < 1024; idx += 256)
            g_S0[cb + (long)(R0 + (idx >> 6)) * 64 + (idx & 63)] = sS[idx];
        for (int idx = tid; idx < 4096; idx += 256)
            sM[idx] = g_M[cb + idx];
        __syncthreads();

        float acc[4];
#pragma unroll
        for (int u = 0; u < 4; u++)
            acc[u] = g_N[cb + (long)(R0 + row) * 64 + tx + 16 * u];
        for (int k = 0; k < 64; k++) {
            const float s = sS[row * 64 + k];
#pragma unroll
            for (int u = 0; u < 4; u++)
                acc[u] = fmaf(s, sM[k * 64 + tx + 16 * u], acc[u]);
        }
        __syncthreads();
#pragma unroll
        for (int u = 0; u < 4; u++) sS[row * 64 + tx + 16 * u] = acc[u];
        __syncthreads();
    }
}

__global__ __launch_bounds__(256, 2) void chunk_out_kernel()
{
    extern __shared__ float sm[];
    float* sQ   = sm;
    float* sKW  = sm + 64 * CP;
    float* sS0T = sm + 2 * 64 * CP;
    float* sTU  = sm + 3 * 64 * CP;
    float* sA   = sm + 4 * 64 * CP;
    float* sGam = sm + 5 * 64 * CP;
    float* sR   = sGam + 64;

    const int chunk = blockIdx.x;
    const int c  = chunk & (NCHUNK - 1);
    const int bh = chunk >> 5;
    const int b = bh >> 4, h = bh & 15;
    const int tid = threadIdx.x;
    const long rowbase = (long)b * Tt + c * 64;
    const int colbase = h * dh;
    const long cb = (long)chunk * 4096;

    for (int idx = tid; idx < 1024; idx += 256) {
        const int row = idx >> 4;
        const int c4  = (idx & 15) << 2;
        const long g = (rowbase + row) * INNER + colbase + c4;
        float4 qv = *(const float4*)(g_Qn + g);
        float4 kv = *(const float4*)(g_Kn + g);
        sQ [row * CP + c4 + 0] = qv.x; sQ [row * CP + c4 + 1] = qv.y;
        sQ [row * CP + c4 + 2] = qv.z; sQ [row * CP + c4 + 3] = qv.w;
        sKW[row * CP + c4 + 0] = kv.x; sKW[row * CP + c4 + 1] = kv.y;
        sKW[row * CP + c4 + 2] = kv.z; sKW[row * CP + c4 + 3] = kv.w;
    }
    for (int idx = tid; idx < 4096; idx += 256) {
        sS0T[(idx & 63) * CP + (idx >> 6)] = g_S0[cb + idx];
        sTU [(idx >> 6) * CP + (idx & 63)] = g_T[cb + idx];
    }
    if (tid < 64) {
        sGam[tid] = g_gam[chunk * 64 + tid];
        sR[tid]   = g_r[chunk * 64 + tid];
    }
    __syncthreads();

    const int ty = tid >> 4, tx = tid & 15;

    {
        float acc[4][4];
#pragma unroll
        for (int v = 0; v < 4; v++)
#pragma unroll
            for (int u = 0; u < 4; u++) acc[v][u] = 0.f;
        for (int k = 0; k < 64; k++) {
            float qa[4], kb[4];
#pragma unroll
            for (int v = 0; v < 4; v++) qa[v] = sQ [(ty + 16 * v) * CP + k];
#pragma unroll
            for (int u = 0; u < 4; u++) kb[u] = sKW[(tx + 16 * u) * CP + k];
#pragma unroll
            for (int v = 0; v < 4; v++)
#pragma unroll
                for (int u = 0; u < 4; u++)
                    acc[v][u] = fmaf(qa[v], kb[u], acc[v][u]);
        }
#pragma unroll
        for (int v = 0; v < 4; v++)
#pragma unroll
            for (int u = 0; u < 4; u++) {
                const int t = ty + 16 * v, j = tx + 16 * u;
                sA[t * CP + j] = (j <= t) ? acc[v][u] * sGam[t] * sR[j] : 0.f;
            }
    }
    __syncthreads();

    for (int idx = tid; idx < 4096; idx += 256)
        sKW[(idx >> 6) * CP + (idx & 63)] = g_W[cb + idx];
    __syncthreads();

    {
        float au[4][4];
#pragma unroll
        for (int v = 0; v < 4; v++)
#pragma unroll
            for (int u = 0; u < 4; u++)
                au[v][u] = sTU[(ty + 16 * v) * CP + tx + 16 * u];
        for (int k = 0; k < 64; k++) {
            float wv[4], sb[4];
#pragma unroll
            for (int v = 0; v < 4; v++) wv[v] = sKW[(ty + 16 * v) * CP + k];
#pragma unroll
            for (int u = 0; u < 4; u++) sb[u] = sS0T[k * CP + tx + 16 * u];
#pragma unroll
            for (int v = 0; v < 4; v++)
#pragma unroll
                for (int u = 0; u < 4; u++)
                    au[v][u] = fmaf(-wv[v], sb[u], au[v][u]);
        }
        __syncthreads();
#pragma unroll
        for (int v = 0; v < 4; v++)
#pragma unroll
            for (int u = 0; u < 4; u++)
                sTU[(ty + 16 * v) * CP + tx + 16 * u] = au[v][u];
    }
    __syncthreads();

    {
        float o1[4][4], o2[4][4];
#pragma unroll
        for (int v = 0; v < 4; v++)
#pragma unroll
            for (int u = 0; u < 4; u++) { o1[v][u] = 0.f; o2[v][u] = 0.f; }
        for (int k = 0; k < 64; k++) {
            float qa[4], sb[4], aa[4], ub[4];
#pragma unroll
            for (int v = 0; v < 4; v++) {
                qa[v] = sQ[(ty + 16 * v) * CP + k];
                aa[v] = sA[(ty + 16 * v) * CP + k];
            }
#pragma unroll
            for (int u = 0; u < 4; u++) {
                sb[u] = sS0T[k * CP + tx + 16 * u];
                ub[u] = sTU [k * CP + tx + 16 * u];
            }
#pragma unroll
            for (int v = 0; v < 4; v++)
#pragma unroll
                for (int u = 0; u < 4; u++) {
                    o1[v][u] = fmaf(qa[v], sb[u], o1[v][u]);
                    o2[v][u] = fmaf(aa[v], ub[u], o2[v][u]);
                }
        }
#pragma unroll
        for (int v = 0; v < 4; v++)
#pragma unroll
            for (int u = 0; u < 4; u++) {
                const int t = ty + 16 * v, a = tx + 16 * u;
                g_O[(rowbase + t) * INNER + colbase + a] =
                    sGam[t] * o1[v][u] + o2[v][u];
            }
    }
}

// ---------------- RMS norm + (1+gamma) + gate (float4) -----------------------
__global__ __launch_bounds__(256) void rmsgate_kernel(const float* __restrict__ gamma)
{
    const int m = blockIdx.x;
    const int tid = threadIdx.x;
    const long base = (long)m * INNER + tid * 4;
    float4 xv = *(const float4*)(g_O + base);
    float ss = xv.x * xv.x + xv.y * xv.y + xv.z * xv.z + xv.w * xv.w;
    for (int off = 16; off; off >>= 1) ss += __shfl_xor_sync(0xffffffffu, ss, off);
    __shared__ float red[8];
    if ((tid & 31) == 0) red[tid >> 5] = ss;
    __syncthreads();
    float tot = 0.f;
#pragma unroll
    for (int w = 0; w < 8; w++) tot += red[w];
    const float inv = 1.f / sqrtf(tot * (1.f / (float)INNER) + 1e-6f);
    float4 gv = *(const float4*)(g_Xg + base);
    float4 gm = *(const float4*)(gamma + tid * 4);
    float4 o;
    o.x = rna_tf32(xv.x * inv * (1.f + gm.x) * gv.x);
    o.y = rna_tf32(xv.y * inv * (1.f + gm.y) * gv.y);
    o.z = rna_tf32(xv.z * inv * (1.f + gm.z) * gv.z);
    o.w = rna_tf32(xv.w * inv * (1.f + gm.w) * gv.w);
    *(float4*)(g_Y + base) = o;
}

// ---------------- launch -----------------------------------------------------
extern "C" void kernel_launch(void* const* d_in, const int* in_sizes, int n_in,
                              void* d_out, int out_size)
{
    const float* x    = (const float*)d_in[0];
    const float* Wq   = (const float*)d_in[1];
    const float* Wk   = (const float*)d_in[2];
    const float* Wv   = (const float*)d_in[3];
    const float* Wa   = (const float*)d_in[4];
    const float* ba   = (const float*)d_in[5];
    const float* Wb   = (const float*)d_in[6];
    const float* bb   = (const float*)d_in[7];
    const float* Wg   = (const float*)d_in[8];
    const float* Wo   = (const float*)d_in[9];
    const float* cq_w = (const float*)d_in[10];
    const float* cq_b = (const float*)d_in[11];
    const float* ck_w = (const float*)d_in[12];
    const float* ck_b = (const float*)d_in[13];
    const float* cv_w = (const float*)d_in[14];
    const float* cv_b = (const float*)d_in[15];
    const float* gamma= (const float*)d_in[16];
    float* out = (float*)d_out;

    const int prep_smem = (3 * 64 * CP + 128) * sizeof(float);
    const int out_smem  = (5 * 64 * CP + 128) * sizeof(float);
    cudaFuncSetAttribute(chunk_prep_kernel,
                         cudaFuncAttributeMaxDynamicSharedMemorySize, prep_smem);
    cudaFuncSetAttribute(chunk_out_kernel,
                         cudaFuncAttributeMaxDynamicSharedMemorySize, out_smem);
    cudaFuncSetAttribute(proj_gemm_kernel,
                         cudaFuncAttributeMaxDynamicSharedMemorySize, GSMEM);
    cudaFuncSetAttribute(out_gemm_kernel,
                         cudaFuncAttributeMaxDynamicSharedMemorySize, GSMEM);

    const int cvt_blocks = (Mrows * Dd + 5 * Dd * INNER) / 1024;
    cvt_kernel<<<cvt_blocks, 256>>>(x, Wq, Wk, Wv, Wg, Wo);
    proj_gemm_kernel<<<dim3(INNER / 128, Mrows / 128, 4), 128, GSMEM>>>();
    conv_kernel<<<dim3(Mrows / 16, 4, 3), 128>>>(cq_w, cq_b, ck_w, ck_b,
                                                 cv_w, cv_b);
    ab_kernel<<<Mrows, 256>>>(x, Wa, ba, Wb, bb);   // launch #4 -> ncu target
    chunk_prep_kernel<<<1024, 256, prep_smem>>>();
    chunk_scan_kernel<<<dim3(Bz * Hh, 4), 256>>>();
    chunk_out_kernel<<<1024, 256, out_smem>>>();
    rmsgate_kernel<<<Mrows, 256>>>(gamma);
    out_gemm_kernel<<<dim3(Dd / 128, Mrows / 128), 128, GSMEM>>>(out);
}

// round 8
// speedup vs baseline: 3.7689x; 1.0140x over previous
#include <cuda_runtime.h>
#include <math.h>
#include <stdint.h>

// Problem constants
#define Bz 2
#define Tt 2048
#define Dd 1024
#define Hh 16
#define dh 64
#define INNER 1024
#define Mrows 4096   // B*T
#define NCHUNK 32
#define CP 65        // padded stride for 64x64 smem tiles

// ---------------- scratch ----------------------------------------------------
__device__ float g_Xq[Mrows * INNER];
__device__ float g_Xk[Mrows * INNER];
__device__ float g_Xv[Mrows * INNER];
__device__ float g_Xg[Mrows * INNER];
__device__ float g_Qn[Mrows * INNER];
__device__ float g_Kn[Mrows * INNER];
__device__ float g_Vv[Mrows * INNER];
__device__ float g_AB[Mrows * 32];
__device__ float g_O [Mrows * INNER];
__device__ float g_Y [Mrows * INNER];
__device__ float g_xa[Mrows * Dd];
__device__ float g_Wr[5 * Dd * INNER];
__device__ float g_T [1024 * 4096];
__device__ float g_W [1024 * 4096];
__device__ float g_M [1024 * 4096];
__device__ float g_N [1024 * 4096];
__device__ float g_S0[1024 * 4096];
__device__ float g_gam[1024 * 64];
__device__ float g_r  [1024 * 64];

// ---------------- helpers ----------------------------------------------------
__device__ __forceinline__ unsigned cvt_tf32(float f) {
    unsigned u;
    asm("cvt.rna.tf32.f32 %0, %1;" : "=r"(u) : "f"(f));
    return u;
}
__device__ __forceinline__ float rna_tf32(float f) {
    return __uint_as_float(cvt_tf32(f));
}
__device__ __forceinline__ uint32_t smem_u32(const void* p) {
    uint32_t a;
    asm("{ .reg .u64 t; cvta.to.shared.u64 t, %1; cvt.u32.u64 %0, t; }"
        : "=r"(a) : "l"(p));
    return a;
}
__device__ __forceinline__ void cp16(uint32_t saddr, const void* gptr) {
    asm volatile("cp.async.cg.shared.global [%0], [%1], 16;" :: "r"(saddr), "l"(gptr));
}
#define CP_COMMIT() asm volatile("cp.async.commit_group;" ::: "memory")

__device__ __forceinline__ void mma_tf32(float* d, unsigned a0, unsigned a1,
                                         unsigned a2, unsigned a3,
                                         unsigned b0, unsigned b1) {
    asm("mma.sync.aligned.m16n8k8.row.col.f32.tf32.tf32.f32 "
        "{%0,%1,%2,%3}, {%4,%5,%6,%7}, {%8,%9}, {%0,%1,%2,%3};\n"
        : "+f"(d[0]), "+f"(d[1]), "+f"(d[2]), "+f"(d[3])
        : "r"(a0), "r"(a1), "r"(a2), "r"(a3), "r"(b0), "r"(b1));
}

// ---------------- tf32 GEMM, 128x128 tile, cp.async 3-stage pipeline ---------
#define APAD 20
#define BPAD 136
#define AST  (128 * APAD)
#define BST  (16 * BPAD)
#define GSMEM ((3 * (AST + BST)) * 4)

__device__ __forceinline__ void tgemm128(const float* __restrict__ A,
                                         const float* __restrict__ Bm,
                                         float* __restrict__ C,
                                         int N, int bm, int bn,
                                         bool do_silu)
{
    extern __shared__ float smp[];
    float* As = smp;
    float* Bs = smp + 3 * AST;

    const int tid  = threadIdx.x;
    const int lane = tid & 31;
    const int wid  = tid >> 5;
    const int warpM = (wid & 1) * 64;
    const int warpN = (wid >> 1) * 64;

    float acc[4][8][4];
#pragma unroll
    for (int mt = 0; mt < 4; mt++)
#pragma unroll
        for (int nt = 0; nt < 8; nt++)
#pragma unroll
            for (int i = 0; i < 4; i++) acc[mt][nt][i] = 0.f;

    const uint32_t asu = smem_u32(As);
    const uint32_t bsu = smem_u32(Bs);

    auto load_stage = [&](int kt, int st) {
        const int k0 = kt << 4;
        const uint32_t sa = asu + st * (AST * 4);
        const uint32_t sb = bsu + st * (BST * 4);
#pragma unroll
        for (int i = 0; i < 4; i++) {
            const int idx = tid + i * 128;
            const int row = idx >> 2, kq = (idx & 3) << 2;
            cp16(sa + (row * APAD + kq) * 4,
                 A + (long)(bm + row) * 1024 + k0 + kq);
            const int kk = idx >> 5, nq = (idx & 31) << 2;
            cp16(sb + (kk * BPAD + nq) * 4,
                 Bm + (long)(k0 + kk) * N + bn + nq);
        }
        CP_COMMIT();
    };

    load_stage(0, 0);
    load_stage(1, 1);
    load_stage(2, 2);

    for (int kt = 0; kt < 64; kt++) {
        const int st = kt - (kt / 3) * 3;
        if (kt <= 61)      asm volatile("cp.async.wait_group 2;" ::: "memory");
        else if (kt == 62) asm volatile("cp.async.wait_group 1;" ::: "memory");
        else               asm volatile("cp.async.wait_group 0;" ::: "memory");
        __syncthreads();

        const float* as = As + st * AST;
        const float* bs = Bs + st * BST;
#pragma unroll
        for (int k8 = 0; k8 < 16; k8 += 8) {
            const int kk0 = k8 + (lane & 3);
            const int kk1 = kk0 + 4;
            unsigned af[4][4], bf[8][2];
#pragma unroll
            for (int mt = 0; mt < 4; mt++) {
                const int r0 = warpM + mt * 16 + (lane >> 2);
                af[mt][0] = __float_as_uint(as[r0 * APAD + kk0]);
                af[mt][1] = __float_as_uint(as[(r0 + 8) * APAD + kk0]);
                af[mt][2] = __float_as_uint(as[r0 * APAD + kk1]);
                af[mt][3] = __float_as_uint(as[(r0 + 8) * APAD + kk1]);
            }
#pragma unroll
            for (int nt = 0; nt < 8; nt++) {
                const int n = warpN + nt * 8 + (lane >> 2);
                bf[nt][0] = __float_as_uint(bs[kk0 * BPAD + n]);
                bf[nt][1] = __float_as_uint(bs[kk1 * BPAD + n]);
            }
#pragma unroll
            for (int mt = 0; mt < 4; mt++)
#pragma unroll
                for (int nt = 0; nt < 8; nt++)
                    mma_tf32(acc[mt][nt], af[mt][0], af[mt][1], af[mt][2], af[mt][3],
                             bf[nt][0], bf[nt][1]);
        }
        __syncthreads();
        if (kt + 3 < 64) load_stage(kt + 3, st);
    }

#pragma unroll
    for (int mt = 0; mt < 4; mt++) {
        const int r0 = bm + warpM + mt * 16 + (lane >> 2);
#pragma unroll
        for (int nt = 0; nt < 8; nt++) {
            const int c = bn + warpN + nt * 8 + ((lane & 3) << 1);
            float v0 = acc[mt][nt][0], v1 = acc[mt][nt][1];
            float v2 = acc[mt][nt][2], v3 = acc[mt][nt][3];
            if (do_silu) {
                v0 = v0 / (1.f + expf(-v0));
                v1 = v1 / (1.f + expf(-v1));
                v2 = v2 / (1.f + expf(-v2));
                v3 = v3 / (1.f + expf(-v3));
            }
            *(float2*)(C + (long)r0 * N + c)       = make_float2(v0, v1);
            *(float2*)(C + (long)(r0 + 8) * N + c) = make_float2(v2, v3);
        }
    }
}

__global__ __launch_bounds__(128) void proj_gemm_kernel()
{
    const int z = blockIdx.z;
    const float* W = g_Wr + (long)z * (Dd * INNER);
    float* O;
    bool silu = false;
    switch (z) {
        case 0:  O = g_Xq; break;
        case 1:  O = g_Xk; break;
        case 2:  O = g_Xv; break;
        default: O = g_Xg; silu = true; break;
    }
    tgemm128(g_xa, W, O, INNER, blockIdx.y * 128, blockIdx.x * 128, silu);
}

__global__ __launch_bounds__(128) void out_gemm_kernel(float* __restrict__ out)
{
    tgemm128(g_Y, g_Wr + 4L * Dd * INNER, out, Dd,
             blockIdx.y * 128, blockIdx.x * 128, false);
}

// ---------------- merged tf32-rounding pre-pass ------------------------------
__global__ __launch_bounds__(256) void cvt_kernel(
    const float* __restrict__ x,
    const float* __restrict__ Wq, const float* __restrict__ Wk,
    const float* __restrict__ Wv, const float* __restrict__ Wg,
    const float* __restrict__ Wo)
{
    const long i = ((long)blockIdx.x * 256 + threadIdx.x) * 4;
    const float* src;
    float* dst;
    if (i < (long)Mrows * Dd) {
        src = x + i;
        dst = g_xa + i;
    } else {
        const long j = i - (long)Mrows * Dd;
        const int w = (int)(j >> 20);
        const float* Ws[5] = {Wq, Wk, Wv, Wg, Wo};
        src = Ws[w] + (j & 1048575);
        dst = g_Wr + j;
    }
    float4 v = *(const float4*)src;
    v.x = rna_tf32(v.x); v.y = rna_tf32(v.y);
    v.z = rna_tf32(v.z); v.w = rna_tf32(v.w);
    *(float4*)dst = v;
}

// ---------------- conv (z<3) + alpha/beta mini-GEMM (z==3) -------------------
__global__ __launch_bounds__(128) void convab_kernel(
    const float* __restrict__ x,
    const float* __restrict__ cq_w, const float* __restrict__ cq_b,
    const float* __restrict__ ck_w, const float* __restrict__ ck_b,
    const float* __restrict__ cv_w, const float* __restrict__ cv_b,
    const float* __restrict__ Wa, const float* __restrict__ ba,
    const float* __restrict__ Wb, const float* __restrict__ bb)
{
    __shared__ float s_ab[32 * 65 + 64 * 33];

    if (blockIdx.z == 3) {
        // alpha/beta GEMM: x(4096,1024) @ [Wa|Wb](1024,32) -> sigmoid -> g_AB
        if (blockIdx.x >= 128 || blockIdx.y != 0) return;
        const int blk = blockIdx.x;          // 32 rows each
        const int tid = threadIdx.x;
        float* xs = s_ab;                    // [32][65]
        float* ws = s_ab + 32 * 65;          // [64][33]
        const int mrow = tid >> 2;           // 0..31
        const int ogrp = tid & 3;            // 0..3 -> 8 outs each

        float acc[8];
#pragma unroll
        for (int j = 0; j < 8; j++) acc[j] = 0.f;

        for (int k0 = 0; k0 < Dd; k0 += 64) {
#pragma unroll
            for (int i = 0; i < 4; i++) {
                const int idx = tid + i * 128;        // 0..511 float4s
                const int row = idx >> 4;
                const int c4  = (idx & 15) << 2;
                float4 v = *(const float4*)(x + (long)(blk * 32 + row) * Dd + k0 + c4);
                xs[row * 65 + c4 + 0] = v.x;
                xs[row * 65 + c4 + 1] = v.y;
                xs[row * 65 + c4 + 2] = v.z;
                xs[row * 65 + c4 + 3] = v.w;
            }
#pragma unroll
            for (int i = 0; i < 16; i++) {
                const int idx = tid + i * 128;        // 0..2047
                const int row = idx >> 5;
                const int col = idx & 31;
                ws[row * 33 + col] = (col < 16) ? Wa[(k0 + row) * Hh + col]
                                                : Wb[(k0 + row) * Hh + col - 16];
            }
            __syncthreads();
#pragma unroll 8
            for (int k = 0; k < 64; k++) {
                const float xv = xs[mrow * 65 + k];
#pragma unroll
                for (int j = 0; j < 8; j++)
                    acc[j] = fmaf(xv, ws[k * 33 + ogrp * 8 + j], acc[j]);
            }
            __syncthreads();
        }
#pragma unroll
        for (int j = 0; j < 8; j++) {
            const int o = ogrp * 8 + j;
            const float bias = (o < 16) ? ba[o] : bb[o - 16];
            g_AB[(long)(blk * 32 + mrow) * 32 + o] =
                1.f / (1.f + expf(-(acc[j] + bias)));
        }
        return;
    }

    // ---- depthwise causal conv + silu (+ l2norm for q,k) ----
    const float* Xin; float* Out; const float* cw; const float* cb; bool donorm;
    switch (blockIdx.z) {
        case 0:  Xin = g_Xq; Out = g_Qn; cw = cq_w; cb = cq_b; donorm = true;  break;
        case 1:  Xin = g_Xk; Out = g_Kn; cw = ck_w; cb = ck_b; donorm = true;  break;
        default: Xin = g_Xv; Out = g_Vv; cw = cv_w; cb = cv_b; donorm = false; break;
    }
    const int bt0 = blockIdx.x * 16;
    const int t0  = bt0 & (Tt - 1);
    const int lane = threadIdx.x & 31;
    const int wid  = threadIdx.x >> 5;
    const int h = blockIdx.y * 4 + wid;
    const int c0 = h * 64 + lane;

    float x0[19], x1[19];
#pragma unroll
    for (int i = 0; i < 19; i++) {
        const int t = t0 - 3 + i;
        if (t < 0) { x0[i] = 0.f; x1[i] = 0.f; }
        else {
            const long g = (long)(bt0 - t0 + t) * INNER + c0;
            x0[i] = Xin[g];
            x1[i] = Xin[g + 32];
        }
    }
    float w0[4], w1[4];
#pragma unroll
    for (int k = 0; k < 4; k++) {
        w0[k] = cw[c0 * 4 + k];
        w1[k] = cw[(c0 + 32) * 4 + k];
    }
    const float b0 = cb[c0], b1 = cb[c0 + 32];

#pragma unroll
    for (int tt = 0; tt < 16; tt++) {
        float a0 = b0, a1 = b1;
#pragma unroll
        for (int k = 0; k < 4; k++) {
            a0 = fmaf(x0[tt + k], w0[k], a0);
            a1 = fmaf(x1[tt + k], w1[k], a1);
        }
        float s0 = a0 / (1.f + expf(-a0));
        float s1 = a1 / (1.f + expf(-a1));
        float ss = s0 * s0 + s1 * s1;
        ss += __shfl_xor_sync(0xffffffffu, ss, 16);
        ss += __shfl_xor_sync(0xffffffffu, ss, 8);
        ss += __shfl_xor_sync(0xffffffffu, ss, 4);
        ss += __shfl_xor_sync(0xffffffffu, ss, 2);
        ss += __shfl_xor_sync(0xffffffffu, ss, 1);
        if (donorm) {
            const float inv = 1.f / fmaxf(sqrtf(ss), 1e-12f);
            s0 *= inv; s1 *= inv;
        }
        const long g = (long)(bt0 + tt) * INNER + c0;
        Out[g] = s0;
        Out[g + 32] = s1;
    }
}

// ============== chunked delta-rule scan ======================================

__global__ __launch_bounds__(256, 2) void chunk_prep_kernel()
{
    extern __shared__ float sm[];
    float* sK = sm;
    float* sV = sm + 64 * CP;
    float* sL = sm + 2 * 64 * CP;
    float* sGam = sm + 3 * 64 * CP;
    float* sR   = sGam + 64;

    const int chunk = blockIdx.x;
    const int c  = chunk & (NCHUNK - 1);
    const int bh = chunk >> 5;
    const int b = bh >> 4, h = bh & 15;
    const int tid = threadIdx.x;
    const long rowbase = (long)b * Tt + c * 64;
    const int colbase = h * dh;
    const long cb = (long)chunk * 4096;

    for (int idx = tid; idx < 1024; idx += 256) {
        const int row = idx >> 4;
        const int c4  = (idx & 15) << 2;
        const long g = (rowbase + row) * INNER + colbase + c4;
        float4 kv = *(const float4*)(g_Kn + g);
        float4 vv = *(const float4*)(g_Vv + g);
        sK[row * CP + c4 + 0] = kv.x; sK[row * CP + c4 + 1] = kv.y;
        sK[row * CP + c4 + 2] = kv.z; sK[row * CP + c4 + 3] = kv.w;
        sV[row * CP + c4 + 0] = vv.x; sV[row * CP + c4 + 1] = vv.y;
        sV[row * CP + c4 + 2] = vv.z; sV[row * CP + c4 + 3] = vv.w;
    }
    if (tid < 64) {
        sGam[tid] = g_AB[(rowbase + tid) * 32 + h];
        sR[tid]   = g_AB[(rowbase + tid) * 32 + 16 + h];
    }
    __syncthreads();
    if (tid == 0) {
        float p = 1.f;
        for (int i = 0; i < 64; i++) { p *= sGam[i]; sGam[i] = p; }
    }
    __syncthreads();
    if (tid < 64) sR[tid] = sR[tid] / sGam[tid];
    __syncthreads();

    const int ty = tid >> 4, tx = tid & 15;

    {
        float acc[4][4];
#pragma unroll
        for (int v = 0; v < 4; v++)
#pragma unroll
            for (int u = 0; u < 4; u++) acc[v][u] = 0.f;
        for (int k = 0; k < 64; k++) {
            float a[4], bb[4];
#pragma unroll
            for (int v = 0; v < 4; v++) a[v]  = sK[(ty + 16 * v) * CP + k];
#pragma unroll
            for (int u = 0; u < 4; u++) bb[u] = sK[(tx + 16 * u) * CP + k];
#pragma unroll
            for (int v = 0; v < 4; v++)
#pragma unroll
                for (int u = 0; u < 4; u++)
                    acc[v][u] = fmaf(a[v], bb[u], acc[v][u]);
        }
#pragma unroll
        for (int v = 0; v < 4; v++)
#pragma unroll
            for (int u = 0; u < 4; u++) {
                const int j = ty + 16 * v, i = tx + 16 * u;
                sL[j * CP + i] = (i < j) ? acc[v][u] * sGam[j] * sR[i] : 0.f;
            }
        __syncthreads();
    }

    float rr_[64];
    const int col = tid & 63;
    const int isW = (tid >> 6) & 1;
    if (tid < 128) {
#pragma unroll
        for (int j = 0; j < 64; j++)
            rr_[j] = isW ? sGam[j] * sK[j * CP + col] : sV[j * CP + col];
#pragma unroll
        for (int j = 0; j < 64; j++) {
            const float xj = rr_[j];
#pragma unroll
            for (int i = j + 1; i < 64; i++)
                rr_[i] -= sL[i * CP + j] * xj;
        }
    }
    __syncthreads();

    const float gC = sGam[63];
    if (tid < 128) {
        float* dst  = isW ? sL : sV;
        float* gdst = isW ? g_W : g_T;
#pragma unroll
        for (int j = 0; j < 64; j++) {
            dst[j * CP + col] = rr_[j];
            gdst[cb + j * 64 + col] = rr_[j];
        }
    } else {
        const int t2 = tid - 128;
        for (int idx = t2; idx < 4096; idx += 128) {
            const int j = idx >> 6;
            sK[j * CP + (idx & 63)] *= gC * sR[j];
        }
    }
    if (tid < 64) {
        g_gam[chunk * 64 + tid] = sGam[tid];
        g_r  [chunk * 64 + tid] = sR[tid];
    }
    __syncthreads();

    {
        float am[4][4], an[4][4];
#pragma unroll
        for (int v = 0; v < 4; v++)
#pragma unroll
            for (int u = 0; u < 4; u++) {
                am[v][u] = ((ty == tx) && (v == u)) ? gC : 0.f;
                an[v][u] = 0.f;
            }
        for (int j = 0; j < 64; j++) {
            float wv[4], tv[4], kb[4];
#pragma unroll
            for (int v = 0; v < 4; v++) {
                wv[v] = sL[j * CP + ty + 16 * v];
                tv[v] = sV[j * CP + ty + 16 * v];
            }
#pragma unroll
            for (int u = 0; u < 4; u++) kb[u] = sK[j * CP + tx + 16 * u];
#pragma unroll
            for (int v = 0; v < 4; v++)
#pragma unroll
                for (int u = 0; u < 4; u++) {
                    am[v][u] = fmaf(-wv[v], kb[u], am[v][u]);
                    an[v][u] = fmaf( tv[v], kb[u], an[v][u]);
                }
        }
#pragma unroll
        for (int v = 0; v < 4; v++)
#pragma unroll
            for (int u = 0; u < 4; u++) {
                const int p = ty + 16 * v, q = tx + 16 * u;
                g_M[cb + p * 64 + q] = am[v][u];
                g_N[cb + p * 64 + q] = an[v][u];
            }
    }
}

__global__ __launch_bounds__(256) void chunk_scan_kernel()
{
    __shared__ float sS[16 * 64];
    __shared__ float sM[64 * 64];
    const int bh = blockIdx.x;
    const int R0 = blockIdx.y * 16;
    const int tid = threadIdx.x;
    const int row = tid >> 4;
    const int tx  = tid & 15;

    for (int idx = tid; idx < 1024; idx += 256) sS[idx] = 0.f;
    __syncthreads();

    for (int c = 0; c < NCHUNK; c++) {
        const long cb = (long)(bh * NCHUNK + c) * 4096;
        for (int idx = tid; idx < 1024; idx += 256)
            g_S0[cb + (long)(R0 + (idx >> 6)) * 64 + (idx & 63)] = sS[idx];
        for (int idx = tid; idx < 4096; idx += 256)
            sM[idx] = g_M[cb + idx];
        __syncthreads();

        float acc[4];
#pragma unroll
        for (int u = 0; u < 4; u++)
            acc[u] = g_N[cb + (long)(R0 + row) * 64 + tx + 16 * u];
        for (int k = 0; k < 64; k++) {
            const float s = sS[row * 64 + k];
#pragma unroll
            for (int u = 0; u < 4; u++)
                acc[u] = fmaf(s, sM[k * 64 + tx + 16 * u], acc[u]);
        }
        __syncthreads();
#pragma unroll
        for (int u = 0; u < 4; u++) sS[row * 64 + tx + 16 * u] = acc[u];
        __syncthreads();
    }
}

__global__ __launch_bounds__(256, 2) void chunk_out_kernel()
{
    extern __shared__ float sm[];
    float* sQ   = sm;
    float* sKW  = sm + 64 * CP;
    float* sS0T = sm + 2 * 64 * CP;
    float* sTU  = sm + 3 * 64 * CP;
    float* sA   = sm + 4 * 64 * CP;
    float* sGam = sm + 5 * 64 * CP;
    float* sR   = sGam + 64;

    const int chunk = blockIdx.x;
    const int c  = chunk & (NCHUNK - 1);
    const int bh = chunk >> 5;
    const int b = bh >> 4, h = bh & 15;
    const int tid = threadIdx.x;
    const long rowbase = (long)b * Tt + c * 64;
    const int colbase = h * dh;
    const long cb = (long)chunk * 4096;

    for (int idx = tid; idx < 1024; idx += 256) {
        const int row = idx >> 4;
        const int c4  = (idx & 15) << 2;
        const long g = (rowbase + row) * INNER + colbase + c4;
        float4 qv = *(const float4*)(g_Qn + g);
        float4 kv = *(const float4*)(g_Kn + g);
        sQ [row * CP + c4 + 0] = qv.x; sQ [row * CP + c4 + 1] = qv.y;
        sQ [row * CP + c4 + 2] = qv.z; sQ [row * CP + c4 + 3] = qv.w;
        sKW[row * CP + c4 + 0] = kv.x; sKW[row * CP + c4 + 1] = kv.y;
        sKW[row * CP + c4 + 2] = kv.z; sKW[row * CP + c4 + 3] = kv.w;
    }
    for (int idx = tid; idx < 4096; idx += 256) {
        sS0T[(idx & 63) * CP + (idx >> 6)] = g_S0[cb + idx];
        sTU [(idx >> 6) * CP + (idx & 63)] = g_T[cb + idx];
    }
    if (tid < 64) {
        sGam[tid] = g_gam[chunk * 64 + tid];
        sR[tid]   = g_r[chunk * 64 + tid];
    }
    __syncthreads();

    const int ty = tid >> 4, tx = tid & 15;

    {
        float acc[4][4];
#pragma unroll
        for (int v = 0; v < 4; v++)
#pragma unroll
            for (int u = 0; u < 4; u++) acc[v][u] = 0.f;
        for (int k = 0; k < 64; k++) {
            float qa[4], kb[4];
#pragma unroll
            for (int v = 0; v < 4; v++) qa[v] = sQ [(ty + 16 * v) * CP + k];
#pragma unroll
            for (int u = 0; u < 4; u++) kb[u] = sKW[(tx + 16 * u) * CP + k];
#pragma unroll
            for (int v = 0; v < 4; v++)
#pragma unroll
                for (int u = 0; u < 4; u++)
                    acc[v][u] = fmaf(qa[v], kb[u], acc[v][u]);
        }
#pragma unroll
        for (int v = 0; v < 4; v++)
#pragma unroll
            for (int u = 0; u < 4; u++) {
                const int t = ty + 16 * v, j = tx + 16 * u;
                sA[t * CP + j] = (j <= t) ? acc[v][u] * sGam[t] * sR[j] : 0.f;
            }
    }
    __syncthreads();

    for (int idx = tid; idx < 4096; idx += 256)
        sKW[(idx >> 6) * CP + (idx & 63)] = g_W[cb + idx];
    __syncthreads();

    {
        float au[4][4];
#pragma unroll
        for (int v = 0; v < 4; v++)
#pragma unroll
            for (int u = 0; u < 4; u++)
                au[v][u] = sTU[(ty + 16 * v) * CP + tx + 16 * u];
        for (int k = 0; k < 64; k++) {
            float wv[4], sb[4];
#pragma unroll
            for (int v = 0; v < 4; v++) wv[v] = sKW[(ty + 16 * v) * CP + k];
#pragma unroll
            for (int u = 0; u < 4; u++) sb[u] = sS0T[k * CP + tx + 16 * u];
#pragma unroll
            for (int v = 0; v < 4; v++)
#pragma unroll
                for (int u = 0; u < 4; u++)
                    au[v][u] = fmaf(-wv[v], sb[u], au[v][u]);
        }
        __syncthreads();
#pragma unroll
        for (int v = 0; v < 4; v++)
#pragma unroll
            for (int u = 0; u < 4; u++)
                sTU[(ty + 16 * v) * CP + tx + 16 * u] = au[v][u];
    }
    __syncthreads();

    {
        float o1[4][4], o2[4][4];
#pragma unroll
        for (int v = 0; v < 4; v++)
#pragma unroll
            for (int u = 0; u < 4; u++) { o1[v][u] = 0.f; o2[v][u] = 0.f; }
        for (int k = 0; k < 64; k++) {
            float qa[4], sb[4], aa[4], ub[4];
#pragma unroll
            for (int v = 0; v < 4; v++) {
                qa[v] = sQ[(ty + 16 * v) * CP + k];
                aa[v] = sA[(ty + 16 * v) * CP + k];
            }
#pragma unroll
            for (int u = 0; u < 4; u++) {
                sb[u] = sS0T[k * CP + tx + 16 * u];
                ub[u] = sTU [k * CP + tx + 16 * u];
            }
#pragma unroll
            for (int v = 0; v < 4; v++)
#pragma unroll
                for (int u = 0; u < 4; u++) {
                    o1[v][u] = fmaf(qa[v], sb[u], o1[v][u]);
                    o2[v][u] = fmaf(aa[v], ub[u], o2[v][u]);
                }
        }
#pragma unroll
        for (int v = 0; v < 4; v++)
#pragma unroll
            for (int u = 0; u < 4; u++) {
                const int t = ty + 16 * v, a = tx + 16 * u;
                g_O[(rowbase + t) * INNER + colbase + a] =
                    sGam[t] * o1[v][u] + o2[v][u];
            }
    }
}

// ---------------- RMS norm + (1+gamma) + gate (float4) -----------------------
__global__ __launch_bounds__(256) void rmsgate_kernel(const float* __restrict__ gamma)
{
    const int m = blockIdx.x;
    const int tid = threadIdx.x;
    const long base = (long)m * INNER + tid * 4;
    float4 xv = *(const float4*)(g_O + base);
    float ss = xv.x * xv.x + xv.y * xv.y + xv.z * xv.z + xv.w * xv.w;
    for (int off = 16; off; off >>= 1) ss += __shfl_xor_sync(0xffffffffu, ss, off);
    __shared__ float red[8];
    if ((tid & 31) == 0) red[tid >> 5] = ss;
    __syncthreads();
    float tot = 0.f;
#pragma unroll
    for (int w = 0; w < 8; w++) tot += red[w];
    const float inv = 1.f / sqrtf(tot * (1.f / (float)INNER) + 1e-6f);
    float4 gv = *(const float4*)(g_Xg + base);
    float4 gm = *(const float4*)(gamma + tid * 4);
    float4 o;
    o.x = rna_tf32(xv.x * inv * (1.f + gm.x) * gv.x);
    o.y = rna_tf32(xv.y * inv * (1.f + gm.y) * gv.y);
    o.z = rna_tf32(xv.z * inv * (1.f + gm.z) * gv.z);
    o.w = rna_tf32(xv.w * inv * (1.f + gm.w) * gv.w);
    *(float4*)(g_Y + base) = o;
}

// ---------------- launch -----------------------------------------------------
extern "C" void kernel_launch(void* const* d_in, const int* in_sizes, int n_in,
                              void* d_out, int out_size)
{
    const float* x    = (const float*)d_in[0];
    const float* Wq   = (const float*)d_in[1];
    const float* Wk   = (const float*)d_in[2];
    const float* Wv   = (const float*)d_in[3];
    const float* Wa   = (const float*)d_in[4];
    const float* ba   = (const float*)d_in[5];
    const float* Wb   = (const float*)d_in[6];
    const float* bb   = (const float*)d_in[7];
    const float* Wg   = (const float*)d_in[8];
    const float* Wo   = (const float*)d_in[9];
    const float* cq_w = (const float*)d_in[10];
    const float* cq_b = (const float*)d_in[11];
    const float* ck_w = (const float*)d_in[12];
    const float* ck_b = (const float*)d_in[13];
    const float* cv_w = (const float*)d_in[14];
    const float* cv_b = (const float*)d_in[15];
    const float* gamma= (const float*)d_in[16];
    float* out = (float*)d_out;

    const int prep_smem = (3 * 64 * CP + 128) * sizeof(float);
    const int out_smem  = (5 * 64 * CP + 128) * sizeof(float);
    cudaFuncSetAttribute(chunk_prep_kernel,
                         cudaFuncAttributeMaxDynamicSharedMemorySize, prep_smem);
    cudaFuncSetAttribute(chunk_out_kernel,
                         cudaFuncAttributeMaxDynamicSharedMemorySize, out_smem);
    cudaFuncSetAttribute(proj_gemm_kernel,
                         cudaFuncAttributeMaxDynamicSharedMemorySize, GSMEM);
    cudaFuncSetAttribute(out_gemm_kernel,
                         cudaFuncAttributeMaxDynamicSharedMemorySize, GSMEM);

    const int cvt_blocks = (Mrows * Dd + 5 * Dd * INNER) / 1024;
    cvt_kernel<<<cvt_blocks, 256>>>(x, Wq, Wk, Wv, Wg, Wo);
    proj_gemm_kernel<<<dim3(INNER / 128, Mrows / 128, 4), 128, GSMEM>>>();
    convab_kernel<<<dim3(Mrows / 16, 4, 4), 128>>>(x, cq_w, cq_b, ck_w, ck_b,
                                                   cv_w, cv_b, Wa, ba, Wb, bb);
    chunk_prep_kernel<<<1024, 256, prep_smem>>>();   // launch #4 -> ncu target
    chunk_scan_kernel<<<dim3(Bz * Hh, 4), 256>>>();
    chunk_out_kernel<<<1024, 256, out_smem>>>();
    rmsgate_kernel<<<Mrows, 256>>>(gamma);
    out_gemm_kernel<<<dim3(Dd / 128, Mrows / 128), 128, GSMEM>>>(out);
}

// round 9
// speedup vs baseline: 4.0814x; 1.0829x over previous
#include <cuda_runtime.h>
#include <math.h>
#include <stdint.h>

// Problem constants
#define Bz 2
#define Tt 2048
#define Dd 1024
#define Hh 16
#define dh 64
#define INNER 1024
#define Mrows 4096   // B*T
#define NCHUNK 32
#define CP 65        // padded stride for 64x64 smem tiles (SIMT kernels)
#define CO 68        // padded stride for chunk_out mma tiles (4r+c banks)

// ---------------- scratch ----------------------------------------------------
__device__ float g_Xq[Mrows * INNER];
__device__ float g_Xk[Mrows * INNER];
__device__ float g_Xv[Mrows * INNER];
__device__ float g_Xg[Mrows * INNER];
__device__ float g_Qn[Mrows * INNER];
__device__ float g_Kn[Mrows * INNER];
__device__ float g_Vv[Mrows * INNER];
__device__ float g_AB[Mrows * 32];
__device__ float g_O [Mrows * INNER];
__device__ float g_Y [Mrows * INNER];
__device__ float g_xa[Mrows * Dd];
__device__ float g_Wr[5 * Dd * INNER];
__device__ float g_T [1024 * 4096];
__device__ float g_W [1024 * 4096];
__device__ float g_M [1024 * 4096];
__device__ float g_N [1024 * 4096];
__device__ float g_S0[1024 * 4096];
__device__ float g_gam[1024 * 64];
__device__ float g_r  [1024 * 64];

// ---------------- helpers ----------------------------------------------------
__device__ __forceinline__ unsigned cvt_tf32(float f) {
    unsigned u;
    asm("cvt.rna.tf32.f32 %0, %1;" : "=r"(u) : "f"(f));
    return u;
}
__device__ __forceinline__ float rna_tf32(float f) {
    return __uint_as_float(cvt_tf32(f));
}
__device__ __forceinline__ uint32_t smem_u32(const void* p) {
    uint32_t a;
    asm("{ .reg .u64 t; cvta.to.shared.u64 t, %1; cvt.u32.u64 %0, t; }"
        : "=r"(a) : "l"(p));
    return a;
}
__device__ __forceinline__ void cp16(uint32_t saddr, const void* gptr) {
    asm volatile("cp.async.cg.shared.global [%0], [%1], 16;" :: "r"(saddr), "l"(gptr));
}
#define CP_COMMIT() asm volatile("cp.async.commit_group;" ::: "memory")

__device__ __forceinline__ void mma_tf32(float* d, unsigned a0, unsigned a1,
                                         unsigned a2, unsigned a3,
                                         unsigned b0, unsigned b1) {
    asm("mma.sync.aligned.m16n8k8.row.col.f32.tf32.tf32.f32 "
        "{%0,%1,%2,%3}, {%4,%5,%6,%7}, {%8,%9}, {%0,%1,%2,%3};\n"
        : "+f"(d[0]), "+f"(d[1]), "+f"(d[2]), "+f"(d[3])
        : "r"(a0), "r"(a1), "r"(a2), "r"(a3), "r"(b0), "r"(b1));
}

// ---------------- tf32 GEMM, 128x128 tile, cp.async 3-stage pipeline ---------
#define APAD 20
#define BPAD 136
#define AST  (128 * APAD)
#define BST  (16 * BPAD)
#define GSMEM ((3 * (AST + BST)) * 4)

__device__ __forceinline__ void tgemm128(const float* __restrict__ A,
                                         const float* __restrict__ Bm,
                                         float* __restrict__ C,
                                         int N, int bm, int bn,
                                         bool do_silu)
{
    extern __shared__ float smp[];
    float* As = smp;
    float* Bs = smp + 3 * AST;

    const int tid  = threadIdx.x;
    const int lane = tid & 31;
    const int wid  = tid >> 5;
    const int warpM = (wid & 1) * 64;
    const int warpN = (wid >> 1) * 64;

    float acc[4][8][4];
#pragma unroll
    for (int mt = 0; mt < 4; mt++)
#pragma unroll
        for (int nt = 0; nt < 8; nt++)
#pragma unroll
            for (int i = 0; i < 4; i++) acc[mt][nt][i] = 0.f;

    const uint32_t asu = smem_u32(As);
    const uint32_t bsu = smem_u32(Bs);

    auto load_stage = [&](int kt, int st) {
        const int k0 = kt << 4;
        const uint32_t sa = asu + st * (AST * 4);
        const uint32_t sb = bsu + st * (BST * 4);
#pragma unroll
        for (int i = 0; i < 4; i++) {
            const int idx = tid + i * 128;
            const int row = idx >> 2, kq = (idx & 3) << 2;
            cp16(sa + (row * APAD + kq) * 4,
                 A + (long)(bm + row) * 1024 + k0 + kq);
            const int kk = idx >> 5, nq = (idx & 31) << 2;
            cp16(sb + (kk * BPAD + nq) * 4,
                 Bm + (long)(k0 + kk) * N + bn + nq);
        }
        CP_COMMIT();
    };

    load_stage(0, 0);
    load_stage(1, 1);
    load_stage(2, 2);

    for (int kt = 0; kt < 64; kt++) {
        const int st = kt - (kt / 3) * 3;
        if (kt <= 61)      asm volatile("cp.async.wait_group 2;" ::: "memory");
        else if (kt == 62) asm volatile("cp.async.wait_group 1;" ::: "memory");
        else               asm volatile("cp.async.wait_group 0;" ::: "memory");
        __syncthreads();

        const float* as = As + st * AST;
        const float* bs = Bs + st * BST;
#pragma unroll
        for (int k8 = 0; k8 < 16; k8 += 8) {
            const int kk0 = k8 + (lane & 3);
            const int kk1 = kk0 + 4;
            unsigned af[4][4], bf[8][2];
#pragma unroll
            for (int mt = 0; mt < 4; mt++) {
                const int r0 = warpM + mt * 16 + (lane >> 2);
                af[mt][0] = __float_as_uint(as[r0 * APAD + kk0]);
                af[mt][1] = __float_as_uint(as[(r0 + 8) * APAD + kk0]);
                af[mt][2] = __float_as_uint(as[r0 * APAD + kk1]);
                af[mt][3] = __float_as_uint(as[(r0 + 8) * APAD + kk1]);
            }
#pragma unroll
            for (int nt = 0; nt < 8; nt++) {
                const int n = warpN + nt * 8 + (lane >> 2);
                bf[nt][0] = __float_as_uint(bs[kk0 * BPAD + n]);
                bf[nt][1] = __float_as_uint(bs[kk1 * BPAD + n]);
            }
#pragma unroll
            for (int mt = 0; mt < 4; mt++)
#pragma unroll
                for (int nt = 0; nt < 8; nt++)
                    mma_tf32(acc[mt][nt], af[mt][0], af[mt][1], af[mt][2], af[mt][3],
                             bf[nt][0], bf[nt][1]);
        }
        __syncthreads();
        if (kt + 3 < 64) load_stage(kt + 3, st);
    }

#pragma unroll
    for (int mt = 0; mt < 4; mt++) {
        const int r0 = bm + warpM + mt * 16 + (lane >> 2);
#pragma unroll
        for (int nt = 0; nt < 8; nt++) {
            const int c = bn + warpN + nt * 8 + ((lane & 3) << 1);
            float v0 = acc[mt][nt][0], v1 = acc[mt][nt][1];
            float v2 = acc[mt][nt][2], v3 = acc[mt][nt][3];
            if (do_silu) {
                v0 = v0 / (1.f + expf(-v0));
                v1 = v1 / (1.f + expf(-v1));
                v2 = v2 / (1.f + expf(-v2));
                v3 = v3 / (1.f + expf(-v3));
            }
            *(float2*)(C + (long)r0 * N + c)       = make_float2(v0, v1);
            *(float2*)(C + (long)(r0 + 8) * N + c) = make_float2(v2, v3);
        }
    }
}

__global__ __launch_bounds__(128) void proj_gemm_kernel()
{
    const int z = blockIdx.z;
    const float* W = g_Wr + (long)z * (Dd * INNER);
    float* O;
    bool silu = false;
    switch (z) {
        case 0:  O = g_Xq; break;
        case 1:  O = g_Xk; break;
        case 2:  O = g_Xv; break;
        default: O = g_Xg; silu = true; break;
    }
    tgemm128(g_xa, W, O, INNER, blockIdx.y * 128, blockIdx.x * 128, silu);
}

__global__ __launch_bounds__(128) void out_gemm_kernel(float* __restrict__ out)
{
    tgemm128(g_Y, g_Wr + 4L * Dd * INNER, out, Dd,
             blockIdx.y * 128, blockIdx.x * 128, false);
}

// ---------------- merged tf32-rounding pre-pass ------------------------------
__global__ __launch_bounds__(256) void cvt_kernel(
    const float* __restrict__ x,
    const float* __restrict__ Wq, const float* __restrict__ Wk,
    const float* __restrict__ Wv, const float* __restrict__ Wg,
    const float* __restrict__ Wo)
{
    const long i = ((long)blockIdx.x * 256 + threadIdx.x) * 4;
    const float* src;
    float* dst;
    if (i < (long)Mrows * Dd) {
        src = x + i;
        dst = g_xa + i;
    } else {
        const long j = i - (long)Mrows * Dd;
        const int w = (int)(j >> 20);
        const float* Ws[5] = {Wq, Wk, Wv, Wg, Wo};
        src = Ws[w] + (j & 1048575);
        dst = g_Wr + j;
    }
    float4 v = *(const float4*)src;
    v.x = rna_tf32(v.x); v.y = rna_tf32(v.y);
    v.z = rna_tf32(v.z); v.w = rna_tf32(v.w);
    *(float4*)dst = v;
}

// ---------------- conv (z<3) + alpha/beta mini-GEMM (z==3) -------------------
__global__ __launch_bounds__(128) void convab_kernel(
    const float* __restrict__ x,
    const float* __restrict__ cq_w, const float* __restrict__ cq_b,
    const float* __restrict__ ck_w, const float* __restrict__ ck_b,
    const float* __restrict__ cv_w, const float* __restrict__ cv_b,
    const float* __restrict__ Wa, const float* __restrict__ ba,
    const float* __restrict__ Wb, const float* __restrict__ bb)
{
    __shared__ float s_ab[32 * 65 + 64 * 33];

    if (blockIdx.z == 3) {
        if (blockIdx.x >= 128 || blockIdx.y != 0) return;
        const int blk = blockIdx.x;
        const int tid = threadIdx.x;
        float* xs = s_ab;
        float* ws = s_ab + 32 * 65;
        const int mrow = tid >> 2;
        const int ogrp = tid & 3;

        float acc[8];
#pragma unroll
        for (int j = 0; j < 8; j++) acc[j] = 0.f;

        for (int k0 = 0; k0 < Dd; k0 += 64) {
#pragma unroll
            for (int i = 0; i < 4; i++) {
                const int idx = tid + i * 128;
                const int row = idx >> 4;
                const int c4  = (idx & 15) << 2;
                float4 v = *(const float4*)(x + (long)(blk * 32 + row) * Dd + k0 + c4);
                xs[row * 65 + c4 + 0] = v.x;
                xs[row * 65 + c4 + 1] = v.y;
                xs[row * 65 + c4 + 2] = v.z;
                xs[row * 65 + c4 + 3] = v.w;
            }
#pragma unroll
            for (int i = 0; i < 16; i++) {
                const int idx = tid + i * 128;
                const int row = idx >> 5;
                const int col = idx & 31;
                ws[row * 33 + col] = (col < 16) ? Wa[(k0 + row) * Hh + col]
                                                : Wb[(k0 + row) * Hh + col - 16];
            }
            __syncthreads();
#pragma unroll 8
            for (int k = 0; k < 64; k++) {
                const float xv = xs[mrow * 65 + k];
#pragma unroll
                for (int j = 0; j < 8; j++)
                    acc[j] = fmaf(xv, ws[k * 33 + ogrp * 8 + j], acc[j]);
            }
            __syncthreads();
        }
#pragma unroll
        for (int j = 0; j < 8; j++) {
            const int o = ogrp * 8 + j;
            const float bias = (o < 16) ? ba[o] : bb[o - 16];
            g_AB[(long)(blk * 32 + mrow) * 32 + o] =
                1.f / (1.f + expf(-(acc[j] + bias)));
        }
        return;
    }

    const float* Xin; float* Out; const float* cw; const float* cb; bool donorm;
    switch (blockIdx.z) {
        case 0:  Xin = g_Xq; Out = g_Qn; cw = cq_w; cb = cq_b; donorm = true;  break;
        case 1:  Xin = g_Xk; Out = g_Kn; cw = ck_w; cb = ck_b; donorm = true;  break;
        default: Xin = g_Xv; Out = g_Vv; cw = cv_w; cb = cv_b; donorm = false; break;
    }
    const int bt0 = blockIdx.x * 16;
    const int t0  = bt0 & (Tt - 1);
    const int lane = threadIdx.x & 31;
    const int wid  = threadIdx.x >> 5;
    const int h = blockIdx.y * 4 + wid;
    const int c0 = h * 64 + lane;

    float x0[19], x1[19];
#pragma unroll
    for (int i = 0; i < 19; i++) {
        const int t = t0 - 3 + i;
        if (t < 0) { x0[i] = 0.f; x1[i] = 0.f; }
        else {
            const long g = (long)(bt0 - t0 + t) * INNER + c0;
            x0[i] = Xin[g];
            x1[i] = Xin[g + 32];
        }
    }
    float w0[4], w1[4];
#pragma unroll
    for (int k = 0; k < 4; k++) {
        w0[k] = cw[c0 * 4 + k];
        w1[k] = cw[(c0 + 32) * 4 + k];
    }
    const float b0 = cb[c0], b1 = cb[c0 + 32];

#pragma unroll
    for (int tt = 0; tt < 16; tt++) {
        float a0 = b0, a1 = b1;
#pragma unroll
        for (int k = 0; k < 4; k++) {
            a0 = fmaf(x0[tt + k], w0[k], a0);
            a1 = fmaf(x1[tt + k], w1[k], a1);
        }
        float s0 = a0 / (1.f + expf(-a0));
        float s1 = a1 / (1.f + expf(-a1));
        float ss = s0 * s0 + s1 * s1;
        ss += __shfl_xor_sync(0xffffffffu, ss, 16);
        ss += __shfl_xor_sync(0xffffffffu, ss, 8);
        ss += __shfl_xor_sync(0xffffffffu, ss, 4);
        ss += __shfl_xor_sync(0xffffffffu, ss, 2);
        ss += __shfl_xor_sync(0xffffffffu, ss, 1);
        if (donorm) {
            const float inv = 1.f / fmaxf(sqrtf(ss), 1e-12f);
            s0 *= inv; s1 *= inv;
        }
        const long g = (long)(bt0 + tt) * INNER + c0;
        Out[g] = s0;
        Out[g + 32] = s1;
    }
}

// ============== chunked delta-rule scan ======================================

__global__ __launch_bounds__(256, 2) void chunk_prep_kernel()
{
    extern __shared__ float sm[];
    float* sK = sm;
    float* sV = sm + 64 * CP;
    float* sL = sm + 2 * 64 * CP;
    float* sGam = sm + 3 * 64 * CP;
    float* sR   = sGam + 64;

    const int chunk = blockIdx.x;
    const int c  = chunk & (NCHUNK - 1);
    const int bh = chunk >> 5;
    const int b = bh >> 4, h = bh & 15;
    const int tid = threadIdx.x;
    const long rowbase = (long)b * Tt + c * 64;
    const int colbase = h * dh;
    const long cb = (long)chunk * 4096;

    for (int idx = tid; idx < 1024; idx += 256) {
        const int row = idx >> 4;
        const int c4  = (idx & 15) << 2;
        const long g = (rowbase + row) * INNER + colbase + c4;
        float4 kv = *(const float4*)(g_Kn + g);
        float4 vv = *(const float4*)(g_Vv + g);
        sK[row * CP + c4 + 0] = kv.x; sK[row * CP + c4 + 1] = kv.y;
        sK[row * CP + c4 + 2] = kv.z; sK[row * CP + c4 + 3] = kv.w;
        sV[row * CP + c4 + 0] = vv.x; sV[row * CP + c4 + 1] = vv.y;
        sV[row * CP + c4 + 2] = vv.z; sV[row * CP + c4 + 3] = vv.w;
    }
    if (tid < 64) {
        sGam[tid] = g_AB[(rowbase + tid) * 32 + h];
        sR[tid]   = g_AB[(rowbase + tid) * 32 + 16 + h];
    }
    __syncthreads();
    if (tid == 0) {
        float p = 1.f;
        for (int i = 0; i < 64; i++) { p *= sGam[i]; sGam[i] = p; }
    }
    __syncthreads();
    if (tid < 64) sR[tid] = sR[tid] / sGam[tid];
    __syncthreads();

    const int ty = tid >> 4, tx = tid & 15;

    {
        float acc[4][4];
#pragma unroll
        for (int v = 0; v < 4; v++)
#pragma unroll
            for (int u = 0; u < 4; u++) acc[v][u] = 0.f;
        for (int k = 0; k < 64; k++) {
            float a[4], bb[4];
#pragma unroll
            for (int v = 0; v < 4; v++) a[v]  = sK[(ty + 16 * v) * CP + k];
#pragma unroll
            for (int u = 0; u < 4; u++) bb[u] = sK[(tx + 16 * u) * CP + k];
#pragma unroll
            for (int v = 0; v < 4; v++)
#pragma unroll
                for (int u = 0; u < 4; u++)
                    acc[v][u] = fmaf(a[v], bb[u], acc[v][u]);
        }
#pragma unroll
        for (int v = 0; v < 4; v++)
#pragma unroll
            for (int u = 0; u < 4; u++) {
                const int j = ty + 16 * v, i = tx + 16 * u;
                sL[j * CP + i] = (i < j) ? acc[v][u] * sGam[j] * sR[i] : 0.f;
            }
        __syncthreads();
    }

    float rr_[64];
    const int col = tid & 63;
    const int isW = (tid >> 6) & 1;
    if (tid < 128) {
#pragma unroll
        for (int j = 0; j < 64; j++)
            rr_[j] = isW ? sGam[j] * sK[j * CP + col] : sV[j * CP + col];
#pragma unroll
        for (int j = 0; j < 64; j++) {
            const float xj = rr_[j];
#pragma unroll
            for (int i = j + 1; i < 64; i++)
                rr_[i] -= sL[i * CP + j] * xj;
        }
    }
    __syncthreads();

    const float gC = sGam[63];
    if (tid < 128) {
        float* dst  = isW ? sL : sV;
        float* gdst = isW ? g_W : g_T;
#pragma unroll
        for (int j = 0; j < 64; j++) {
            dst[j * CP + col] = rr_[j];
            gdst[cb + j * 64 + col] = rr_[j];
        }
    } else {
        const int t2 = tid - 128;
        for (int idx = t2; idx < 4096; idx += 128) {
            const int j = idx >> 6;
            sK[j * CP + (idx & 63)] *= gC * sR[j];
        }
    }
    if (tid < 64) {
        g_gam[chunk * 64 + tid] = sGam[tid];
        g_r  [chunk * 64 + tid] = sR[tid];
    }
    __syncthreads();

    {
        float am[4][4], an[4][4];
#pragma unroll
        for (int v = 0; v < 4; v++)
#pragma unroll
            for (int u = 0; u < 4; u++) {
                am[v][u] = ((ty == tx) && (v == u)) ? gC : 0.f;
                an[v][u] = 0.f;
            }
        for (int j = 0; j < 64; j++) {
            float wv[4], tv[4], kb[4];
#pragma unroll
            for (int v = 0; v < 4; v++) {
                wv[v] = sL[j * CP + ty + 16 * v];
                tv[v] = sV[j * CP + ty + 16 * v];
            }
#pragma unroll
            for (int u = 0; u < 4; u++) kb[u] = sK[j * CP + tx + 16 * u];
#pragma unroll
            for (int v = 0; v < 4; v++)
#pragma unroll
                for (int u = 0; u < 4; u++) {
                    am[v][u] = fmaf(-wv[v], kb[u], am[v][u]);
                    an[v][u] = fmaf( tv[v], kb[u], an[v][u]);
                }
        }
#pragma unroll
        for (int v = 0; v < 4; v++)
#pragma unroll
            for (int u = 0; u < 4; u++) {
                const int p = ty + 16 * v, q = tx + 16 * u;
                g_M[cb + p * 64 + q] = am[v][u];
                g_N[cb + p * 64 + q] = an[v][u];
            }
    }
}

__global__ __launch_bounds__(256) void chunk_scan_kernel()
{
    __shared__ float sS[16 * 64];
    __shared__ float sM[64 * 64];
    const int bh = blockIdx.x;
    const int R0 = blockIdx.y * 16;
    const int tid = threadIdx.x;
    const int row = tid >> 4;
    const int tx  = tid & 15;

    for (int idx = tid; idx < 1024; idx += 256) sS[idx] = 0.f;
    __syncthreads();

    for (int c = 0; c < NCHUNK; c++) {
        const long cb = (long)(bh * NCHUNK + c) * 4096;
        for (int idx = tid; idx < 1024; idx += 256)
            g_S0[cb + (long)(R0 + (idx >> 6)) * 64 + (idx & 63)] = sS[idx];
        for (int idx = tid; idx < 4096; idx += 256)
            sM[idx] = g_M[cb + idx];
        __syncthreads();

        float acc[4];
#pragma unroll
        for (int u = 0; u < 4; u++)
            acc[u] = g_N[cb + (long)(R0 + row) * 64 + tx + 16 * u];
        for (int k = 0; k < 64; k++) {
            const float s = sS[row * 64 + k];
#pragma unroll
            for (int u = 0; u < 4; u++)
                acc[u] = fmaf(s, sM[k * 64 + tx + 16 * u], acc[u]);
        }
        __syncthreads();
#pragma unroll
        for (int u = 0; u < 4; u++) sS[row * 64 + tx + 16 * u] = acc[u];
        __syncthreads();
    }
}

// ---- chunk_out: tensor-core (tf32 mma) version ------------------------------
// Buffers [row][k] with stride CO=68 (banks 4r+c -> conflict-free fragments).
// Phase 1: Araw(t,j) = Qg·K^T  -> sA = tril(r_j * Araw)      (Qg = gam_t * q)
// Phase 2: D(a,j)   = S0·W^T  -> sUT[a][j] = T[j][a] - D
// Phase 3: O(t,a)   = Qg·S0^T + A·U   (accumulated in one fragment set)
#define CO_SMEM ((6 * 64 * CO + 128) * 4)

__device__ __forceinline__ void mma_block64(const float* __restrict__ As_,
                                            const float* __restrict__ Bs_,
                                            int m0, int n0, int lane,
                                            float acc[2][2][4])
{
#pragma unroll
    for (int k8 = 0; k8 < 64; k8 += 8) {
        const int kk0 = k8 + (lane & 3);
        const int kk1 = kk0 + 4;
        unsigned af[2][4], bf[2][2];
#pragma unroll
        for (int mt = 0; mt < 2; mt++) {
            const int r0 = m0 + mt * 16 + (lane >> 2);
            af[mt][0] = __float_as_uint(As_[r0 * CO + kk0]);
            af[mt][1] = __float_as_uint(As_[(r0 + 8) * CO + kk0]);
            af[mt][2] = __float_as_uint(As_[r0 * CO + kk1]);
            af[mt][3] = __float_as_uint(As_[(r0 + 8) * CO + kk1]);
        }
#pragma unroll
        for (int nt = 0; nt < 2; nt++) {
            const int n = n0 + nt * 8 + (lane >> 2);
            bf[nt][0] = __float_as_uint(Bs_[n * CO + kk0]);
            bf[nt][1] = __float_as_uint(Bs_[n * CO + kk1]);
        }
#pragma unroll
        for (int mt = 0; mt < 2; mt++)
#pragma unroll
            for (int nt = 0; nt < 2; nt++)
                mma_tf32(acc[mt][nt], af[mt][0], af[mt][1], af[mt][2], af[mt][3],
                         bf[nt][0], bf[nt][1]);
    }
}

__global__ __launch_bounds__(256, 2) void chunk_out_kernel()
{
    extern __shared__ float sm[];
    float* sQg = sm;                 // gam-scaled Q (rounded)
    float* sK  = sm + 64 * CO;       // K (rounded) -> reused as sUT
    float* sS0 = sm + 2 * 64 * CO;   // S0 (rounded)
    float* sW  = sm + 3 * 64 * CO;   // W (rounded)
    float* sT  = sm + 4 * 64 * CO;   // T (fp32)
    float* sA  = sm + 5 * 64 * CO;   // A (rounded)
    float* sGam = sm + 6 * 64 * CO;
    float* sR   = sGam + 64;
    float* sUT  = sK;

    const int chunk = blockIdx.x;
    const int c  = chunk & (NCHUNK - 1);
    const int bh = chunk >> 5;
    const int b = bh >> 4, h = bh & 15;
    const int tid = threadIdx.x;
    const int lane = tid & 31;
    const int wid  = tid >> 5;
    const int m0 = (wid & 1) * 32;
    const int n0 = (wid >> 1) * 16;
    const long rowbase = (long)b * Tt + c * 64;
    const int colbase = h * dh;
    const long cb = (long)chunk * 4096;

    if (tid < 64) {
        sGam[tid] = g_gam[chunk * 64 + tid];
        sR[tid]   = g_r[chunk * 64 + tid];
    }
    __syncthreads();

    for (int idx = tid; idx < 1024; idx += 256) {
        const int row = idx >> 4;
        const int c4  = (idx & 15) << 2;
        const long g = (rowbase + row) * INNER + colbase + c4;
        float4 qv = *(const float4*)(g_Qn + g);
        float4 kv = *(const float4*)(g_Kn + g);
        const float gm = sGam[row];
        sQg[row * CO + c4 + 0] = rna_tf32(qv.x * gm);
        sQg[row * CO + c4 + 1] = rna_tf32(qv.y * gm);
        sQg[row * CO + c4 + 2] = rna_tf32(qv.z * gm);
        sQg[row * CO + c4 + 3] = rna_tf32(qv.w * gm);
        sK [row * CO + c4 + 0] = rna_tf32(kv.x);
        sK [row * CO + c4 + 1] = rna_tf32(kv.y);
        sK [row * CO + c4 + 2] = rna_tf32(kv.z);
        sK [row * CO + c4 + 3] = rna_tf32(kv.w);
    }
    for (int idx = tid; idx < 4096; idx += 256) {
        const int r = idx >> 6, cc = idx & 63;
        sS0[r * CO + cc] = rna_tf32(g_S0[cb + idx]);
        sW [r * CO + cc] = rna_tf32(g_W[cb + idx]);
        sT [r * CO + cc] = g_T[cb + idx];
    }
    __syncthreads();

    // Phase 1: A = tril(diag(gam) Q K^T diag(r))
    {
        float acc[2][2][4];
#pragma unroll
        for (int mt = 0; mt < 2; mt++)
#pragma unroll
            for (int nt = 0; nt < 2; nt++)
#pragma unroll
                for (int i = 0; i < 4; i++) acc[mt][nt][i] = 0.f;
        mma_block64(sQg, sK, m0, n0, lane, acc);
        __syncthreads();                   // sK reads done before overwrite
#pragma unroll
        for (int mt = 0; mt < 2; mt++) {
            const int t0r = m0 + mt * 16 + (lane >> 2);
#pragma unroll
            for (int nt = 0; nt < 2; nt++) {
                const int j0 = n0 + nt * 8 + ((lane & 3) << 1);
#pragma unroll
                for (int half = 0; half < 2; half++) {
                    const int t = t0r + half * 8;
                    const float v0 = acc[mt][nt][half * 2 + 0];
                    const float v1 = acc[mt][nt][half * 2 + 1];
                    sA[t * CO + j0]     = (j0     <= t) ? rna_tf32(v0 * sR[j0])     : 0.f;
                    sA[t * CO + j0 + 1] = (j0 + 1 <= t) ? rna_tf32(v1 * sR[j0 + 1]) : 0.f;
                }
            }
        }
    }

    // Phase 2: UT[a][j] = T[j][a] - (S0 W^T)(a,j)
    {
        float acc[2][2][4];
#pragma unroll
        for (int mt = 0; mt < 2; mt++)
#pragma unroll
            for (int nt = 0; nt < 2; nt++)
#pragma unroll
                for (int i = 0; i < 4; i++) acc[mt][nt][i] = 0.f;
        mma_block64(sS0, sW, m0, n0, lane, acc);
        __syncthreads();
#pragma unroll
        for (int mt = 0; mt < 2; mt++) {
            const int a0 = m0 + mt * 16 + (lane >> 2);
#pragma unroll
            for (int nt = 0; nt < 2; nt++) {
                const int j0 = n0 + nt * 8 + ((lane & 3) << 1);
#pragma unroll
                for (int half = 0; half < 2; half++) {
                    const int a = a0 + half * 8;
                    sUT[a * CO + j0]     = rna_tf32(sT[j0 * CO + a]       - acc[mt][nt][half * 2 + 0]);
                    sUT[a * CO + j0 + 1] = rna_tf32(sT[(j0 + 1) * CO + a] - acc[mt][nt][half * 2 + 1]);
                }
            }
        }
    }
    __syncthreads();

    // Phase 3: O = Qg S0^T + A U
    {
        float acc[2][2][4];
#pragma unroll
        for (int mt = 0; mt < 2; mt++)
#pragma unroll
            for (int nt = 0; nt < 2; nt++)
#pragma unroll
                for (int i = 0; i < 4; i++) acc[mt][nt][i] = 0.f;
        mma_block64(sQg, sS0, m0, n0, lane, acc);
        mma_block64(sA, sUT, m0, n0, lane, acc);
#pragma unroll
        for (int mt = 0; mt < 2; mt++) {
            const int t0r = m0 + mt * 16 + (lane >> 2);
#pragma unroll
            for (int nt = 0; nt < 2; nt++) {
                const int a0 = n0 + nt * 8 + ((lane & 3) << 1);
#pragma unroll
                for (int half = 0; half < 2; half++) {
                    const int t = t0r + half * 8;
                    *(float2*)(g_O + (rowbase + t) * INNER + colbase + a0) =
                        make_float2(acc[mt][nt][half * 2 + 0],
                                    acc[mt][nt][half * 2 + 1]);
                }
            }
        }
    }
}

// ---------------- RMS norm + (1+gamma) + gate (float4) -----------------------
__global__ __launch_bounds__(256) void rmsgate_kernel(const float* __restrict__ gamma)
{
    const int m = blockIdx.x;
    const int tid = threadIdx.x;
    const long base = (long)m * INNER + tid * 4;
    float4 xv = *(const float4*)(g_O + base);
    float ss = xv.x * xv.x + xv.y * xv.y + xv.z * xv.z + xv.w * xv.w;
    for (int off = 16; off; off >>= 1) ss += __shfl_xor_sync(0xffffffffu, ss, off);
    __shared__ float red[8];
    if ((tid & 31) == 0) red[tid >> 5] = ss;
    __syncthreads();
    float tot = 0.f;
#pragma unroll
    for (int w = 0; w < 8; w++) tot += red[w];
    const float inv = 1.f / sqrtf(tot * (1.f / (float)INNER) + 1e-6f);
    float4 gv = *(const float4*)(g_Xg + base);
    float4 gm = *(const float4*)(gamma + tid * 4);
    float4 o;
    o.x = rna_tf32(xv.x * inv * (1.f + gm.x) * gv.x);
    o.y = rna_tf32(xv.y * inv * (1.f + gm.y) * gv.y);
    o.z = rna_tf32(xv.z * inv * (1.f + gm.z) * gv.z);
    o.w = rna_tf32(xv.w * inv * (1.f + gm.w) * gv.w);
    *(float4*)(g_Y + base) = o;
}

// ---------------- launch -----------------------------------------------------
extern "C" void kernel_launch(void* const* d_in, const int* in_sizes, int n_in,
                              void* d_out, int out_size)
{
    const float* x    = (const float*)d_in[0];
    const float* Wq   = (const float*)d_in[1];
    const float* Wk   = (const float*)d_in[2];
    const float* Wv   = (const float*)d_in[3];
    const float* Wa   = (const float*)d_in[4];
    const float* ba   = (const float*)d_in[5];
    const float* Wb   = (const float*)d_in[6];
    const float* bb   = (const float*)d_in[7];
    const float* Wg   = (const float*)d_in[8];
    const float* Wo   = (const float*)d_in[9];
    const float* cq_w = (const float*)d_in[10];
    const float* cq_b = (const float*)d_in[11];
    const float* ck_w = (const float*)d_in[12];
    const float* ck_b = (const float*)d_in[13];
    const float* cv_w = (const float*)d_in[14];
    const float* cv_b = (const float*)d_in[15];
    const float* gamma= (const float*)d_in[16];
    float* out = (float*)d_out;

    const int prep_smem = (3 * 64 * CP + 128) * sizeof(float);
    cudaFuncSetAttribute(chunk_prep_kernel,
                         cudaFuncAttributeMaxDynamicSharedMemorySize, prep_smem);
    cudaFuncSetAttribute(chunk_out_kernel,
                         cudaFuncAttributeMaxDynamicSharedMemorySize, CO_SMEM);
    cudaFuncSetAttribute(proj_gemm_kernel,
                         cudaFuncAttributeMaxDynamicSharedMemorySize, GSMEM);
    cudaFuncSetAttribute(out_gemm_kernel,
                         cudaFuncAttributeMaxDynamicSharedMemorySize, GSMEM);

    const int cvt_blocks = (Mrows * Dd + 5 * Dd * INNER) / 1024;
    cvt_kernel<<<cvt_blocks, 256>>>(x, Wq, Wk, Wv, Wg, Wo);
    proj_gemm_kernel<<<dim3(INNER / 128, Mrows / 128, 4), 128, GSMEM>>>();
    convab_kernel<<<dim3(Mrows / 16, 4, 4), 128>>>(x, cq_w, cq_b, ck_w, ck_b,
                                                   cv_w, cv_b, Wa, ba, Wb, bb);
    chunk_prep_kernel<<<1024, 256, prep_smem>>>();
    chunk_scan_kernel<<<dim3(Bz * Hh, 4), 256>>>();
    chunk_out_kernel<<<1024, 256, CO_SMEM>>>();
    rmsgate_kernel<<<Mrows, 256>>>(gamma);
    out_gemm_kernel<<<dim3(Dd / 128, Mrows / 128), 128, GSMEM>>>(out);
}